// round 2
// baseline (speedup 1.0000x reference)
#include <cuda_runtime.h>
#include <math.h>

#define BATCH 8
#define NINST 100
#define NPAIR 9900
#define DIM   1024
#define HID   1024
#define NCLS  51
#define NROWS (BATCH*NPAIR)   // 79200
#define NCAND 128             // candidates per batch for exact repair

// ---------------- scratch (device globals; no allocs allowed) ----------------
__device__ float  g_A12[BATCH*NINST*2048];     // inst @ [W1a | W1b]
__device__ float  g_h[81100800];               // 79200 x 1024 hidden (fp32)
__device__ float  g_overall[NROWS];            // fp32 ranking key
__device__ int    g_cand_idx[BATCH*NCAND];     // candidate pair indices
__device__ int    g_cand_lab[BATCH*NCAND];
__device__ double g_cand_prob[BATCH*NCAND];
__device__ double g_cand_ovr[BATCH*NCAND];
__device__ double g_hd[BATCH*NCAND*1024];      // fp64 hidden for candidates

// =============================================================================
// K1: A12[r, j] = inst[r, :] @ W1[half*1024 + :, jc]   (M=800, N=2048, K=1024)
// =============================================================================
__global__ __launch_bounds__(256) void k1_instproj(const float* __restrict__ inst,
                                                   const float* __restrict__ W1)
{
    __shared__ float As[16][68];
    __shared__ float Bs[16][64];
    int tid = threadIdx.x;
    int n0 = blockIdx.x * 64;
    int m0 = blockIdx.y * 64;
    int half = n0 >> 10;
    int jc0  = n0 & 1023;
    const float* wbase = W1 + (size_t)half * 1024 * 1024 + jc0;

    int arow = tid >> 2;
    int akq  = (tid & 3) * 4;
    int ar   = m0 + arow; if (ar > 799) ar = 799;
    const float* aptr = inst + (size_t)ar * 1024 + akq;

    int brow = tid >> 4;
    int bn   = (tid & 15) * 4;

    int tx = tid & 15, ty = tid >> 4;
    float acc[4][4] = {};

    for (int k0 = 0; k0 < 1024; k0 += 16) {
        float4 av = *(const float4*)(aptr + k0);
        float4 bv = *(const float4*)(wbase + (size_t)(k0 + brow) * 1024 + bn);
        As[akq+0][arow] = av.x; As[akq+1][arow] = av.y;
        As[akq+2][arow] = av.z; As[akq+3][arow] = av.w;
        *(float4*)&Bs[brow][bn] = bv;
        __syncthreads();
        #pragma unroll
        for (int kk = 0; kk < 16; kk++) {
            float af[4], bf[4];
            *(float4*)af = *(const float4*)&As[kk][ty*4];
            *(float4*)bf = *(const float4*)&Bs[kk][tx*4];
            #pragma unroll
            for (int i = 0; i < 4; i++)
                #pragma unroll
                for (int j = 0; j < 4; j++)
                    acc[i][j] += af[i] * bf[j];
        }
        __syncthreads();
    }
    #pragma unroll
    for (int i = 0; i < 4; i++) {
        int r = m0 + ty*4 + i;
        if (r < 800) {
            float4 o = make_float4(acc[i][0], acc[i][1], acc[i][2], acc[i][3]);
            *(float4*)&g_A12[(size_t)r*2048 + n0 + tx*4] = o;
        }
    }
}

// =============================================================================
// K2: h[b,p,n] = lrelu( phr_gather @ W1c + A1[sub] + A2[obj] + b1 )
// =============================================================================
__global__ __launch_bounds__(256) void k2_hgemm(const float* __restrict__ phrase,
                                                const float* __restrict__ W1,
                                                const float* __restrict__ b1,
                                                const int*   __restrict__ connect,
                                                const int*   __restrict__ pidx)
{
    __shared__ float As[8][132];
    __shared__ float Bs[8][128];
    __shared__ int ssub[128], sobj[128], sphr[128];
    int tid = threadIdx.x;
    int b  = blockIdx.z;
    int p0 = blockIdx.y * 128;
    int n0 = blockIdx.x * 128;

    for (int m = tid; m < 128; m += 256) {
        int p = p0 + m; if (p >= NPAIR) p = NPAIR - 1;
        sphr[m] = pidx[b*NPAIR + p];
        ssub[m] = connect[(size_t)b*2*NPAIR + p];
        sobj[m] = connect[(size_t)b*2*NPAIR + NPAIR + p];
    }
    __syncthreads();

    int arow = tid >> 1;
    int akq  = (tid & 1) * 4;
    const float* aptr = phrase + ((size_t)b*NPAIR + sphr[arow]) * 1024 + akq;
    int bk = tid >> 5;
    int bn = (tid & 31) * 4;
    const float* wptr = W1 + (size_t)2048*1024 + (size_t)bk*1024 + n0 + bn;

    int tx = tid & 15, ty = tid >> 4;
    float acc[8][8] = {};

    float4 a_nx = *(const float4*)(aptr);
    float4 b_nx = *(const float4*)(wptr);

    for (int k0 = 0; k0 < 1024; k0 += 8) {
        As[akq+0][arow] = a_nx.x; As[akq+1][arow] = a_nx.y;
        As[akq+2][arow] = a_nx.z; As[akq+3][arow] = a_nx.w;
        *(float4*)&Bs[bk][bn] = b_nx;
        __syncthreads();
        if (k0 + 8 < 1024) {
            a_nx = *(const float4*)(aptr + k0 + 8);
            b_nx = *(const float4*)(wptr + (size_t)(k0 + 8) * 1024);
        }
        #pragma unroll
        for (int kk = 0; kk < 8; kk++) {
            float af[8], bf[8];
            *(float4*)&af[0] = *(const float4*)&As[kk][ty*8];
            *(float4*)&af[4] = *(const float4*)&As[kk][ty*8+4];
            *(float4*)&bf[0] = *(const float4*)&Bs[kk][tx*8];
            *(float4*)&bf[4] = *(const float4*)&Bs[kk][tx*8+4];
            #pragma unroll
            for (int i = 0; i < 8; i++)
                #pragma unroll
                for (int j = 0; j < 8; j++)
                    acc[i][j] += af[i] * bf[j];
        }
        __syncthreads();
    }

    const float* a12b = g_A12 + (size_t)b*NINST*2048;
    #pragma unroll
    for (int i = 0; i < 8; i++) {
        int m = ty*8 + i;
        int p = p0 + m;
        if (p >= NPAIR) continue;
        const float* r1 = a12b + (size_t)ssub[m]*2048 + n0;
        const float* r2 = a12b + (size_t)sobj[m]*2048 + 1024 + n0;
        float* ho = g_h + ((size_t)b*NPAIR + p)*1024 + n0;
        #pragma unroll
        for (int j4 = 0; j4 < 8; j4 += 4) {
            int nl = tx*8 + j4;
            float4 v1 = *(const float4*)(r1 + nl);
            float4 v2 = *(const float4*)(r2 + nl);
            float4 vb = *(const float4*)(b1 + n0 + nl);
            float4 o;
            o.x = acc[i][j4+0] + v1.x + v2.x + vb.x;
            o.y = acc[i][j4+1] + v1.y + v2.y + vb.y;
            o.z = acc[i][j4+2] + v1.z + v2.z + vb.z;
            o.w = acc[i][j4+3] + v1.w + v2.w + vb.w;
            o.x = o.x > 0.f ? o.x : 0.01f*o.x;
            o.y = o.y > 0.f ? o.y : 0.01f*o.y;
            o.z = o.z > 0.f ? o.z : 0.01f*o.z;
            o.w = o.w > 0.f ? o.w : 0.01f*o.w;
            *(float4*)(ho + nl) = o;
        }
    }
}

// =============================================================================
// K3a: logits = h @ W2 + b2    (M=79200, N=51 padded to 64, K=1024)
// =============================================================================
__global__ __launch_bounds__(256) void k3a_logits(const float* __restrict__ W2,
                                                  const float* __restrict__ b2,
                                                  float* __restrict__ out_logits)
{
    __shared__ float hsm[32][132];
    __shared__ float w2s[32][64];
    int tid = threadIdx.x;
    size_t row0 = (size_t)blockIdx.x * 128;

    int lr = tid >> 1;
    int lk = (tid & 1) * 16;
    size_t grow = row0 + lr; if (grow > (size_t)NROWS - 1) grow = NROWS - 1;
    const float* hptr = g_h + grow * 1024 + lk;

    int tx = tid & 15, ty = tid >> 4;
    float acc[8][4] = {};

    for (int k0 = 0; k0 < 1024; k0 += 32) {
        #pragma unroll
        for (int q = 0; q < 4; q++) {
            float4 v = *(const float4*)(hptr + k0 + q*4);
            hsm[lk + q*4 + 0][lr] = v.x;
            hsm[lk + q*4 + 1][lr] = v.y;
            hsm[lk + q*4 + 2][lr] = v.z;
            hsm[lk + q*4 + 3][lr] = v.w;
        }
        for (int idx = tid; idx < 32*64; idx += 256) {
            int kk = idx >> 6, c = idx & 63;
            w2s[kk][c] = (c < NCLS) ? W2[(size_t)(k0 + kk)*NCLS + c] : 0.f;
        }
        __syncthreads();
        #pragma unroll
        for (int kk = 0; kk < 32; kk++) {
            float af[8], bf[4];
            *(float4*)&af[0] = *(const float4*)&hsm[kk][ty*8];
            *(float4*)&af[4] = *(const float4*)&hsm[kk][ty*8+4];
            *(float4*)bf = *(const float4*)&w2s[kk][tx*4];
            #pragma unroll
            for (int i = 0; i < 8; i++)
                #pragma unroll
                for (int j = 0; j < 4; j++)
                    acc[i][j] += af[i]*bf[j];
        }
        __syncthreads();
    }
    #pragma unroll
    for (int j = 0; j < 4; j++) {
        int c = tx*4 + j;
        if (c >= NCLS) continue;
        float bb = b2[c];
        #pragma unroll
        for (int i = 0; i < 8; i++) {
            size_t r = row0 + (size_t)ty*8 + i;
            if (r < NROWS) out_logits[r*NCLS + c] = acc[i][j] + bb;
        }
    }
}

// =============================================================================
// K3b: softmax -> probs output; fp32 overall (ranking key only)
// =============================================================================
__global__ void k3b_softmax(const float* __restrict__ out_logits,
                            const float* __restrict__ scores,
                            const int*   __restrict__ connect,
                            float* __restrict__ out_probs)
{
    int row = blockIdx.x * blockDim.x + threadIdx.x;
    if (row >= NROWS) return;
    const float* lp = out_logits + (size_t)row * NCLS;
    float l[NCLS];
    float m = -1e30f;
    #pragma unroll
    for (int c = 0; c < NCLS; c++) { l[c] = lp[c]; m = fmaxf(m, l[c]); }
    float s = 0.f;
    #pragma unroll
    for (int c = 0; c < NCLS; c++) { l[c] = expf(l[c] - m); s += l[c]; }
    float* pp = out_probs + (size_t)row * NCLS;
    float best = 0.f;
    #pragma unroll
    for (int c = 0; c < NCLS; c++) {
        float pr = l[c] / s;
        pp[c] = pr;
        if (c >= 1 && pr > best) best = pr;
    }
    int b = row / NPAIR, p = row % NPAIR;
    int si = connect[(size_t)b*2*NPAIR + p];
    int oi = connect[(size_t)b*2*NPAIR + NPAIR + p];
    g_overall[row] = best * scores[b*NINST + si] * scores[b*NINST + oi];
}

// =============================================================================
// K4: per-batch select top-NCAND candidate indices by fp32 overall
// =============================================================================
__global__ __launch_bounds__(1024) void k4_select()
{
    __shared__ float vals[NPAIR];
    __shared__ float wv[32];
    __shared__ int   wi[32];
    int b = blockIdx.x;
    int tid = threadIdx.x;
    for (int i = tid; i < NPAIR; i += 1024) vals[i] = g_overall[b*NPAIR + i];
    __syncthreads();

    for (int t = 0; t < NCAND; t++) {
        float bv = -1.0f; int bi = 0x7fffffff;
        for (int i = tid; i < NPAIR; i += 1024) {
            float v = vals[i];
            if (v > bv) { bv = v; bi = i; }
        }
        #pragma unroll
        for (int o = 16; o; o >>= 1) {
            float ov2 = __shfl_down_sync(0xffffffffu, bv, o);
            int   oi2 = __shfl_down_sync(0xffffffffu, bi, o);
            if (ov2 > bv || (ov2 == bv && oi2 < bi)) { bv = ov2; bi = oi2; }
        }
        if ((tid & 31) == 0) { wv[tid >> 5] = bv; wi[tid >> 5] = bi; }
        __syncthreads();
        if (tid < 32) {
            bv = wv[tid]; bi = wi[tid];
            #pragma unroll
            for (int o = 16; o; o >>= 1) {
                float ov2 = __shfl_down_sync(0xffffffffu, bv, o);
                int   oi2 = __shfl_down_sync(0xffffffffu, bi, o);
                if (ov2 > bv || (ov2 == bv && oi2 < bi)) { bv = ov2; bi = oi2; }
            }
            if (tid == 0) {
                g_cand_idx[b*NCAND + t] = bi;
                vals[bi] = -2.0f;
            }
        }
        __syncthreads();
    }
}

// =============================================================================
// K5: fp64 exact h for candidates. 4 candidates/block, 256 threads.
// =============================================================================
#define CPB 4
__global__ __launch_bounds__(256) void k5_repair_h(const float* __restrict__ inst,
                                                   const float* __restrict__ phrase,
                                                   const float* __restrict__ W1,
                                                   const float* __restrict__ b1,
                                                   const int*   __restrict__ connect,
                                                   const int*   __restrict__ pidx)
{
    __shared__ float sf[CPB][3072];   // 48 KB
    int b = blockIdx.x >> 5;          // 32 groups per batch
    int g = blockIdx.x & 31;
    int tid = threadIdx.x;

    for (int c = 0; c < CPB; c++) {
        int slot = b*NCAND + g*CPB + c;
        int p  = g_cand_idx[slot];
        int si = connect[(size_t)b*2*NPAIR + p];
        int oi = connect[(size_t)b*2*NPAIR + NPAIR + p];
        int ph = pidx[b*NPAIR + p];
        const float* s0 = inst   + ((size_t)b*NINST + si)*1024;
        const float* s1 = inst   + ((size_t)b*NINST + oi)*1024;
        const float* s2 = phrase + ((size_t)b*NPAIR + ph)*1024;
        for (int k = tid; k < 1024; k += 256) {
            sf[c][k]        = s0[k];
            sf[c][1024 + k] = s1[k];
            sf[c][2048 + k] = s2[k];
        }
    }
    __syncthreads();

    double acc[CPB][4] = {};
    for (int k = 0; k < 3072; k++) {
        const float* wr = W1 + (size_t)k*1024 + tid;
        double w0 = (double)wr[0];
        double w1v = (double)wr[256];
        double w2v = (double)wr[512];
        double w3 = (double)wr[768];
        #pragma unroll
        for (int c = 0; c < CPB; c++) {
            double f = (double)sf[c][k];
            acc[c][0] = fma(f, w0,  acc[c][0]);
            acc[c][1] = fma(f, w1v, acc[c][1]);
            acc[c][2] = fma(f, w2v, acc[c][2]);
            acc[c][3] = fma(f, w3,  acc[c][3]);
        }
    }
    #pragma unroll
    for (int c = 0; c < CPB; c++) {
        int slot = b*NCAND + g*CPB + c;
        #pragma unroll
        for (int j = 0; j < 4; j++) {
            double v = acc[c][j] + (double)b1[tid + j*256];
            v = v > 0.0 ? v : 0.01 * v;
            g_hd[(size_t)slot*1024 + tid + j*256] = v;
        }
    }
}

// =============================================================================
// K6: fp64 logits + softmax + decisions per candidate
// =============================================================================
__global__ __launch_bounds__(64) void k6_decide(const float* __restrict__ W2,
                                                const float* __restrict__ b2,
                                                const float* __restrict__ scores,
                                                const int*   __restrict__ connect)
{
    __shared__ double sh[1024];
    __shared__ double slog[NCLS];
    int slot = blockIdx.x;
    int tid = threadIdx.x;
    const double* hd = g_hd + (size_t)slot*1024;
    for (int k = tid; k < 1024; k += 64) sh[k] = hd[k];
    __syncthreads();

    if (tid < NCLS) {
        double acc = 0.0;
        #pragma unroll 8
        for (int k = 0; k < 1024; k++)
            acc = fma(sh[k], (double)W2[(size_t)k*NCLS + tid], acc);
        slog[tid] = acc + (double)b2[tid];
    }
    __syncthreads();

    if (tid == 0) {
        double m = slog[0];
        for (int c = 1; c < NCLS; c++) m = slog[c] > m ? slog[c] : m;
        double e[NCLS]; double s = 0.0;
        for (int c = 0; c < NCLS; c++) { e[c] = exp(slog[c] - m); s += e[c]; }
        double best = 0.0; int bl = 0;
        for (int c = 1; c < NCLS; c++) {
            double pr = e[c] / s;
            if (pr > best) { best = pr; bl = c; }
        }
        int b = slot >> 7;
        int p = g_cand_idx[slot];
        int si = connect[(size_t)b*2*NPAIR + p];
        int oi = connect[(size_t)b*2*NPAIR + NPAIR + p];
        double ov = best * (double)scores[b*NINST + si] * (double)scores[b*NINST + oi];
        g_cand_ovr[slot]  = ov;
        g_cand_prob[slot] = best;
        g_cand_lab[slot]  = bl;
    }
}

// =============================================================================
// K7: final top-100 per batch over NCAND fp64 candidates (tie -> smaller idx)
// =============================================================================
__global__ __launch_bounds__(128) void k7_final(float* __restrict__ outbase)
{
    __shared__ double v[NCAND];
    __shared__ int    pidx[NCAND];
    int b = blockIdx.x, tid = threadIdx.x;
    v[tid]    = g_cand_ovr[b*NCAND + tid];
    pidx[tid] = g_cand_idx[b*NCAND + tid];
    __syncthreads();

    if (tid == 0) {
        float* out_lab  = outbase;
        float* out_prob = outbase + 800;
        float* out_val  = outbase + 1600;
        float* out_idx  = outbase + 2400;
        for (int t = 0; t < 100; t++) {
            double bv = -1.0; int bj = 0; int bidx = 0x7fffffff;
            for (int j = 0; j < NCAND; j++) {
                double val = v[j]; int ix = pidx[j];
                if (val > bv || (val == bv && ix < bidx)) { bv = val; bj = j; bidx = ix; }
            }
            int slot2 = b*NCAND + bj;
            out_val [b*100 + t] = (float)bv;
            out_idx [b*100 + t] = (float)bidx;
            out_lab [b*100 + t] = (float)g_cand_lab[slot2];
            out_prob[b*100 + t] = (float)g_cand_prob[slot2];
            v[bj] = -2.0;
        }
    }
}

// =============================================================================
extern "C" void kernel_launch(void* const* d_in, const int* in_sizes, int n_in,
                              void* d_out, int out_size)
{
    const float* inst    = (const float*)d_in[0];
    const float* phrase  = (const float*)d_in[1];
    const float* scores  = (const float*)d_in[2];
    const float* W1      = (const float*)d_in[3];
    const float* b1      = (const float*)d_in[4];
    const float* W2      = (const float*)d_in[5];
    const float* b2      = (const float*)d_in[6];
    const int*   connect = (const int*)d_in[7];
    const int*   pidx    = (const int*)d_in[8];

    float* out        = (float*)d_out;
    float* out_logits = out;
    float* out_probs  = out + (size_t)BATCH*NPAIR*NCLS;
    float* out_top    = out + (size_t)2*BATCH*NPAIR*NCLS;

    k1_instproj<<<dim3(32, 13), 256>>>(inst, W1);
    k2_hgemm<<<dim3(8, 78, BATCH), 256>>>(phrase, W1, b1, connect, pidx);
    k3a_logits<<<619, 256>>>(W2, b2, out_logits);
    k3b_softmax<<<(NROWS + 255) / 256, 256>>>(out_logits, scores, connect, out_probs);
    k4_select<<<BATCH, 1024>>>();
    k5_repair_h<<<BATCH*32, 256>>>(inst, phrase, W1, b1, connect, pidx);
    k6_decide<<<BATCH*NCAND, 64>>>(W2, b2, scores, connect);
    k7_final<<<BATCH, 128>>>(out_top);
}

// round 4
// speedup vs baseline: 1.0922x; 1.0922x over previous
#include <cuda_runtime.h>
#include <cuda_bf16.h>
#include <math.h>
#include <stdint.h>

#define BATCH 8
#define NINST 100
#define NPAIR 9900
#define NCLS  51
#define NROWS (BATCH*NPAIR)   // 79200
#define NCAND 128
#define KC    64
#define K2_SMEM (128*1024)

// ---------------- scratch (device globals; no allocs allowed) ----------------
__device__ float  g_A12[BATCH*NINST*2048];
__device__ float  g_h[81100800];                // 79200 x 1024 fp32
__device__ float  g_overall[NROWS];
__device__ int    g_cand_idx[BATCH*NCAND];
__device__ int    g_cand_lab[BATCH*NCAND];
__device__ double g_cand_prob[BATCH*NCAND];
__device__ double g_cand_ovr[BATCH*NCAND];
__device__ double g_hd[BATCH*NCAND*1024];
__device__ __align__(16) unsigned short g_Ahi[81100800];  // gathered phrase, bf16 hi
__device__ __align__(16) unsigned short g_Alo[81100800];  // bf16 lo
__device__ __align__(16) unsigned short g_Bhi[1024*1024]; // W1c^T [n][k] bf16 hi
__device__ __align__(16) unsigned short g_Blo[1024*1024];

// ---------------- helpers (baseline PTX only: sm_80-class, no 'a' features) --
__device__ __forceinline__ uint32_t smem_u32(const void* p) {
    uint32_t a;
    asm("{ .reg .u64 t; cvta.to.shared.u64 t, %1; cvt.u32.u64 %0, t; }" : "=r"(a) : "l"(p));
    return a;
}
#define SWZ(x) ((x) ^ (((x) >> 3) & 0x70))
__device__ __forceinline__ void cpasync16(uint32_t dst, const void* src) {
    asm volatile("cp.async.cg.shared.global [%0], [%1], 16;" :: "r"(dst), "l"(src));
}
#define CP_COMMIT() asm volatile("cp.async.commit_group;" ::: "memory")
__device__ __forceinline__ void ldsm4(uint32_t* r, uint32_t addr) {
    asm volatile("ldmatrix.sync.aligned.m8n8.x4.shared.b16 {%0,%1,%2,%3}, [%4];"
        : "=r"(r[0]), "=r"(r[1]), "=r"(r[2]), "=r"(r[3]) : "r"(addr));
}
__device__ __forceinline__ void mma16816(float* c, const uint32_t* a, const uint32_t* b) {
    asm volatile("mma.sync.aligned.m16n8k16.row.col.f32.bf16.bf16.f32 "
        "{%0,%1,%2,%3}, {%4,%5,%6,%7}, {%8,%9}, {%0,%1,%2,%3};"
        : "+f"(c[0]), "+f"(c[1]), "+f"(c[2]), "+f"(c[3])
        : "r"(a[0]), "r"(a[1]), "r"(a[2]), "r"(a[3]), "r"(b[0]), "r"(b[1]));
}

// =============================================================================
// prep_w: W1c (rows 2048..3071 of W1, [k][n]) -> g_Bhi/g_Blo as [n][k] bf16
// =============================================================================
__global__ __launch_bounds__(256) void kprep_w(const float* __restrict__ W1)
{
    __shared__ float t[32][33];
    int kk0 = blockIdx.x * 32, nn0 = blockIdx.y * 32;
    int tx = threadIdx.x & 31, ty = threadIdx.x >> 5;  // (32,8)
    #pragma unroll
    for (int i = 0; i < 32; i += 8)
        t[ty + i][tx] = W1[(size_t)(2048 + kk0 + ty + i) * 1024 + nn0 + tx];
    __syncthreads();
    #pragma unroll
    for (int i = 0; i < 32; i += 8) {
        float x = t[tx][ty + i];
        __nv_bfloat16 h = __float2bfloat16(x);
        float lo = x - __bfloat162float(h);
        __nv_bfloat16 l = __float2bfloat16(lo);
        size_t o = (size_t)(nn0 + ty + i) * 1024 + kk0 + tx;
        g_Bhi[o] = __bfloat16_as_ushort(h);
        g_Blo[o] = __bfloat16_as_ushort(l);
    }
}

// =============================================================================
// prep_a: gather phrase rows per pair, split into bf16 hi/lo
// =============================================================================
__global__ __launch_bounds__(256) void kprep_a(const float* __restrict__ phrase,
                                               const int* __restrict__ pidx)
{
    int r = blockIdx.x;                 // 0..79199
    int b = r / NPAIR;
    int ph = pidx[r];
    const float4* src = (const float4*)(phrase + ((size_t)b * NPAIR + ph) * 1024);
    float4 v = src[threadIdx.x];
    ushort4 hi, lo;
    #define SPL(c, hf, lf) { __nv_bfloat16 _h = __float2bfloat16(v.c); \
        float _l = v.c - __bfloat162float(_h); \
        hf = __bfloat16_as_ushort(_h); lf = __bfloat16_as_ushort(__float2bfloat16(_l)); }
    SPL(x, hi.x, lo.x) SPL(y, hi.y, lo.y) SPL(z, hi.z, lo.z) SPL(w, hi.w, lo.w)
    #undef SPL
    size_t o = (size_t)r * 1024 + threadIdx.x * 4;
    *(ushort4*)(g_Ahi + o) = hi;
    *(ushort4*)(g_Alo + o) = lo;
}

// =============================================================================
// K1: A12[r, j] = inst[r, :] @ W1[half*1024 + :, jc]   (fp32, small)
// =============================================================================
__global__ __launch_bounds__(256) void k1_instproj(const float* __restrict__ inst,
                                                   const float* __restrict__ W1)
{
    __shared__ float As[16][68];
    __shared__ float Bs[16][64];
    int tid = threadIdx.x;
    int n0 = blockIdx.x * 64;
    int m0 = blockIdx.y * 64;
    int half = n0 >> 10;
    int jc0  = n0 & 1023;
    const float* wbase = W1 + (size_t)half * 1024 * 1024 + jc0;

    int arow = tid >> 2;
    int akq  = (tid & 3) * 4;
    int ar   = m0 + arow; if (ar > 799) ar = 799;
    const float* aptr = inst + (size_t)ar * 1024 + akq;
    int brow = tid >> 4;
    int bn   = (tid & 15) * 4;
    int tx = tid & 15, ty = tid >> 4;
    float acc[4][4] = {};

    for (int k0 = 0; k0 < 1024; k0 += 16) {
        float4 av = *(const float4*)(aptr + k0);
        float4 bv = *(const float4*)(wbase + (size_t)(k0 + brow) * 1024 + bn);
        As[akq+0][arow] = av.x; As[akq+1][arow] = av.y;
        As[akq+2][arow] = av.z; As[akq+3][arow] = av.w;
        *(float4*)&Bs[brow][bn] = bv;
        __syncthreads();
        #pragma unroll
        for (int kk = 0; kk < 16; kk++) {
            float af[4], bf[4];
            *(float4*)af = *(const float4*)&As[kk][ty*4];
            *(float4*)bf = *(const float4*)&Bs[kk][tx*4];
            #pragma unroll
            for (int i = 0; i < 4; i++)
                #pragma unroll
                for (int j = 0; j < 4; j++)
                    acc[i][j] += af[i] * bf[j];
        }
        __syncthreads();
    }
    #pragma unroll
    for (int i = 0; i < 4; i++) {
        int r = m0 + ty*4 + i;
        if (r < 800)
            *(float4*)&g_A12[(size_t)r*2048 + n0 + tx*4] =
                make_float4(acc[i][0], acc[i][1], acc[i][2], acc[i][3]);
    }
}

// =============================================================================
// K2 (mma.sync bf16 split): h = lrelu( Aphr @ W1c + A12[sub] + A12[obj] + b1 )
// CTA 128x128, K in 16 chunks of 64, cp.async double buffer, 8 warps (4M x 2N),
// warp tile 32x64. 3 products: hi*hi + lo*hi + hi*lo.
// smem stage (64KB): Ahi@0 Alo@16K Bhi@32K Blo@48K, rows of 128B, SW128 swizzle.
// =============================================================================
__device__ __forceinline__ void k2_load(uint32_t st, int tid, int k0,
                                        size_t rowbase, int p0, int n0)
{
    #pragma unroll 1
    for (int i = tid; i < 4096; i += 256) {
        int q  = i & 7;
        int rr = (i >> 3) & 127;
        uint32_t sw = SWZ(rr * 128 + q * 16);
        const unsigned short* src;
        uint32_t dst;
        if (i < 2048) {
            int p = p0 + rr; if (p > NPAIR - 1) p = NPAIR - 1;
            src = ((i < 1024) ? g_Ahi : g_Alo) + (rowbase + p) * 1024 + k0 + q * 8;
            dst = st + ((i < 1024) ? 0 : 16384) + sw;
        } else {
            src = ((i < 3072) ? g_Bhi : g_Blo) + (size_t)(n0 + rr) * 1024 + k0 + q * 8;
            dst = st + ((i < 3072) ? 32768 : 49152) + sw;
        }
        cpasync16(dst, src);
    }
}

__global__ __launch_bounds__(256, 1) void k2_mma(const float* __restrict__ b1,
                                                 const int* __restrict__ connect)
{
    extern __shared__ __align__(1024) char smem[];
    uint32_t sb = smem_u32(smem);
    int tid = threadIdx.x;
    int lane = tid & 31, wid = tid >> 5;
    int wm = wid & 3, wn = wid >> 2;       // 4 M-warps x 2 N-warps
    int n0 = blockIdx.x * 128;
    int p0 = blockIdx.y * 128;
    int b  = blockIdx.z;
    size_t rowbase = (size_t)b * NPAIR;

    float acc[2][8][4] = {};

    k2_load(sb,         tid, 0,  rowbase, p0, n0); CP_COMMIT();
    k2_load(sb + 65536, tid, KC, rowbase, p0, n0); CP_COMMIT();

    #pragma unroll 1
    for (int c = 0; c < 16; c++) {
        if (c < 15) asm volatile("cp.async.wait_group 1;" ::: "memory");
        else        asm volatile("cp.async.wait_group 0;" ::: "memory");
        __syncthreads();

        uint32_t st  = sb + (c & 1) * 65536;
        uint32_t sAh = st, sAl = st + 16384, sBh = st + 32768, sBl = st + 49152;

        #pragma unroll
        for (int ks = 0; ks < 4; ks++) {
            int kb = ks * 32;
            uint32_t ah[2][4], al[2][4], bh[4][4], bl[4][4];
            #pragma unroll
            for (int mt = 0; mt < 2; mt++) {
                uint32_t off = SWZ((wm*32 + mt*16 + (lane & 15)) * 128 + kb + (lane >> 4) * 16);
                ldsm4(ah[mt], sAh + off);
                ldsm4(al[mt], sAl + off);
            }
            int nrow  = (lane & 7) + ((lane >> 4) & 1) * 8;
            int khalf = ((lane >> 3) & 1) * 16;
            #pragma unroll
            for (int ntq = 0; ntq < 4; ntq++) {
                uint32_t off = SWZ((wn*64 + ntq*16 + nrow) * 128 + kb + khalf);
                ldsm4(bh[ntq], sBh + off);
                ldsm4(bl[ntq], sBl + off);
            }
            #pragma unroll
            for (int mt = 0; mt < 2; mt++)
                #pragma unroll
                for (int nt = 0; nt < 8; nt++) {
                    const uint32_t* bhp = &bh[nt >> 1][(nt & 1) * 2];
                    const uint32_t* blp = &bl[nt >> 1][(nt & 1) * 2];
                    mma16816(acc[mt][nt], ah[mt], bhp);
                    mma16816(acc[mt][nt], al[mt], bhp);
                    mma16816(acc[mt][nt], ah[mt], blp);
                }
        }
        __syncthreads();
        if (c + 2 < 16) {
            k2_load(sb + (c & 1) * 65536, tid, (c + 2) * KC, rowbase, p0, n0);
            CP_COMMIT();
        }
    }

    // ---- epilogue: acc + A12[sub] + A12[obj] + b1, lrelu, store g_h ----
    int gp = lane >> 2, tq = lane & 3;
    int n0w = n0 + wn * 64;
    size_t bb2 = (size_t)b * 2 * NPAIR;
    const float* a12b = g_A12 + (size_t)b * NINST * 2048;
    #pragma unroll
    for (int mt = 0; mt < 2; mt++) {
        #pragma unroll
        for (int half = 0; half < 2; half++) {
            int p = p0 + wm*32 + mt*16 + gp + half*8;
            if (p >= NPAIR) continue;
            int sub = connect[bb2 + p];
            int obj = connect[bb2 + NPAIR + p];
            const float* r1 = a12b + (size_t)sub * 2048 + n0w;
            const float* r2 = a12b + (size_t)obj * 2048 + 1024 + n0w;
            float* ho = g_h + ((size_t)b * NPAIR + p) * 1024 + n0w;
            #pragma unroll
            for (int nt = 0; nt < 8; nt++) {
                int cc = nt*8 + tq*2;
                float2 v1 = *(const float2*)(r1 + cc);
                float2 v2 = *(const float2*)(r2 + cc);
                float2 vb = *(const float2*)(b1 + n0w + cc);
                float x = acc[mt][nt][half*2+0] + v1.x + v2.x + vb.x;
                float y = acc[mt][nt][half*2+1] + v1.y + v2.y + vb.y;
                x = x > 0.f ? x : 0.01f * x;
                y = y > 0.f ? y : 0.01f * y;
                *(float2*)(ho + cc) = make_float2(x, y);
            }
        }
    }
}

// =============================================================================
// K3a: logits = h @ W2 + b2    (fp32)
// =============================================================================
__global__ __launch_bounds__(256) void k3a_logits(const float* __restrict__ W2,
                                                  const float* __restrict__ b2,
                                                  float* __restrict__ out_logits)
{
    __shared__ float hsm[32][132];
    __shared__ float w2s[32][64];
    int tid = threadIdx.x;
    size_t row0 = (size_t)blockIdx.x * 128;
    int lr = tid >> 1;
    int lk = (tid & 1) * 16;
    size_t grow = row0 + lr; if (grow > (size_t)NROWS - 1) grow = NROWS - 1;
    const float* hptr = g_h + grow * 1024 + lk;
    int tx = tid & 15, ty = tid >> 4;
    float acc[8][4] = {};

    for (int k0 = 0; k0 < 1024; k0 += 32) {
        #pragma unroll
        for (int q = 0; q < 4; q++) {
            float4 v = *(const float4*)(hptr + k0 + q*4);
            hsm[lk + q*4 + 0][lr] = v.x;
            hsm[lk + q*4 + 1][lr] = v.y;
            hsm[lk + q*4 + 2][lr] = v.z;
            hsm[lk + q*4 + 3][lr] = v.w;
        }
        for (int idx = tid; idx < 32*64; idx += 256) {
            int kk = idx >> 6, c = idx & 63;
            w2s[kk][c] = (c < NCLS) ? W2[(size_t)(k0 + kk)*NCLS + c] : 0.f;
        }
        __syncthreads();
        #pragma unroll
        for (int kk = 0; kk < 32; kk++) {
            float af[8], bf[4];
            *(float4*)&af[0] = *(const float4*)&hsm[kk][ty*8];
            *(float4*)&af[4] = *(const float4*)&hsm[kk][ty*8+4];
            *(float4*)bf = *(const float4*)&w2s[kk][tx*4];
            #pragma unroll
            for (int i = 0; i < 8; i++)
                #pragma unroll
                for (int j = 0; j < 4; j++)
                    acc[i][j] += af[i]*bf[j];
        }
        __syncthreads();
    }
    #pragma unroll
    for (int j = 0; j < 4; j++) {
        int c = tx*4 + j;
        if (c >= NCLS) continue;
        float bb = b2[c];
        #pragma unroll
        for (int i = 0; i < 8; i++) {
            size_t r = row0 + (size_t)ty*8 + i;
            if (r < NROWS) out_logits[r*NCLS + c] = acc[i][j] + bb;
        }
    }
}

// =============================================================================
// K3b: softmax -> probs output; fp32 overall (ranking key)
// =============================================================================
__global__ void k3b_softmax(const float* __restrict__ out_logits,
                            const float* __restrict__ scores,
                            const int*   __restrict__ connect,
                            float* __restrict__ out_probs)
{
    int row = blockIdx.x * blockDim.x + threadIdx.x;
    if (row >= NROWS) return;
    const float* lp = out_logits + (size_t)row * NCLS;
    float l[NCLS];
    float m = -1e30f;
    #pragma unroll
    for (int c = 0; c < NCLS; c++) { l[c] = lp[c]; m = fmaxf(m, l[c]); }
    float s = 0.f;
    #pragma unroll
    for (int c = 0; c < NCLS; c++) { l[c] = expf(l[c] - m); s += l[c]; }
    float* pp = out_probs + (size_t)row * NCLS;
    float best = 0.f;
    #pragma unroll
    for (int c = 0; c < NCLS; c++) {
        float pr = l[c] / s;
        pp[c] = pr;
        if (c >= 1 && pr > best) best = pr;
    }
    int b = row / NPAIR, p = row % NPAIR;
    int si = connect[(size_t)b*2*NPAIR + p];
    int oi = connect[(size_t)b*2*NPAIR + NPAIR + p];
    g_overall[row] = best * scores[b*NINST + si] * scores[b*NINST + oi];
}

// =============================================================================
// K4: warp-tournament top-NCAND selection (set only; order fixed later in fp64)
// =============================================================================
__global__ __launch_bounds__(1024) void k4_select()
{
    __shared__ float vals[NPAIR];
    __shared__ float wmax[32];
    __shared__ int   warg[32];
    __shared__ int   s_win;
    int b = blockIdx.x, tid = threadIdx.x, w = tid >> 5, lane = tid & 31;
    for (int i = tid; i < NPAIR; i += 1024) vals[i] = g_overall[b*NPAIR + i];
    __syncthreads();

    int lo = w * 310;
    int hiv = lo + 310; if (hiv > NPAIR) hiv = NPAIR;
    float bv = -1.f; int bi = 0x7fffffff;
    for (int i = lo + lane; i < hiv; i += 32) {
        float v = vals[i];
        if (v > bv || (v == bv && i < bi)) { bv = v; bi = i; }
    }
    #pragma unroll
    for (int o = 16; o; o >>= 1) {
        float ov = __shfl_down_sync(0xffffffffu, bv, o);
        int   oi = __shfl_down_sync(0xffffffffu, bi, o);
        if (ov > bv || (ov == bv && oi < bi)) { bv = ov; bi = oi; }
    }
    if (lane == 0) { wmax[w] = bv; warg[w] = bi; }
    __syncthreads();

    for (int t = 0; t < NCAND; t++) {
        if (tid < 32) {
            float v = wmax[lane]; int i2 = warg[lane];
            #pragma unroll
            for (int o = 16; o; o >>= 1) {
                float ov = __shfl_down_sync(0xffffffffu, v, o);
                int   oi = __shfl_down_sync(0xffffffffu, i2, o);
                if (ov > v || (ov == v && oi < i2)) { v = ov; i2 = oi; }
            }
            if (lane == 0) {
                g_cand_idx[b*NCAND + t] = i2;
                vals[i2] = -2.f;
                s_win = i2 / 310;
            }
        }
        __syncthreads();
        if (w == s_win) {
            float nv = -1.f; int ni = 0x7fffffff;
            for (int i = lo + lane; i < hiv; i += 32) {
                float v = vals[i];
                if (v > nv || (v == nv && i < ni)) { nv = v; ni = i; }
            }
            #pragma unroll
            for (int o = 16; o; o >>= 1) {
                float ov = __shfl_down_sync(0xffffffffu, nv, o);
                int   oi = __shfl_down_sync(0xffffffffu, ni, o);
                if (ov > nv || (ov == nv && oi < ni)) { nv = ov; ni = oi; }
            }
            if (lane == 0) { wmax[w] = nv; warg[w] = ni; }
        }
        __syncthreads();
    }
}

// =============================================================================
// K5: fp64 exact h for candidates (4 candidates/block)
// =============================================================================
#define CPB 4
__global__ __launch_bounds__(256) void k5_repair_h(const float* __restrict__ inst,
                                                   const float* __restrict__ phrase,
                                                   const float* __restrict__ W1,
                                                   const float* __restrict__ b1,
                                                   const int*   __restrict__ connect,
                                                   const int*   __restrict__ pidx)
{
    __shared__ float sf[CPB][3072];
    int b = blockIdx.x >> 5;
    int g = blockIdx.x & 31;
    int tid = threadIdx.x;

    for (int c = 0; c < CPB; c++) {
        int slot = b*NCAND + g*CPB + c;
        int p  = g_cand_idx[slot];
        int si = connect[(size_t)b*2*NPAIR + p];
        int oi = connect[(size_t)b*2*NPAIR + NPAIR + p];
        int ph = pidx[b*NPAIR + p];
        const float* s0 = inst   + ((size_t)b*NINST + si)*1024;
        const float* s1 = inst   + ((size_t)b*NINST + oi)*1024;
        const float* s2 = phrase + ((size_t)b*NPAIR + ph)*1024;
        for (int k = tid; k < 1024; k += 256) {
            sf[c][k]        = s0[k];
            sf[c][1024 + k] = s1[k];
            sf[c][2048 + k] = s2[k];
        }
    }
    __syncthreads();

    double acc[CPB][4] = {};
    for (int k = 0; k < 3072; k++) {
        const float* wr = W1 + (size_t)k*1024 + tid;
        double w0 = (double)wr[0];
        double w1v = (double)wr[256];
        double w2v = (double)wr[512];
        double w3 = (double)wr[768];
        #pragma unroll
        for (int c = 0; c < CPB; c++) {
            double f = (double)sf[c][k];
            acc[c][0] = fma(f, w0,  acc[c][0]);
            acc[c][1] = fma(f, w1v, acc[c][1]);
            acc[c][2] = fma(f, w2v, acc[c][2]);
            acc[c][3] = fma(f, w3,  acc[c][3]);
        }
    }
    #pragma unroll
    for (int c = 0; c < CPB; c++) {
        int slot = b*NCAND + g*CPB + c;
        #pragma unroll
        for (int j = 0; j < 4; j++) {
            double v = acc[c][j] + (double)b1[tid + j*256];
            v = v > 0.0 ? v : 0.01 * v;
            g_hd[(size_t)slot*1024 + tid + j*256] = v;
        }
    }
}

// =============================================================================
// K6: fp64 logits + softmax + decisions per candidate
// =============================================================================
__global__ __launch_bounds__(64) void k6_decide(const float* __restrict__ W2,
                                                const float* __restrict__ b2,
                                                const float* __restrict__ scores,
                                                const int*   __restrict__ connect)
{
    __shared__ double sh[1024];
    __shared__ double slog[NCLS];
    int slot = blockIdx.x;
    int tid = threadIdx.x;
    const double* hd = g_hd + (size_t)slot*1024;
    for (int k = tid; k < 1024; k += 64) sh[k] = hd[k];
    __syncthreads();

    if (tid < NCLS) {
        double acc = 0.0;
        #pragma unroll 8
        for (int k = 0; k < 1024; k++)
            acc = fma(sh[k], (double)W2[(size_t)k*NCLS + tid], acc);
        slog[tid] = acc + (double)b2[tid];
    }
    __syncthreads();

    if (tid == 0) {
        double m = slog[0];
        for (int c = 1; c < NCLS; c++) m = slog[c] > m ? slog[c] : m;
        double e[NCLS]; double s = 0.0;
        for (int c = 0; c < NCLS; c++) { e[c] = exp(slog[c] - m); s += e[c]; }
        double best = 0.0; int bl = 0;
        for (int c = 1; c < NCLS; c++) {
            double pr = e[c] / s;
            if (pr > best) { best = pr; bl = c; }
        }
        int b = slot >> 7;
        int p = g_cand_idx[slot];
        int si = connect[(size_t)b*2*NPAIR + p];
        int oi = connect[(size_t)b*2*NPAIR + NPAIR + p];
        double ov = best * (double)scores[b*NINST + si] * (double)scores[b*NINST + oi];
        g_cand_ovr[slot]  = ov;
        g_cand_prob[slot] = best;
        g_cand_lab[slot]  = bl;
    }
}

// =============================================================================
// K7: final top-100 per batch over NCAND fp64 candidates (tie -> smaller idx)
// =============================================================================
__global__ __launch_bounds__(128) void k7_final(float* __restrict__ outbase)
{
    __shared__ double v[NCAND];
    __shared__ int    pix[NCAND];
    int b = blockIdx.x, tid = threadIdx.x;
    v[tid]   = g_cand_ovr[b*NCAND + tid];
    pix[tid] = g_cand_idx[b*NCAND + tid];
    __syncthreads();

    if (tid == 0) {
        float* out_lab  = outbase;
        float* out_prob = outbase + 800;
        float* out_val  = outbase + 1600;
        float* out_idx  = outbase + 2400;
        for (int t = 0; t < 100; t++) {
            double bv = -1.0; int bj = 0; int bidx = 0x7fffffff;
            for (int j = 0; j < NCAND; j++) {
                double val = v[j]; int ix = pix[j];
                if (val > bv || (val == bv && ix < bidx)) { bv = val; bj = j; bidx = ix; }
            }
            int slot2 = b*NCAND + bj;
            out_val [b*100 + t] = (float)bv;
            out_idx [b*100 + t] = (float)bidx;
            out_lab [b*100 + t] = (float)g_cand_lab[slot2];
            out_prob[b*100 + t] = (float)g_cand_prob[slot2];
            v[bj] = -2.0;
        }
    }
}

// =============================================================================
extern "C" void kernel_launch(void* const* d_in, const int* in_sizes, int n_in,
                              void* d_out, int out_size)
{
    const float* inst    = (const float*)d_in[0];
    const float* phrase  = (const float*)d_in[1];
    const float* scores  = (const float*)d_in[2];
    const float* W1      = (const float*)d_in[3];
    const float* b1      = (const float*)d_in[4];
    const float* W2      = (const float*)d_in[5];
    const float* b2      = (const float*)d_in[6];
    const int*   connect = (const int*)d_in[7];
    const int*   pidx    = (const int*)d_in[8];

    float* out        = (float*)d_out;
    float* out_logits = out;
    float* out_probs  = out + (size_t)BATCH*NPAIR*NCLS;
    float* out_top    = out + (size_t)2*BATCH*NPAIR*NCLS;

    cudaFuncSetAttribute(k2_mma, cudaFuncAttributeMaxDynamicSharedMemorySize, K2_SMEM);

    kprep_w<<<dim3(32, 32), 256>>>(W1);
    kprep_a<<<NROWS, 256>>>(phrase, pidx);
    k1_instproj<<<dim3(32, 13), 256>>>(inst, W1);
    k2_mma<<<dim3(8, 78, BATCH), 256, K2_SMEM>>>(b1, connect);
    k3a_logits<<<619, 256>>>(W2, b2, out_logits);
    k3b_softmax<<<(NROWS + 255) / 256, 256>>>(out_logits, scores, connect, out_probs);
    k4_select<<<BATCH, 1024>>>();
    k5_repair_h<<<BATCH*32, 256>>>(inst, phrase, W1, b1, connect, pidx);
    k6_decide<<<BATCH*NCAND, 64>>>(W2, b2, scores, connect);
    k7_final<<<BATCH, 128>>>(out_top);
}

// round 5
// speedup vs baseline: 1.1672x; 1.0687x over previous
#include <cuda_runtime.h>
#include <cuda_bf16.h>
#include <math.h>
#include <stdint.h>

#define BATCH 8
#define NINST 100
#define NPAIR 9900
#define NCLS  51
#define NROWS (BATCH*NPAIR)   // 79200
#define NCAND 128
#define KC    64
#define K2_SMEM (128*1024)

// ---------------- scratch (device globals; no allocs allowed) ----------------
__device__ float  g_A12[BATCH*NINST*2048];
__device__ float  g_h[81100800];                // 79200 x 1024 fp32
__device__ float  g_overall[NROWS];
__device__ int    g_cand_idx[BATCH*NCAND];
__device__ int    g_cand_lab[BATCH*NCAND];
__device__ double g_cand_prob[BATCH*NCAND];
__device__ double g_cand_ovr[BATCH*NCAND];
__device__ double g_hd2[2][BATCH*NCAND*1024];  // fp64 partial hidden (K halves)
__device__ __align__(16) unsigned short g_Ahi[81100800];  // gathered phrase, bf16 hi
__device__ __align__(16) unsigned short g_Alo[81100800];  // bf16 lo
__device__ __align__(16) unsigned short g_Bhi[1024*1024]; // W1c^T [n][k] bf16 hi
__device__ __align__(16) unsigned short g_Blo[1024*1024];

// ---------------- helpers (baseline PTX only) ----------------
__device__ __forceinline__ uint32_t smem_u32(const void* p) {
    uint32_t a;
    asm("{ .reg .u64 t; cvta.to.shared.u64 t, %1; cvt.u32.u64 %0, t; }" : "=r"(a) : "l"(p));
    return a;
}
#define SWZ(x) ((x) ^ (((x) >> 3) & 0x70))
__device__ __forceinline__ void cpasync16(uint32_t dst, const void* src) {
    asm volatile("cp.async.cg.shared.global [%0], [%1], 16;" :: "r"(dst), "l"(src));
}
#define CP_COMMIT() asm volatile("cp.async.commit_group;" ::: "memory")
__device__ __forceinline__ void ldsm4(uint32_t* r, uint32_t addr) {
    asm volatile("ldmatrix.sync.aligned.m8n8.x4.shared.b16 {%0,%1,%2,%3}, [%4];"
        : "=r"(r[0]), "=r"(r[1]), "=r"(r[2]), "=r"(r[3]) : "r"(addr));
}
__device__ __forceinline__ void mma16816(float* c, const uint32_t* a, const uint32_t* b) {
    asm volatile("mma.sync.aligned.m16n8k16.row.col.f32.bf16.bf16.f32 "
        "{%0,%1,%2,%3}, {%4,%5,%6,%7}, {%8,%9}, {%0,%1,%2,%3};"
        : "+f"(c[0]), "+f"(c[1]), "+f"(c[2]), "+f"(c[3])
        : "r"(a[0]), "r"(a[1]), "r"(a[2]), "r"(a[3]), "r"(b[0]), "r"(b[1]));
}

// =============================================================================
// prep_w: W1c (rows 2048..3071 of W1, [k][n]) -> g_Bhi/g_Blo as [n][k] bf16
// =============================================================================
__global__ __launch_bounds__(256) void kprep_w(const float* __restrict__ W1)
{
    __shared__ float t[32][33];
    int kk0 = blockIdx.x * 32, nn0 = blockIdx.y * 32;
    int tx = threadIdx.x & 31, ty = threadIdx.x >> 5;
    #pragma unroll
    for (int i = 0; i < 32; i += 8)
        t[ty + i][tx] = W1[(size_t)(2048 + kk0 + ty + i) * 1024 + nn0 + tx];
    __syncthreads();
    #pragma unroll
    for (int i = 0; i < 32; i += 8) {
        float x = t[tx][ty + i];
        __nv_bfloat16 h = __float2bfloat16(x);
        float lo = x - __bfloat162float(h);
        __nv_bfloat16 l = __float2bfloat16(lo);
        size_t o = (size_t)(nn0 + ty + i) * 1024 + kk0 + tx;
        g_Bhi[o] = __bfloat16_as_ushort(h);
        g_Blo[o] = __bfloat16_as_ushort(l);
    }
}

// =============================================================================
// prep_a: gather phrase rows per pair, split into bf16 hi/lo
// =============================================================================
__global__ __launch_bounds__(256) void kprep_a(const float* __restrict__ phrase,
                                               const int* __restrict__ pidx)
{
    int r = blockIdx.x;
    int b = r / NPAIR;
    int ph = pidx[r];
    const float4* src = (const float4*)(phrase + ((size_t)b * NPAIR + ph) * 1024);
    float4 v = src[threadIdx.x];
    ushort4 hi, lo;
    #define SPL(c, hf, lf) { __nv_bfloat16 _h = __float2bfloat16(v.c); \
        float _l = v.c - __bfloat162float(_h); \
        hf = __bfloat16_as_ushort(_h); lf = __bfloat16_as_ushort(__float2bfloat16(_l)); }
    SPL(x, hi.x, lo.x) SPL(y, hi.y, lo.y) SPL(z, hi.z, lo.z) SPL(w, hi.w, lo.w)
    #undef SPL
    size_t o = (size_t)r * 1024 + threadIdx.x * 4;
    *(ushort4*)(g_Ahi + o) = hi;
    *(ushort4*)(g_Alo + o) = lo;
}

// =============================================================================
// K1: A12[r, j] = inst[r, :] @ W1[half*1024 + :, jc]   (fp32, small)
// =============================================================================
__global__ __launch_bounds__(256) void k1_instproj(const float* __restrict__ inst,
                                                   const float* __restrict__ W1)
{
    __shared__ float As[16][68];
    __shared__ float Bs[16][64];
    int tid = threadIdx.x;
    int n0 = blockIdx.x * 64;
    int m0 = blockIdx.y * 64;
    int half = n0 >> 10;
    int jc0  = n0 & 1023;
    const float* wbase = W1 + (size_t)half * 1024 * 1024 + jc0;

    int arow = tid >> 2;
    int akq  = (tid & 3) * 4;
    int ar   = m0 + arow; if (ar > 799) ar = 799;
    const float* aptr = inst + (size_t)ar * 1024 + akq;
    int brow = tid >> 4;
    int bn   = (tid & 15) * 4;
    int tx = tid & 15, ty = tid >> 4;
    float acc[4][4] = {};

    for (int k0 = 0; k0 < 1024; k0 += 16) {
        float4 av = *(const float4*)(aptr + k0);
        float4 bv = *(const float4*)(wbase + (size_t)(k0 + brow) * 1024 + bn);
        As[akq+0][arow] = av.x; As[akq+1][arow] = av.y;
        As[akq+2][arow] = av.z; As[akq+3][arow] = av.w;
        *(float4*)&Bs[brow][bn] = bv;
        __syncthreads();
        #pragma unroll
        for (int kk = 0; kk < 16; kk++) {
            float af[4], bf[4];
            *(float4*)af = *(const float4*)&As[kk][ty*4];
            *(float4*)bf = *(const float4*)&Bs[kk][tx*4];
            #pragma unroll
            for (int i = 0; i < 4; i++)
                #pragma unroll
                for (int j = 0; j < 4; j++)
                    acc[i][j] += af[i] * bf[j];
        }
        __syncthreads();
    }
    #pragma unroll
    for (int i = 0; i < 4; i++) {
        int r = m0 + ty*4 + i;
        if (r < 800)
            *(float4*)&g_A12[(size_t)r*2048 + n0 + tx*4] =
                make_float4(acc[i][0], acc[i][1], acc[i][2], acc[i][3]);
    }
}

// =============================================================================
// K2 (mma.sync bf16 split): h = lrelu( Aphr @ W1c + A12[sub] + A12[obj] + b1 )
// =============================================================================
__device__ __forceinline__ void k2_load(uint32_t st, int tid, int k0,
                                        size_t rowbase, int p0, int n0)
{
    #pragma unroll 1
    for (int i = tid; i < 4096; i += 256) {
        int q  = i & 7;
        int rr = (i >> 3) & 127;
        uint32_t sw = SWZ(rr * 128 + q * 16);
        const unsigned short* src;
        uint32_t dst;
        if (i < 2048) {
            int p = p0 + rr; if (p > NPAIR - 1) p = NPAIR - 1;
            src = ((i < 1024) ? g_Ahi : g_Alo) + (rowbase + p) * 1024 + k0 + q * 8;
            dst = st + ((i < 1024) ? 0 : 16384) + sw;
        } else {
            src = ((i < 3072) ? g_Bhi : g_Blo) + (size_t)(n0 + rr) * 1024 + k0 + q * 8;
            dst = st + ((i < 3072) ? 32768 : 49152) + sw;
        }
        cpasync16(dst, src);
    }
}

__global__ __launch_bounds__(256, 1) void k2_mma(const float* __restrict__ b1,
                                                 const int* __restrict__ connect)
{
    extern __shared__ __align__(1024) char smem[];
    uint32_t sb = smem_u32(smem);
    int tid = threadIdx.x;
    int lane = tid & 31, wid = tid >> 5;
    int wm = wid & 3, wn = wid >> 2;
    int n0 = blockIdx.x * 128;
    int p0 = blockIdx.y * 128;
    int b  = blockIdx.z;
    size_t rowbase = (size_t)b * NPAIR;

    float acc[2][8][4] = {};

    k2_load(sb,         tid, 0,  rowbase, p0, n0); CP_COMMIT();
    k2_load(sb + 65536, tid, KC, rowbase, p0, n0); CP_COMMIT();

    #pragma unroll 1
    for (int c = 0; c < 16; c++) {
        if (c < 15) asm volatile("cp.async.wait_group 1;" ::: "memory");
        else        asm volatile("cp.async.wait_group 0;" ::: "memory");
        __syncthreads();

        uint32_t st  = sb + (c & 1) * 65536;
        uint32_t sAh = st, sAl = st + 16384, sBh = st + 32768, sBl = st + 49152;

        #pragma unroll
        for (int ks = 0; ks < 4; ks++) {
            int kb = ks * 32;
            uint32_t ah[2][4], al[2][4], bh[4][4], bl[4][4];
            #pragma unroll
            for (int mt = 0; mt < 2; mt++) {
                uint32_t off = SWZ((wm*32 + mt*16 + (lane & 15)) * 128 + kb + (lane >> 4) * 16);
                ldsm4(ah[mt], sAh + off);
                ldsm4(al[mt], sAl + off);
            }
            int nrow  = (lane & 7) + ((lane >> 4) & 1) * 8;
            int khalf = ((lane >> 3) & 1) * 16;
            #pragma unroll
            for (int ntq = 0; ntq < 4; ntq++) {
                uint32_t off = SWZ((wn*64 + ntq*16 + nrow) * 128 + kb + khalf);
                ldsm4(bh[ntq], sBh + off);
                ldsm4(bl[ntq], sBl + off);
            }
            #pragma unroll
            for (int mt = 0; mt < 2; mt++)
                #pragma unroll
                for (int nt = 0; nt < 8; nt++) {
                    const uint32_t* bhp = &bh[nt >> 1][(nt & 1) * 2];
                    const uint32_t* blp = &bl[nt >> 1][(nt & 1) * 2];
                    mma16816(acc[mt][nt], ah[mt], bhp);
                    mma16816(acc[mt][nt], al[mt], bhp);
                    mma16816(acc[mt][nt], ah[mt], blp);
                }
        }
        __syncthreads();
        if (c + 2 < 16) {
            k2_load(sb + (c & 1) * 65536, tid, (c + 2) * KC, rowbase, p0, n0);
            CP_COMMIT();
        }
    }

    int gp = lane >> 2, tq = lane & 3;
    int n0w = n0 + wn * 64;
    size_t bb2 = (size_t)b * 2 * NPAIR;
    const float* a12b = g_A12 + (size_t)b * NINST * 2048;
    #pragma unroll
    for (int mt = 0; mt < 2; mt++) {
        #pragma unroll
        for (int half = 0; half < 2; half++) {
            int p = p0 + wm*32 + mt*16 + gp + half*8;
            if (p >= NPAIR) continue;
            int sub = connect[bb2 + p];
            int obj = connect[bb2 + NPAIR + p];
            const float* r1 = a12b + (size_t)sub * 2048 + n0w;
            const float* r2 = a12b + (size_t)obj * 2048 + 1024 + n0w;
            float* ho = g_h + ((size_t)b * NPAIR + p) * 1024 + n0w;
            #pragma unroll
            for (int nt = 0; nt < 8; nt++) {
                int cc = nt*8 + tq*2;
                float2 v1 = *(const float2*)(r1 + cc);
                float2 v2 = *(const float2*)(r2 + cc);
                float2 vb = *(const float2*)(b1 + n0w + cc);
                float x = acc[mt][nt][half*2+0] + v1.x + v2.x + vb.x;
                float y = acc[mt][nt][half*2+1] + v1.y + v2.y + vb.y;
                x = x > 0.f ? x : 0.01f * x;
                y = y > 0.f ? y : 0.01f * y;
                *(float2*)(ho + cc) = make_float2(x, y);
            }
        }
    }
}

// =============================================================================
// K3a: logits = h @ W2 + b2    (fp32)
// =============================================================================
__global__ __launch_bounds__(256) void k3a_logits(const float* __restrict__ W2,
                                                  const float* __restrict__ b2,
                                                  float* __restrict__ out_logits)
{
    __shared__ float hsm[32][132];
    __shared__ float w2s[32][64];
    int tid = threadIdx.x;
    size_t row0 = (size_t)blockIdx.x * 128;
    int lr = tid >> 1;
    int lk = (tid & 1) * 16;
    size_t grow = row0 + lr; if (grow > (size_t)NROWS - 1) grow = NROWS - 1;
    const float* hptr = g_h + grow * 1024 + lk;
    int tx = tid & 15, ty = tid >> 4;
    float acc[8][4] = {};

    for (int k0 = 0; k0 < 1024; k0 += 32) {
        #pragma unroll
        for (int q = 0; q < 4; q++) {
            float4 v = *(const float4*)(hptr + k0 + q*4);
            hsm[lk + q*4 + 0][lr] = v.x;
            hsm[lk + q*4 + 1][lr] = v.y;
            hsm[lk + q*4 + 2][lr] = v.z;
            hsm[lk + q*4 + 3][lr] = v.w;
        }
        for (int idx = tid; idx < 32*64; idx += 256) {
            int kk = idx >> 6, c = idx & 63;
            w2s[kk][c] = (c < NCLS) ? W2[(size_t)(k0 + kk)*NCLS + c] : 0.f;
        }
        __syncthreads();
        #pragma unroll
        for (int kk = 0; kk < 32; kk++) {
            float af[8], bf[4];
            *(float4*)&af[0] = *(const float4*)&hsm[kk][ty*8];
            *(float4*)&af[4] = *(const float4*)&hsm[kk][ty*8+4];
            *(float4*)bf = *(const float4*)&w2s[kk][tx*4];
            #pragma unroll
            for (int i = 0; i < 8; i++)
                #pragma unroll
                for (int j = 0; j < 4; j++)
                    acc[i][j] += af[i]*bf[j];
        }
        __syncthreads();
    }
    #pragma unroll
    for (int j = 0; j < 4; j++) {
        int c = tx*4 + j;
        if (c >= NCLS) continue;
        float bb = b2[c];
        #pragma unroll
        for (int i = 0; i < 8; i++) {
            size_t r = row0 + (size_t)ty*8 + i;
            if (r < NROWS) out_logits[r*NCLS + c] = acc[i][j] + bb;
        }
    }
}

// =============================================================================
// K3b: softmax -> probs output; fp32 overall (ranking key)
// =============================================================================
__global__ void k3b_softmax(const float* __restrict__ out_logits,
                            const float* __restrict__ scores,
                            const int*   __restrict__ connect,
                            float* __restrict__ out_probs)
{
    int row = blockIdx.x * blockDim.x + threadIdx.x;
    if (row >= NROWS) return;
    const float* lp = out_logits + (size_t)row * NCLS;
    float l[NCLS];
    float m = -1e30f;
    #pragma unroll
    for (int c = 0; c < NCLS; c++) { l[c] = lp[c]; m = fmaxf(m, l[c]); }
    float s = 0.f;
    #pragma unroll
    for (int c = 0; c < NCLS; c++) { l[c] = expf(l[c] - m); s += l[c]; }
    float inv = 1.0f / s;
    float* pp = out_probs + (size_t)row * NCLS;
    float best = 0.f;
    #pragma unroll
    for (int c = 0; c < NCLS; c++) {
        float pr = l[c] * inv;
        pp[c] = pr;
        if (c >= 1 && pr > best) best = pr;
    }
    int b = row / NPAIR, p = row % NPAIR;
    int si = connect[(size_t)b*2*NPAIR + p];
    int oi = connect[(size_t)b*2*NPAIR + NPAIR + p];
    g_overall[row] = best * scores[b*NINST + si] * scores[b*NINST + oi];
}

// =============================================================================
// K4: warp-tournament top-NCAND selection
// =============================================================================
__global__ __launch_bounds__(1024) void k4_select()
{
    __shared__ float vals[NPAIR];
    __shared__ float wmax[32];
    __shared__ int   warg[32];
    __shared__ int   s_win;
    int b = blockIdx.x, tid = threadIdx.x, w = tid >> 5, lane = tid & 31;
    for (int i = tid; i < NPAIR; i += 1024) vals[i] = g_overall[b*NPAIR + i];
    __syncthreads();

    int lo = w * 310;
    int hiv = lo + 310; if (hiv > NPAIR) hiv = NPAIR;
    float bv = -1.f; int bi = 0x7fffffff;
    for (int i = lo + lane; i < hiv; i += 32) {
        float v = vals[i];
        if (v > bv || (v == bv && i < bi)) { bv = v; bi = i; }
    }
    #pragma unroll
    for (int o = 16; o; o >>= 1) {
        float ov = __shfl_down_sync(0xffffffffu, bv, o);
        int   oi = __shfl_down_sync(0xffffffffu, bi, o);
        if (ov > bv || (ov == bv && oi < bi)) { bv = ov; bi = oi; }
    }
    if (lane == 0) { wmax[w] = bv; warg[w] = bi; }
    __syncthreads();

    for (int t = 0; t < NCAND; t++) {
        if (tid < 32) {
            float v = wmax[lane]; int i2 = warg[lane];
            #pragma unroll
            for (int o = 16; o; o >>= 1) {
                float ov = __shfl_down_sync(0xffffffffu, v, o);
                int   oi = __shfl_down_sync(0xffffffffu, i2, o);
                if (ov > v || (ov == v && oi < i2)) { v = ov; i2 = oi; }
            }
            if (lane == 0) {
                g_cand_idx[b*NCAND + t] = i2;
                vals[i2] = -2.f;
                s_win = i2 / 310;
            }
        }
        __syncthreads();
        if (w == s_win) {
            float nv = -1.f; int ni = 0x7fffffff;
            for (int i = lo + lane; i < hiv; i += 32) {
                float v = vals[i];
                if (v > nv || (v == nv && i < ni)) { nv = v; ni = i; }
            }
            #pragma unroll
            for (int o = 16; o; o >>= 1) {
                float ov = __shfl_down_sync(0xffffffffu, nv, o);
                int   oi = __shfl_down_sync(0xffffffffu, ni, o);
                if (ov > nv || (ov == nv && oi < ni)) { nv = ov; ni = oi; }
            }
            if (lane == 0) { wmax[w] = nv; warg[w] = ni; }
        }
        __syncthreads();
    }
}

// =============================================================================
// K5 v2: fp64 exact partial h for candidates.
// grid (ksplit=2, 16 groups, 8 batch); 8 cand/block; float4 W1 loads.
// Each thread owns output cols tid*4..tid*4+3 for K-half [ks*1536, +1536).
// =============================================================================
__global__ __launch_bounds__(256) void k5_repair_h(const float* __restrict__ inst,
                                                   const float* __restrict__ phrase,
                                                   const float* __restrict__ W1,
                                                   const int*   __restrict__ connect,
                                                   const int*   __restrict__ pidx)
{
    __shared__ float sf[8][1536];   // 48 KB
    int ks = blockIdx.x;            // 0..1 K half
    int g  = blockIdx.y;            // 0..15 candidate group
    int b  = blockIdx.z;            // batch
    int tid = threadIdx.x;
    int k0 = ks * 1536;

    #pragma unroll 1
    for (int c = 0; c < 8; c++) {
        int slot = b*NCAND + g*8 + c;
        int p  = g_cand_idx[slot];
        int si = connect[(size_t)b*2*NPAIR + p];
        int oi = connect[(size_t)b*2*NPAIR + NPAIR + p];
        int ph = pidx[b*NPAIR + p];
        const float* s0 = inst   + ((size_t)b*NINST + si)*1024;
        const float* s1 = inst   + ((size_t)b*NINST + oi)*1024;
        const float* s2 = phrase + ((size_t)b*NPAIR + ph)*1024;
        for (int k = tid; k < 1536; k += 256) {
            int f = k0 + k;
            float v;
            if (f < 1024)       v = s0[f];
            else if (f < 2048)  v = s1[f - 1024];
            else                v = s2[f - 2048];
            sf[c][k] = v;
        }
    }
    __syncthreads();

    double acc[8][4] = {};
    const float* wcol = W1 + (size_t)k0 * 1024 + tid * 4;
    #pragma unroll 2
    for (int k = 0; k < 1536; k++) {
        float4 w = *(const float4*)(wcol + (size_t)k * 1024);
        double w0 = (double)w.x, w1 = (double)w.y, w2 = (double)w.z, w3 = (double)w.w;
        #pragma unroll
        for (int c = 0; c < 8; c++) {
            double f = (double)sf[c][k];
            acc[c][0] = fma(f, w0, acc[c][0]);
            acc[c][1] = fma(f, w1, acc[c][1]);
            acc[c][2] = fma(f, w2, acc[c][2]);
            acc[c][3] = fma(f, w3, acc[c][3]);
        }
    }
    double* outp = g_hd2[ks];
    #pragma unroll
    for (int c = 0; c < 8; c++) {
        int slot = b*NCAND + g*8 + c;
        double* dst = outp + (size_t)slot*1024 + tid*4;
        dst[0] = acc[c][0]; dst[1] = acc[c][1];
        dst[2] = acc[c][2]; dst[3] = acc[c][3];
    }
}

// =============================================================================
// K6: combine fp64 halves + b1 + lrelu, then logits + softmax + decisions
// =============================================================================
__global__ __launch_bounds__(64) void k6_decide(const float* __restrict__ W2,
                                                const float* __restrict__ b2,
                                                const float* __restrict__ b1,
                                                const float* __restrict__ scores,
                                                const int*   __restrict__ connect)
{
    __shared__ double sh[1024];
    __shared__ double slog[NCLS];
    int slot = blockIdx.x;
    int tid = threadIdx.x;
    const double* h0 = g_hd2[0] + (size_t)slot*1024;
    const double* h1 = g_hd2[1] + (size_t)slot*1024;
    for (int k = tid; k < 1024; k += 64) {
        double v = h0[k] + h1[k] + (double)b1[k];
        v = v > 0.0 ? v : 0.01 * v;
        sh[k] = v;
    }
    __syncthreads();

    if (tid < NCLS) {
        double acc = 0.0;
        #pragma unroll 8
        for (int k = 0; k < 1024; k++)
            acc = fma(sh[k], (double)W2[(size_t)k*NCLS + tid], acc);
        slog[tid] = acc + (double)b2[tid];
    }
    __syncthreads();

    if (tid == 0) {
        double m = slog[0];
        for (int c = 1; c < NCLS; c++) m = slog[c] > m ? slog[c] : m;
        double e[NCLS]; double s = 0.0;
        for (int c = 0; c < NCLS; c++) { e[c] = exp(slog[c] - m); s += e[c]; }
        double best = 0.0; int bl = 0;
        for (int c = 1; c < NCLS; c++) {
            double pr = e[c] / s;
            if (pr > best) { best = pr; bl = c; }
        }
        int b = slot >> 7;
        int p = g_cand_idx[slot];
        int si = connect[(size_t)b*2*NPAIR + p];
        int oi = connect[(size_t)b*2*NPAIR + NPAIR + p];
        double ov = best * (double)scores[b*NINST + si] * (double)scores[b*NINST + oi];
        g_cand_ovr[slot]  = ov;
        g_cand_prob[slot] = best;
        g_cand_lab[slot]  = bl;
    }
}

// =============================================================================
// K7: final top-100 per batch over NCAND fp64 candidates
// =============================================================================
__global__ __launch_bounds__(128) void k7_final(float* __restrict__ outbase)
{
    __shared__ double v[NCAND];
    __shared__ int    pix[NCAND];
    int b = blockIdx.x, tid = threadIdx.x;
    v[tid]   = g_cand_ovr[b*NCAND + tid];
    pix[tid] = g_cand_idx[b*NCAND + tid];
    __syncthreads();

    if (tid == 0) {
        float* out_lab  = outbase;
        float* out_prob = outbase + 800;
        float* out_val  = outbase + 1600;
        float* out_idx  = outbase + 2400;
        for (int t = 0; t < 100; t++) {
            double bv = -1.0; int bj = 0; int bidx = 0x7fffffff;
            for (int j = 0; j < NCAND; j++) {
                double val = v[j]; int ix = pix[j];
                if (val > bv || (val == bv && ix < bidx)) { bv = val; bj = j; bidx = ix; }
            }
            int slot2 = b*NCAND + bj;
            out_val [b*100 + t] = (float)bv;
            out_idx [b*100 + t] = (float)bidx;
            out_lab [b*100 + t] = (float)g_cand_lab[slot2];
            out_prob[b*100 + t] = (float)g_cand_prob[slot2];
            v[bj] = -2.0;
        }
    }
}

// =============================================================================
extern "C" void kernel_launch(void* const* d_in, const int* in_sizes, int n_in,
                              void* d_out, int out_size)
{
    const float* inst    = (const float*)d_in[0];
    const float* phrase  = (const float*)d_in[1];
    const float* scores  = (const float*)d_in[2];
    const float* W1      = (const float*)d_in[3];
    const float* b1      = (const float*)d_in[4];
    const float* W2      = (const float*)d_in[5];
    const float* b2      = (const float*)d_in[6];
    const int*   connect = (const int*)d_in[7];
    const int*   pidx    = (const int*)d_in[8];

    float* out        = (float*)d_out;
    float* out_logits = out;
    float* out_probs  = out + (size_t)BATCH*NPAIR*NCLS;
    float* out_top    = out + (size_t)2*BATCH*NPAIR*NCLS;

    cudaFuncSetAttribute(k2_mma, cudaFuncAttributeMaxDynamicSharedMemorySize, K2_SMEM);

    kprep_w<<<dim3(32, 32), 256>>>(W1);
    kprep_a<<<NROWS, 256>>>(phrase, pidx);
    k1_instproj<<<dim3(32, 13), 256>>>(inst, W1);
    k2_mma<<<dim3(8, 78, BATCH), 256, K2_SMEM>>>(b1, connect);
    k3a_logits<<<619, 256>>>(W2, b2, out_logits);
    k3b_softmax<<<(NROWS + 255) / 256, 256>>>(out_logits, scores, connect, out_probs);
    k4_select<<<BATCH, 1024>>>();
    k5_repair_h<<<dim3(2, 16, BATCH), 256>>>(inst, phrase, W1, connect, pidx);
    k6_decide<<<BATCH*NCAND, 64>>>(W2, b2, b1, scores, connect);
    k7_final<<<BATCH, 128>>>(out_top);
}

// round 6
// speedup vs baseline: 2.8150x; 2.4118x over previous
#include <cuda_runtime.h>
#include <cuda_bf16.h>
#include <math.h>
#include <stdint.h>

#define BATCH 8
#define NINST 100
#define NPAIR 9900
#define NCLS  51
#define NROWS (BATCH*NPAIR)   // 79200
#define NCAND 128
#define KC    64
#define K2_SMEM (128*1024)

// ---------------- scratch (device globals; no allocs allowed) ----------------
__device__ float  g_A12[BATCH*NINST*2048];
__device__ float  g_h[81100800];                // 79200 x 1024 fp32
__device__ float  g_overall[NROWS];
__device__ int    g_cand_idx[BATCH*NCAND];
__device__ int    g_cand_lab[BATCH*NCAND];
__device__ double g_cand_prob[BATCH*NCAND];
__device__ double g_cand_ovr[BATCH*NCAND];
__device__ float  g_hs[2][BATCH*NCAND*1024];   // compensated fp32 partial h (sum)
__device__ float  g_hc[2][BATCH*NCAND*1024];   // compensated fp32 partial h (comp)
__device__ __align__(16) unsigned short g_Ahi[81100800];  // gathered phrase, bf16 hi
__device__ __align__(16) unsigned short g_Alo[81100800];  // bf16 lo
__device__ __align__(16) unsigned short g_Bhi[1024*1024]; // W1c^T [n][k] bf16 hi
__device__ __align__(16) unsigned short g_Blo[1024*1024];

// ---------------- helpers (baseline PTX only) ----------------
__device__ __forceinline__ uint32_t smem_u32(const void* p) {
    uint32_t a;
    asm("{ .reg .u64 t; cvta.to.shared.u64 t, %1; cvt.u32.u64 %0, t; }" : "=r"(a) : "l"(p));
    return a;
}
#define SWZ(x) ((x) ^ (((x) >> 3) & 0x70))
__device__ __forceinline__ void cpasync16(uint32_t dst, const void* src) {
    asm volatile("cp.async.cg.shared.global [%0], [%1], 16;" :: "r"(dst), "l"(src));
}
#define CP_COMMIT() asm volatile("cp.async.commit_group;" ::: "memory")
__device__ __forceinline__ void ldsm4(uint32_t* r, uint32_t addr) {
    asm volatile("ldmatrix.sync.aligned.m8n8.x4.shared.b16 {%0,%1,%2,%3}, [%4];"
        : "=r"(r[0]), "=r"(r[1]), "=r"(r[2]), "=r"(r[3]) : "r"(addr));
}
__device__ __forceinline__ void mma16816(float* c, const uint32_t* a, const uint32_t* b) {
    asm volatile("mma.sync.aligned.m16n8k16.row.col.f32.bf16.bf16.f32 "
        "{%0,%1,%2,%3}, {%4,%5,%6,%7}, {%8,%9}, {%0,%1,%2,%3};"
        : "+f"(c[0]), "+f"(c[1]), "+f"(c[2]), "+f"(c[3])
        : "r"(a[0]), "r"(a[1]), "r"(a[2]), "r"(a[3]), "r"(b[0]), "r"(b[1]));
}

// =============================================================================
// prep_w: W1c (rows 2048..3071 of W1, [k][n]) -> g_Bhi/g_Blo as [n][k] bf16
// =============================================================================
__global__ __launch_bounds__(256) void kprep_w(const float* __restrict__ W1)
{
    __shared__ float t[32][33];
    int kk0 = blockIdx.x * 32, nn0 = blockIdx.y * 32;
    int tx = threadIdx.x & 31, ty = threadIdx.x >> 5;
    #pragma unroll
    for (int i = 0; i < 32; i += 8)
        t[ty + i][tx] = W1[(size_t)(2048 + kk0 + ty + i) * 1024 + nn0 + tx];
    __syncthreads();
    #pragma unroll
    for (int i = 0; i < 32; i += 8) {
        float x = t[tx][ty + i];
        __nv_bfloat16 h = __float2bfloat16(x);
        float lo = x - __bfloat162float(h);
        __nv_bfloat16 l = __float2bfloat16(lo);
        size_t o = (size_t)(nn0 + ty + i) * 1024 + kk0 + tx;
        g_Bhi[o] = __bfloat16_as_ushort(h);
        g_Blo[o] = __bfloat16_as_ushort(l);
    }
}

// =============================================================================
// prep_a: gather phrase rows per pair, split into bf16 hi/lo
// =============================================================================
__global__ __launch_bounds__(256) void kprep_a(const float* __restrict__ phrase,
                                               const int* __restrict__ pidx)
{
    int r = blockIdx.x;
    int b = r / NPAIR;
    int ph = pidx[r];
    const float4* src = (const float4*)(phrase + ((size_t)b * NPAIR + ph) * 1024);
    float4 v = src[threadIdx.x];
    ushort4 hi, lo;
    #define SPL(c, hf, lf) { __nv_bfloat16 _h = __float2bfloat16(v.c); \
        float _l = v.c - __bfloat162float(_h); \
        hf = __bfloat16_as_ushort(_h); lf = __bfloat16_as_ushort(__float2bfloat16(_l)); }
    SPL(x, hi.x, lo.x) SPL(y, hi.y, lo.y) SPL(z, hi.z, lo.z) SPL(w, hi.w, lo.w)
    #undef SPL
    size_t o = (size_t)r * 1024 + threadIdx.x * 4;
    *(ushort4*)(g_Ahi + o) = hi;
    *(ushort4*)(g_Alo + o) = lo;
}

// =============================================================================
// K1: A12[r, j] = inst[r, :] @ W1[half*1024 + :, jc]   (fp32, small)
// =============================================================================
__global__ __launch_bounds__(256) void k1_instproj(const float* __restrict__ inst,
                                                   const float* __restrict__ W1)
{
    __shared__ float As[16][68];
    __shared__ float Bs[16][64];
    int tid = threadIdx.x;
    int n0 = blockIdx.x * 64;
    int m0 = blockIdx.y * 64;
    int half = n0 >> 10;
    int jc0  = n0 & 1023;
    const float* wbase = W1 + (size_t)half * 1024 * 1024 + jc0;

    int arow = tid >> 2;
    int akq  = (tid & 3) * 4;
    int ar   = m0 + arow; if (ar > 799) ar = 799;
    const float* aptr = inst + (size_t)ar * 1024 + akq;
    int brow = tid >> 4;
    int bn   = (tid & 15) * 4;
    int tx = tid & 15, ty = tid >> 4;
    float acc[4][4] = {};

    for (int k0 = 0; k0 < 1024; k0 += 16) {
        float4 av = *(const float4*)(aptr + k0);
        float4 bv = *(const float4*)(wbase + (size_t)(k0 + brow) * 1024 + bn);
        As[akq+0][arow] = av.x; As[akq+1][arow] = av.y;
        As[akq+2][arow] = av.z; As[akq+3][arow] = av.w;
        *(float4*)&Bs[brow][bn] = bv;
        __syncthreads();
        #pragma unroll
        for (int kk = 0; kk < 16; kk++) {
            float af[4], bf[4];
            *(float4*)af = *(const float4*)&As[kk][ty*4];
            *(float4*)bf = *(const float4*)&Bs[kk][tx*4];
            #pragma unroll
            for (int i = 0; i < 4; i++)
                #pragma unroll
                for (int j = 0; j < 4; j++)
                    acc[i][j] += af[i] * bf[j];
        }
        __syncthreads();
    }
    #pragma unroll
    for (int i = 0; i < 4; i++) {
        int r = m0 + ty*4 + i;
        if (r < 800)
            *(float4*)&g_A12[(size_t)r*2048 + n0 + tx*4] =
                make_float4(acc[i][0], acc[i][1], acc[i][2], acc[i][3]);
    }
}

// =============================================================================
// K2 (mma.sync bf16 split): h = lrelu( Aphr @ W1c + A12[sub] + A12[obj] + b1 )
// =============================================================================
__device__ __forceinline__ void k2_load(uint32_t st, int tid, int k0,
                                        size_t rowbase, int p0, int n0)
{
    #pragma unroll 1
    for (int i = tid; i < 4096; i += 256) {
        int q  = i & 7;
        int rr = (i >> 3) & 127;
        uint32_t sw = SWZ(rr * 128 + q * 16);
        const unsigned short* src;
        uint32_t dst;
        if (i < 2048) {
            int p = p0 + rr; if (p > NPAIR - 1) p = NPAIR - 1;
            src = ((i < 1024) ? g_Ahi : g_Alo) + (rowbase + p) * 1024 + k0 + q * 8;
            dst = st + ((i < 1024) ? 0 : 16384) + sw;
        } else {
            src = ((i < 3072) ? g_Bhi : g_Blo) + (size_t)(n0 + rr) * 1024 + k0 + q * 8;
            dst = st + ((i < 3072) ? 32768 : 49152) + sw;
        }
        cpasync16(dst, src);
    }
}

__global__ __launch_bounds__(256, 1) void k2_mma(const float* __restrict__ b1,
                                                 const int* __restrict__ connect)
{
    extern __shared__ __align__(1024) char smem[];
    uint32_t sb = smem_u32(smem);
    int tid = threadIdx.x;
    int lane = tid & 31, wid = tid >> 5;
    int wm = wid & 3, wn = wid >> 2;
    int n0 = blockIdx.x * 128;
    int p0 = blockIdx.y * 128;
    int b  = blockIdx.z;
    size_t rowbase = (size_t)b * NPAIR;

    float acc[2][8][4] = {};

    k2_load(sb,         tid, 0,  rowbase, p0, n0); CP_COMMIT();
    k2_load(sb + 65536, tid, KC, rowbase, p0, n0); CP_COMMIT();

    #pragma unroll 1
    for (int c = 0; c < 16; c++) {
        if (c < 15) asm volatile("cp.async.wait_group 1;" ::: "memory");
        else        asm volatile("cp.async.wait_group 0;" ::: "memory");
        __syncthreads();

        uint32_t st  = sb + (c & 1) * 65536;
        uint32_t sAh = st, sAl = st + 16384, sBh = st + 32768, sBl = st + 49152;

        #pragma unroll
        for (int ks = 0; ks < 4; ks++) {
            int kb = ks * 32;
            uint32_t ah[2][4], al[2][4], bh[4][4], bl[4][4];
            #pragma unroll
            for (int mt = 0; mt < 2; mt++) {
                uint32_t off = SWZ((wm*32 + mt*16 + (lane & 15)) * 128 + kb + (lane >> 4) * 16);
                ldsm4(ah[mt], sAh + off);
                ldsm4(al[mt], sAl + off);
            }
            int nrow  = (lane & 7) + ((lane >> 4) & 1) * 8;
            int khalf = ((lane >> 3) & 1) * 16;
            #pragma unroll
            for (int ntq = 0; ntq < 4; ntq++) {
                uint32_t off = SWZ((wn*64 + ntq*16 + nrow) * 128 + kb + khalf);
                ldsm4(bh[ntq], sBh + off);
                ldsm4(bl[ntq], sBl + off);
            }
            #pragma unroll
            for (int mt = 0; mt < 2; mt++)
                #pragma unroll
                for (int nt = 0; nt < 8; nt++) {
                    const uint32_t* bhp = &bh[nt >> 1][(nt & 1) * 2];
                    const uint32_t* blp = &bl[nt >> 1][(nt & 1) * 2];
                    mma16816(acc[mt][nt], ah[mt], bhp);
                    mma16816(acc[mt][nt], al[mt], bhp);
                    mma16816(acc[mt][nt], ah[mt], blp);
                }
        }
        __syncthreads();
        if (c + 2 < 16) {
            k2_load(sb + (c & 1) * 65536, tid, (c + 2) * KC, rowbase, p0, n0);
            CP_COMMIT();
        }
    }

    int gp = lane >> 2, tq = lane & 3;
    int n0w = n0 + wn * 64;
    size_t bb2 = (size_t)b * 2 * NPAIR;
    const float* a12b = g_A12 + (size_t)b * NINST * 2048;
    #pragma unroll
    for (int mt = 0; mt < 2; mt++) {
        #pragma unroll
        for (int half = 0; half < 2; half++) {
            int p = p0 + wm*32 + mt*16 + gp + half*8;
            if (p >= NPAIR) continue;
            int sub = connect[bb2 + p];
            int obj = connect[bb2 + NPAIR + p];
            const float* r1 = a12b + (size_t)sub * 2048 + n0w;
            const float* r2 = a12b + (size_t)obj * 2048 + 1024 + n0w;
            float* ho = g_h + ((size_t)b * NPAIR + p) * 1024 + n0w;
            #pragma unroll
            for (int nt = 0; nt < 8; nt++) {
                int cc = nt*8 + tq*2;
                float2 v1 = *(const float2*)(r1 + cc);
                float2 v2 = *(const float2*)(r2 + cc);
                float2 vb = *(const float2*)(b1 + n0w + cc);
                float x = acc[mt][nt][half*2+0] + v1.x + v2.x + vb.x;
                float y = acc[mt][nt][half*2+1] + v1.y + v2.y + vb.y;
                x = x > 0.f ? x : 0.01f * x;
                y = y > 0.f ? y : 0.01f * y;
                *(float2*)(ho + cc) = make_float2(x, y);
            }
        }
    }
}

// =============================================================================
// K3a: logits = h @ W2 + b2    (fp32)
// =============================================================================
__global__ __launch_bounds__(256) void k3a_logits(const float* __restrict__ W2,
                                                  const float* __restrict__ b2,
                                                  float* __restrict__ out_logits)
{
    __shared__ float hsm[32][132];
    __shared__ float w2s[32][64];
    int tid = threadIdx.x;
    size_t row0 = (size_t)blockIdx.x * 128;
    int lr = tid >> 1;
    int lk = (tid & 1) * 16;
    size_t grow = row0 + lr; if (grow > (size_t)NROWS - 1) grow = NROWS - 1;
    const float* hptr = g_h + grow * 1024 + lk;
    int tx = tid & 15, ty = tid >> 4;
    float acc[8][4] = {};

    for (int k0 = 0; k0 < 1024; k0 += 32) {
        #pragma unroll
        for (int q = 0; q < 4; q++) {
            float4 v = *(const float4*)(hptr + k0 + q*4);
            hsm[lk + q*4 + 0][lr] = v.x;
            hsm[lk + q*4 + 1][lr] = v.y;
            hsm[lk + q*4 + 2][lr] = v.z;
            hsm[lk + q*4 + 3][lr] = v.w;
        }
        for (int idx = tid; idx < 32*64; idx += 256) {
            int kk = idx >> 6, c = idx & 63;
            w2s[kk][c] = (c < NCLS) ? W2[(size_t)(k0 + kk)*NCLS + c] : 0.f;
        }
        __syncthreads();
        #pragma unroll
        for (int kk = 0; kk < 32; kk++) {
            float af[8], bf[4];
            *(float4*)&af[0] = *(const float4*)&hsm[kk][ty*8];
            *(float4*)&af[4] = *(const float4*)&hsm[kk][ty*8+4];
            *(float4*)bf = *(const float4*)&w2s[kk][tx*4];
            #pragma unroll
            for (int i = 0; i < 8; i++)
                #pragma unroll
                for (int j = 0; j < 4; j++)
                    acc[i][j] += af[i]*bf[j];
        }
        __syncthreads();
    }
    #pragma unroll
    for (int j = 0; j < 4; j++) {
        int c = tx*4 + j;
        if (c >= NCLS) continue;
        float bb = b2[c];
        #pragma unroll
        for (int i = 0; i < 8; i++) {
            size_t r = row0 + (size_t)ty*8 + i;
            if (r < NROWS) out_logits[r*NCLS + c] = acc[i][j] + bb;
        }
    }
}

// =============================================================================
// K3b: softmax -> probs output; fp32 overall (ranking key)
// =============================================================================
__global__ void k3b_softmax(const float* __restrict__ out_logits,
                            const float* __restrict__ scores,
                            const int*   __restrict__ connect,
                            float* __restrict__ out_probs)
{
    int row = blockIdx.x * blockDim.x + threadIdx.x;
    if (row >= NROWS) return;
    const float* lp = out_logits + (size_t)row * NCLS;
    float l[NCLS];
    float m = -1e30f;
    #pragma unroll
    for (int c = 0; c < NCLS; c++) { l[c] = lp[c]; m = fmaxf(m, l[c]); }
    float s = 0.f;
    #pragma unroll
    for (int c = 0; c < NCLS; c++) { l[c] = expf(l[c] - m); s += l[c]; }
    float inv = 1.0f / s;
    float* pp = out_probs + (size_t)row * NCLS;
    float best = 0.f;
    #pragma unroll
    for (int c = 0; c < NCLS; c++) {
        float pr = l[c] * inv;
        pp[c] = pr;
        if (c >= 1 && pr > best) best = pr;
    }
    int b = row / NPAIR, p = row % NPAIR;
    int si = connect[(size_t)b*2*NPAIR + p];
    int oi = connect[(size_t)b*2*NPAIR + NPAIR + p];
    g_overall[row] = best * scores[b*NINST + si] * scores[b*NINST + oi];
}

// =============================================================================
// K4: warp-tournament top-NCAND selection
// =============================================================================
__global__ __launch_bounds__(1024) void k4_select()
{
    __shared__ float vals[NPAIR];
    __shared__ float wmax[32];
    __shared__ int   warg[32];
    __shared__ int   s_win;
    int b = blockIdx.x, tid = threadIdx.x, w = tid >> 5, lane = tid & 31;
    for (int i = tid; i < NPAIR; i += 1024) vals[i] = g_overall[b*NPAIR + i];
    __syncthreads();

    int lo = w * 310;
    int hiv = lo + 310; if (hiv > NPAIR) hiv = NPAIR;
    float bv = -1.f; int bi = 0x7fffffff;
    for (int i = lo + lane; i < hiv; i += 32) {
        float v = vals[i];
        if (v > bv || (v == bv && i < bi)) { bv = v; bi = i; }
    }
    #pragma unroll
    for (int o = 16; o; o >>= 1) {
        float ov = __shfl_down_sync(0xffffffffu, bv, o);
        int   oi = __shfl_down_sync(0xffffffffu, bi, o);
        if (ov > bv || (ov == bv && oi < bi)) { bv = ov; bi = oi; }
    }
    if (lane == 0) { wmax[w] = bv; warg[w] = bi; }
    __syncthreads();

    for (int t = 0; t < NCAND; t++) {
        if (tid < 32) {
            float v = wmax[lane]; int i2 = warg[lane];
            #pragma unroll
            for (int o = 16; o; o >>= 1) {
                float ov = __shfl_down_sync(0xffffffffu, v, o);
                int   oi = __shfl_down_sync(0xffffffffu, i2, o);
                if (ov > v || (ov == v && oi < i2)) { v = ov; i2 = oi; }
            }
            if (lane == 0) {
                g_cand_idx[b*NCAND + t] = i2;
                vals[i2] = -2.f;
                s_win = i2 / 310;
            }
        }
        __syncthreads();
        if (w == s_win) {
            float nv = -1.f; int ni = 0x7fffffff;
            for (int i = lo + lane; i < hiv; i += 32) {
                float v = vals[i];
                if (v > nv || (v == nv && i < ni)) { nv = v; ni = i; }
            }
            #pragma unroll
            for (int o = 16; o; o >>= 1) {
                float ov = __shfl_down_sync(0xffffffffu, nv, o);
                int   oi = __shfl_down_sync(0xffffffffu, ni, o);
                if (ov > nv || (ov == nv && oi < ni)) { nv = ov; ni = oi; }
            }
            if (lane == 0) { wmax[w] = nv; warg[w] = ni; }
        }
        __syncthreads();
    }
}

// =============================================================================
// K5 v3: compensated-fp32 exact partial h for candidates.
// grid (ksplit=2, 32 groups, 8 batch); 4 cand/block; TwoSum + FMA error capture
// via __f*_rn intrinsics (immune to fast-math / contraction).
// Each thread owns output cols tid*4..tid*4+3 for K-half [ks*1536, +1536).
// =============================================================================
#define CPB 4
__global__ __launch_bounds__(256) void k5_repair_h(const float* __restrict__ inst,
                                                   const float* __restrict__ phrase,
                                                   const float* __restrict__ W1,
                                                   const int*   __restrict__ connect,
                                                   const int*   __restrict__ pidx)
{
    __shared__ float sf[CPB][1536];   // 24 KB
    int ks = blockIdx.x;              // 0..1 K half
    int g  = blockIdx.y;              // 0..31 candidate group
    int b  = blockIdx.z;              // batch
    int tid = threadIdx.x;
    int k0 = ks * 1536;

    #pragma unroll 1
    for (int c = 0; c < CPB; c++) {
        int slot = b*NCAND + g*CPB + c;
        int p  = g_cand_idx[slot];
        int si = connect[(size_t)b*2*NPAIR + p];
        int oi = connect[(size_t)b*2*NPAIR + NPAIR + p];
        int ph = pidx[b*NPAIR + p];
        const float* s0 = inst   + ((size_t)b*NINST + si)*1024;
        const float* s1 = inst   + ((size_t)b*NINST + oi)*1024;
        const float* s2 = phrase + ((size_t)b*NPAIR + ph)*1024;
        for (int k = tid; k < 1536; k += 256) {
            int f = k0 + k;
            float v;
            if (f < 1024)       v = s0[f];
            else if (f < 2048)  v = s1[f - 1024];
            else                v = s2[f - 2048];
            sf[c][k] = v;
        }
    }
    __syncthreads();

    float s[CPB][4] = {};
    float comp[CPB][4] = {};
    const float* wcol = W1 + (size_t)k0 * 1024 + tid * 4;
    #pragma unroll 2
    for (int k = 0; k < 1536; k++) {
        float4 w = *(const float4*)(wcol + (size_t)k * 1024);
        float wv[4] = {w.x, w.y, w.z, w.w};
        #pragma unroll
        for (int c = 0; c < CPB; c++) {
            float f = sf[c][k];
            #pragma unroll
            for (int j = 0; j < 4; j++) {
                float p  = __fmul_rn(f, wv[j]);
                float e  = __fmaf_rn(f, wv[j], -p);         // exact product error
                float t  = __fadd_rn(s[c][j], p);           // Knuth TwoSum
                float z  = __fsub_rn(t, s[c][j]);
                float e2 = __fadd_rn(__fsub_rn(s[c][j], __fsub_rn(t, z)),
                                     __fsub_rn(p, z));
                comp[c][j] = __fadd_rn(comp[c][j], __fadd_rn(e2, e));
                s[c][j] = t;
            }
        }
    }
    float* outs = g_hs[ks];
    float* outc = g_hc[ks];
    #pragma unroll
    for (int c = 0; c < CPB; c++) {
        int slot = b*NCAND + g*CPB + c;
        *(float4*)(outs + (size_t)slot*1024 + tid*4) =
            make_float4(s[c][0], s[c][1], s[c][2], s[c][3]);
        *(float4*)(outc + (size_t)slot*1024 + tid*4) =
            make_float4(comp[c][0], comp[c][1], comp[c][2], comp[c][3]);
    }
}

// =============================================================================
// K6: combine compensated halves + b1 + lrelu (fp64), then logits + softmax +
//     decisions per candidate
// =============================================================================
__global__ __launch_bounds__(64) void k6_decide(const float* __restrict__ W2,
                                                const float* __restrict__ b2,
                                                const float* __restrict__ b1,
                                                const float* __restrict__ scores,
                                                const int*   __restrict__ connect)
{
    __shared__ double sh[1024];
    __shared__ double slog[NCLS];
    int slot = blockIdx.x;
    int tid = threadIdx.x;
    size_t base = (size_t)slot * 1024;
    for (int k = tid; k < 1024; k += 64) {
        double v = ((double)g_hs[0][base + k] + (double)g_hc[0][base + k])
                 + ((double)g_hs[1][base + k] + (double)g_hc[1][base + k])
                 + (double)b1[k];
        v = v > 0.0 ? v : 0.01 * v;
        sh[k] = v;
    }
    __syncthreads();

    if (tid < NCLS) {
        double acc = 0.0;
        #pragma unroll 8
        for (int k = 0; k < 1024; k++)
            acc = fma(sh[k], (double)W2[(size_t)k*NCLS + tid], acc);
        slog[tid] = acc + (double)b2[tid];
    }
    __syncthreads();

    if (tid == 0) {
        double m = slog[0];
        for (int c = 1; c < NCLS; c++) m = slog[c] > m ? slog[c] : m;
        double e[NCLS]; double ssum = 0.0;
        for (int c = 0; c < NCLS; c++) { e[c] = exp(slog[c] - m); ssum += e[c]; }
        double best = 0.0; int bl = 0;
        for (int c = 1; c < NCLS; c++) {
            double pr = e[c] / ssum;
            if (pr > best) { best = pr; bl = c; }
        }
        int b = slot >> 7;
        int p = g_cand_idx[slot];
        int si = connect[(size_t)b*2*NPAIR + p];
        int oi = connect[(size_t)b*2*NPAIR + NPAIR + p];
        double ov = best * (double)scores[b*NINST + si] * (double)scores[b*NINST + oi];
        g_cand_ovr[slot]  = ov;
        g_cand_prob[slot] = best;
        g_cand_lab[slot]  = bl;
    }
}

// =============================================================================
// K7: final top-100 per batch over NCAND candidates
// =============================================================================
__global__ __launch_bounds__(128) void k7_final(float* __restrict__ outbase)
{
    __shared__ double v[NCAND];
    __shared__ int    pix[NCAND];
    int b = blockIdx.x, tid = threadIdx.x;
    v[tid]   = g_cand_ovr[b*NCAND + tid];
    pix[tid] = g_cand_idx[b*NCAND + tid];
    __syncthreads();

    if (tid == 0) {
        float* out_lab  = outbase;
        float* out_prob = outbase + 800;
        float* out_val  = outbase + 1600;
        float* out_idx  = outbase + 2400;
        for (int t = 0; t < 100; t++) {
            double bv = -1.0; int bj = 0; int bidx = 0x7fffffff;
            for (int j = 0; j < NCAND; j++) {
                double val = v[j]; int ix = pix[j];
                if (val > bv || (val == bv && ix < bidx)) { bv = val; bj = j; bidx = ix; }
            }
            int slot2 = b*NCAND + bj;
            out_val [b*100 + t] = (float)bv;
            out_idx [b*100 + t] = (float)bidx;
            out_lab [b*100 + t] = (float)g_cand_lab[slot2];
            out_prob[b*100 + t] = (float)g_cand_prob[slot2];
            v[bj] = -2.0;
        }
    }
}

// =============================================================================
extern "C" void kernel_launch(void* const* d_in, const int* in_sizes, int n_in,
                              void* d_out, int out_size)
{
    const float* inst    = (const float*)d_in[0];
    const float* phrase  = (const float*)d_in[1];
    const float* scores  = (const float*)d_in[2];
    const float* W1      = (const float*)d_in[3];
    const float* b1      = (const float*)d_in[4];
    const float* W2      = (const float*)d_in[5];
    const float* b2      = (const float*)d_in[6];
    const int*   connect = (const int*)d_in[7];
    const int*   pidx    = (const int*)d_in[8];

    float* out        = (float*)d_out;
    float* out_logits = out;
    float* out_probs  = out + (size_t)BATCH*NPAIR*NCLS;
    float* out_top    = out + (size_t)2*BATCH*NPAIR*NCLS;

    cudaFuncSetAttribute(k2_mma, cudaFuncAttributeMaxDynamicSharedMemorySize, K2_SMEM);

    kprep_w<<<dim3(32, 32), 256>>>(W1);
    kprep_a<<<NROWS, 256>>>(phrase, pidx);
    k1_instproj<<<dim3(32, 13), 256>>>(inst, W1);
    k2_mma<<<dim3(8, 78, BATCH), 256, K2_SMEM>>>(b1, connect);
    k3a_logits<<<619, 256>>>(W2, b2, out_logits);
    k3b_softmax<<<(NROWS + 255) / 256, 256>>>(out_logits, scores, connect, out_probs);
    k4_select<<<BATCH, 1024>>>();
    k5_repair_h<<<dim3(2, 32, BATCH), 256>>>(inst, phrase, W1, connect, pidx);
    k6_decide<<<BATCH*NCAND, 64>>>(W2, b2, b1, scores, connect);
    k7_final<<<BATCH, 128>>>(out_top);
}

// round 7
// speedup vs baseline: 3.0999x; 1.1012x over previous
#include <cuda_runtime.h>
#include <cuda_bf16.h>
#include <math.h>
#include <stdint.h>

#define BATCH 8
#define NINST 100
#define NPAIR 9900
#define NCLS  51
#define NROWS (BATCH*NPAIR)   // 79200
#define NCAND 128
#define KC    64
// k2/k3a stage: Ahi 16K | Alo 16K | Bhi 8K | Blo 8K = 48KB
#define SA_LO 16384
#define SB_HI 32768
#define SB_LO 40960
#define STAGE 49152
#define MM_SMEM (2*STAGE)

// ---------------- scratch (device globals; no allocs allowed) ----------------
__device__ float  g_A12[BATCH*NINST*2048];
__device__ float  g_overall[NROWS];
__device__ int    g_cand_idx[BATCH*NCAND];
__device__ int    g_cand_lab[BATCH*NCAND];
__device__ double g_cand_prob[BATCH*NCAND];
__device__ double g_cand_ovr[BATCH*NCAND];
__device__ float  g_hs[2][BATCH*NCAND*1024];   // compensated fp32 partial h (sum)
__device__ float  g_hc[2][BATCH*NCAND*1024];   // compensated fp32 partial h (comp)
__device__ __align__(16) unsigned short g_Ahi[81100800];  // gathered phrase bf16 hi
__device__ __align__(16) unsigned short g_Alo[81100800];  // bf16 lo
__device__ __align__(16) unsigned short g_Bhi[1024*1024]; // W1c^T [n][k] bf16 hi
__device__ __align__(16) unsigned short g_Blo[1024*1024];
__device__ __align__(16) unsigned short g_Hhi[81100800];  // hidden h bf16 hi
__device__ __align__(16) unsigned short g_Hlo[81100800];  // hidden h bf16 lo
__device__ __align__(16) unsigned short g_W2hi[64*1024];  // W2^T padded [64][1024]
__device__ __align__(16) unsigned short g_W2lo[64*1024];

// ---------------- helpers (baseline PTX only) ----------------
__device__ __forceinline__ uint32_t smem_u32(const void* p) {
    uint32_t a;
    asm("{ .reg .u64 t; cvta.to.shared.u64 t, %1; cvt.u32.u64 %0, t; }" : "=r"(a) : "l"(p));
    return a;
}
#define SWZ(x) ((x) ^ (((x) >> 3) & 0x70))
__device__ __forceinline__ void cpasync16(uint32_t dst, const void* src) {
    asm volatile("cp.async.cg.shared.global [%0], [%1], 16;" :: "r"(dst), "l"(src));
}
#define CP_COMMIT() asm volatile("cp.async.commit_group;" ::: "memory")
__device__ __forceinline__ void ldsm4(uint32_t* r, uint32_t addr) {
    asm volatile("ldmatrix.sync.aligned.m8n8.x4.shared.b16 {%0,%1,%2,%3}, [%4];"
        : "=r"(r[0]), "=r"(r[1]), "=r"(r[2]), "=r"(r[3]) : "r"(addr));
}
__device__ __forceinline__ void mma16816(float* c, const uint32_t* a, const uint32_t* b) {
    asm volatile("mma.sync.aligned.m16n8k16.row.col.f32.bf16.bf16.f32 "
        "{%0,%1,%2,%3}, {%4,%5,%6,%7}, {%8,%9}, {%0,%1,%2,%3};"
        : "+f"(c[0]), "+f"(c[1]), "+f"(c[2]), "+f"(c[3])
        : "r"(a[0]), "r"(a[1]), "r"(a[2]), "r"(a[3]), "r"(b[0]), "r"(b[1]));
}

// =============================================================================
// prep_w: W1c (rows 2048..3071 of W1, [k][n]) -> g_Bhi/g_Blo as [n][k] bf16
// =============================================================================
__global__ __launch_bounds__(256) void kprep_w(const float* __restrict__ W1)
{
    __shared__ float t[32][33];
    int kk0 = blockIdx.x * 32, nn0 = blockIdx.y * 32;
    int tx = threadIdx.x & 31, ty = threadIdx.x >> 5;
    #pragma unroll
    for (int i = 0; i < 32; i += 8)
        t[ty + i][tx] = W1[(size_t)(2048 + kk0 + ty + i) * 1024 + nn0 + tx];
    __syncthreads();
    #pragma unroll
    for (int i = 0; i < 32; i += 8) {
        float x = t[tx][ty + i];
        __nv_bfloat16 h = __float2bfloat16(x);
        float lo = x - __bfloat162float(h);
        __nv_bfloat16 l = __float2bfloat16(lo);
        size_t o = (size_t)(nn0 + ty + i) * 1024 + kk0 + tx;
        g_Bhi[o] = __bfloat16_as_ushort(h);
        g_Blo[o] = __bfloat16_as_ushort(l);
    }
}

// =============================================================================
// prep_w2: W2 [k][51] -> g_W2hi/lo [n=64 pad][k] bf16
// =============================================================================
__global__ __launch_bounds__(256) void kprep_w2(const float* __restrict__ W2)
{
    int n = blockIdx.x;            // 0..63
    for (int k = threadIdx.x; k < 1024; k += 256) {
        float x = (n < NCLS) ? W2[(size_t)k * NCLS + n] : 0.f;
        __nv_bfloat16 h = __float2bfloat16(x);
        float lo = x - __bfloat162float(h);
        g_W2hi[n * 1024 + k] = __bfloat16_as_ushort(h);
        g_W2lo[n * 1024 + k] = __bfloat16_as_ushort(__float2bfloat16(lo));
    }
}

// =============================================================================
// prep_a: gather phrase rows per pair, split into bf16 hi/lo
// =============================================================================
__global__ __launch_bounds__(256) void kprep_a(const float* __restrict__ phrase,
                                               const int* __restrict__ pidx)
{
    int r = blockIdx.x;
    int b = r / NPAIR;
    int ph = pidx[r];
    const float4* src = (const float4*)(phrase + ((size_t)b * NPAIR + ph) * 1024);
    float4 v = src[threadIdx.x];
    ushort4 hi, lo;
    #define SPL(c, hf, lf) { __nv_bfloat16 _h = __float2bfloat16(v.c); \
        float _l = v.c - __bfloat162float(_h); \
        hf = __bfloat16_as_ushort(_h); lf = __bfloat16_as_ushort(__float2bfloat16(_l)); }
    SPL(x, hi.x, lo.x) SPL(y, hi.y, lo.y) SPL(z, hi.z, lo.z) SPL(w, hi.w, lo.w)
    #undef SPL
    size_t o = (size_t)r * 1024 + threadIdx.x * 4;
    *(ushort4*)(g_Ahi + o) = hi;
    *(ushort4*)(g_Alo + o) = lo;
}

// =============================================================================
// K1: A12[r, j] = inst[r, :] @ W1[half*1024 + :, jc]   (fp32, small)
// =============================================================================
__global__ __launch_bounds__(256) void k1_instproj(const float* __restrict__ inst,
                                                   const float* __restrict__ W1)
{
    __shared__ float As[16][68];
    __shared__ float Bs[16][64];
    int tid = threadIdx.x;
    int n0 = blockIdx.x * 64;
    int m0 = blockIdx.y * 64;
    int half = n0 >> 10;
    int jc0  = n0 & 1023;
    const float* wbase = W1 + (size_t)half * 1024 * 1024 + jc0;

    int arow = tid >> 2;
    int akq  = (tid & 3) * 4;
    int ar   = m0 + arow; if (ar > 799) ar = 799;
    const float* aptr = inst + (size_t)ar * 1024 + akq;
    int brow = tid >> 4;
    int bn   = (tid & 15) * 4;
    int tx = tid & 15, ty = tid >> 4;
    float acc[4][4] = {};

    for (int k0 = 0; k0 < 1024; k0 += 16) {
        float4 av = *(const float4*)(aptr + k0);
        float4 bv = *(const float4*)(wbase + (size_t)(k0 + brow) * 1024 + bn);
        As[akq+0][arow] = av.x; As[akq+1][arow] = av.y;
        As[akq+2][arow] = av.z; As[akq+3][arow] = av.w;
        *(float4*)&Bs[brow][bn] = bv;
        __syncthreads();
        #pragma unroll
        for (int kk = 0; kk < 16; kk++) {
            float af[4], bf[4];
            *(float4*)af = *(const float4*)&As[kk][ty*4];
            *(float4*)bf = *(const float4*)&Bs[kk][tx*4];
            #pragma unroll
            for (int i = 0; i < 4; i++)
                #pragma unroll
                for (int j = 0; j < 4; j++)
                    acc[i][j] += af[i] * bf[j];
        }
        __syncthreads();
    }
    #pragma unroll
    for (int i = 0; i < 4; i++) {
        int r = m0 + ty*4 + i;
        if (r < 800)
            *(float4*)&g_A12[(size_t)r*2048 + n0 + tx*4] =
                make_float4(acc[i][0], acc[i][1], acc[i][2], acc[i][3]);
    }
}

// =============================================================================
// K2 (mma.sync bf16 split, 2 CTA/SM): h = lrelu(Aphr@W1c + A12[sub]+A12[obj]+b1)
// CTA 128 rows x 64 cols; 8 warps = 4M x 2N, warp tile 32x32; KC=64, 2 stages.
// Epilogue writes h as bf16 hi/lo for tensor k3a.
// =============================================================================
__device__ __forceinline__ void k2_load(uint32_t st, int tid, int k0,
                                        size_t rowbase, int p0, int n0)
{
    #pragma unroll 1
    for (int i = tid; i < 3072; i += 256) {
        int q = i & 7;
        const unsigned short* src;
        uint32_t dst;
        if (i < 2048) {
            int t = i >> 10;
            int r = (i >> 3) & 127;
            int p = p0 + r; if (p > NPAIR - 1) p = NPAIR - 1;
            src = (t ? g_Alo : g_Ahi) + (rowbase + p) * 1024 + k0 + q * 8;
            dst = st + t * SA_LO + SWZ(r * 128 + q * 16);
        } else {
            int j = i - 2048;
            int t = j >> 9;
            int n = (j >> 3) & 63;
            src = (t ? g_Blo : g_Bhi) + (size_t)(n0 + n) * 1024 + k0 + q * 8;
            dst = st + SB_HI + t * 8192 + SWZ(n * 128 + q * 16);
        }
        cpasync16(dst, src);
    }
}

__global__ void __launch_bounds__(256, 2) k2_mma(const float* __restrict__ b1,
                                                 const int* __restrict__ connect)
{
    extern __shared__ __align__(1024) char smem[];
    uint32_t sb = smem_u32(smem);
    int tid = threadIdx.x;
    int lane = tid & 31, wid = tid >> 5;
    int wm = wid & 3, wn = wid >> 2;       // 4 M-warps x 2 N-warps
    int n0 = blockIdx.x * 64;
    int p0 = blockIdx.y * 128;
    int b  = blockIdx.z;
    size_t rowbase = (size_t)b * NPAIR;

    float acc[2][4][4] = {};

    k2_load(sb,         tid, 0,  rowbase, p0, n0); CP_COMMIT();
    k2_load(sb + STAGE, tid, KC, rowbase, p0, n0); CP_COMMIT();

    #pragma unroll 1
    for (int c = 0; c < 16; c++) {
        if (c < 15) asm volatile("cp.async.wait_group 1;" ::: "memory");
        else        asm volatile("cp.async.wait_group 0;" ::: "memory");
        __syncthreads();

        uint32_t st  = sb + (c & 1) * STAGE;
        uint32_t sAh = st, sAl = st + SA_LO, sBh = st + SB_HI, sBl = st + SB_LO;

        #pragma unroll
        for (int ks = 0; ks < 4; ks++) {
            int kb = ks * 32;
            uint32_t ah[2][4], al[2][4], bh[2][4], bl[2][4];
            #pragma unroll
            for (int mt = 0; mt < 2; mt++) {
                uint32_t off = SWZ((wm*32 + mt*16 + (lane & 15)) * 128 + kb + (lane >> 4) * 16);
                ldsm4(ah[mt], sAh + off);
                ldsm4(al[mt], sAl + off);
            }
            int nrow  = (lane & 7) + ((lane >> 4) & 1) * 8;
            int khalf = ((lane >> 3) & 1) * 16;
            #pragma unroll
            for (int ntq = 0; ntq < 2; ntq++) {
                uint32_t off = SWZ((wn*32 + ntq*16 + nrow) * 128 + kb + khalf);
                ldsm4(bh[ntq], sBh + off);
                ldsm4(bl[ntq], sBl + off);
            }
            #pragma unroll
            for (int mt = 0; mt < 2; mt++)
                #pragma unroll
                for (int nt = 0; nt < 4; nt++) {
                    const uint32_t* bhp = &bh[nt >> 1][(nt & 1) * 2];
                    const uint32_t* blp = &bl[nt >> 1][(nt & 1) * 2];
                    mma16816(acc[mt][nt], ah[mt], bhp);
                    mma16816(acc[mt][nt], al[mt], bhp);
                    mma16816(acc[mt][nt], ah[mt], blp);
                }
        }
        __syncthreads();
        if (c + 2 < 16) {
            k2_load(sb + (c & 1) * STAGE, tid, (c + 2) * KC, rowbase, p0, n0);
            CP_COMMIT();
        }
    }

    // epilogue: + A12[sub] + A12[obj] + b1, lrelu, split to bf16 hi/lo
    int gp = lane >> 2, tq = lane & 3;
    int n0w = n0 + wn * 32;
    size_t bb2 = (size_t)b * 2 * NPAIR;
    const float* a12b = g_A12 + (size_t)b * NINST * 2048;
    #pragma unroll
    for (int mt = 0; mt < 2; mt++) {
        #pragma unroll
        for (int half = 0; half < 2; half++) {
            int p = p0 + wm*32 + mt*16 + gp + half*8;
            if (p >= NPAIR) continue;
            int sub = connect[bb2 + p];
            int obj = connect[bb2 + NPAIR + p];
            const float* r1 = a12b + (size_t)sub * 2048 + n0w;
            const float* r2 = a12b + (size_t)obj * 2048 + 1024 + n0w;
            size_t hoff = ((size_t)b * NPAIR + p) * 1024 + n0w;
            #pragma unroll
            for (int nt = 0; nt < 4; nt++) {
                int cc = nt*8 + tq*2;
                float2 v1 = *(const float2*)(r1 + cc);
                float2 v2 = *(const float2*)(r2 + cc);
                float2 vb = *(const float2*)(b1 + n0w + cc);
                float x = acc[mt][nt][half*2+0] + v1.x + v2.x + vb.x;
                float y = acc[mt][nt][half*2+1] + v1.y + v2.y + vb.y;
                x = x > 0.f ? x : 0.01f * x;
                y = y > 0.f ? y : 0.01f * y;
                __nv_bfloat16 xh = __float2bfloat16(x);
                __nv_bfloat16 yh = __float2bfloat16(y);
                ushort2 hi2, lo2;
                hi2.x = __bfloat16_as_ushort(xh);
                hi2.y = __bfloat16_as_ushort(yh);
                lo2.x = __bfloat16_as_ushort(__float2bfloat16(x - __bfloat162float(xh)));
                lo2.y = __bfloat16_as_ushort(__float2bfloat16(y - __bfloat162float(yh)));
                *(ushort2*)(g_Hhi + hoff + cc) = hi2;
                *(ushort2*)(g_Hlo + hoff + cc) = lo2;
            }
        }
    }
}

// =============================================================================
// K3a (tensor): logits = h @ W2 + b2. CTA 128 rows x 64 cols (51 used),
// same structure as k2; A = g_Hhi/lo, B = g_W2hi/lo.
// =============================================================================
__device__ __forceinline__ void k3a_load(uint32_t st, int tid, int k0, int row0)
{
    #pragma unroll 1
    for (int i = tid; i < 3072; i += 256) {
        int q = i & 7;
        const unsigned short* src;
        uint32_t dst;
        if (i < 2048) {
            int t = i >> 10;
            int r = (i >> 3) & 127;
            int p = row0 + r; if (p > NROWS - 1) p = NROWS - 1;
            src = (t ? g_Hlo : g_Hhi) + (size_t)p * 1024 + k0 + q * 8;
            dst = st + t * SA_LO + SWZ(r * 128 + q * 16);
        } else {
            int j = i - 2048;
            int t = j >> 9;
            int n = (j >> 3) & 63;
            src = (t ? g_W2lo : g_W2hi) + (size_t)n * 1024 + k0 + q * 8;
            dst = st + SB_HI + t * 8192 + SWZ(n * 128 + q * 16);
        }
        cpasync16(dst, src);
    }
}

__global__ void __launch_bounds__(256, 2) k3a_logits(const float* __restrict__ b2,
                                                     float* __restrict__ out_logits)
{
    extern __shared__ __align__(1024) char smem[];
    uint32_t sb = smem_u32(smem);
    int tid = threadIdx.x;
    int lane = tid & 31, wid = tid >> 5;
    int wm = wid & 3, wn = wid >> 2;
    int row0 = blockIdx.x * 128;

    float acc[2][4][4] = {};

    k3a_load(sb,         tid, 0,  row0); CP_COMMIT();
    k3a_load(sb + STAGE, tid, KC, row0); CP_COMMIT();

    #pragma unroll 1
    for (int c = 0; c < 16; c++) {
        if (c < 15) asm volatile("cp.async.wait_group 1;" ::: "memory");
        else        asm volatile("cp.async.wait_group 0;" ::: "memory");
        __syncthreads();

        uint32_t st  = sb + (c & 1) * STAGE;
        uint32_t sAh = st, sAl = st + SA_LO, sBh = st + SB_HI, sBl = st + SB_LO;

        #pragma unroll
        for (int ks = 0; ks < 4; ks++) {
            int kb = ks * 32;
            uint32_t ah[2][4], al[2][4], bh[2][4], bl[2][4];
            #pragma unroll
            for (int mt = 0; mt < 2; mt++) {
                uint32_t off = SWZ((wm*32 + mt*16 + (lane & 15)) * 128 + kb + (lane >> 4) * 16);
                ldsm4(ah[mt], sAh + off);
                ldsm4(al[mt], sAl + off);
            }
            int nrow  = (lane & 7) + ((lane >> 4) & 1) * 8;
            int khalf = ((lane >> 3) & 1) * 16;
            #pragma unroll
            for (int ntq = 0; ntq < 2; ntq++) {
                uint32_t off = SWZ((wn*32 + ntq*16 + nrow) * 128 + kb + khalf);
                ldsm4(bh[ntq], sBh + off);
                ldsm4(bl[ntq], sBl + off);
            }
            #pragma unroll
            for (int mt = 0; mt < 2; mt++)
                #pragma unroll
                for (int nt = 0; nt < 4; nt++) {
                    const uint32_t* bhp = &bh[nt >> 1][(nt & 1) * 2];
                    const uint32_t* blp = &bl[nt >> 1][(nt & 1) * 2];
                    mma16816(acc[mt][nt], ah[mt], bhp);
                    mma16816(acc[mt][nt], al[mt], bhp);
                    mma16816(acc[mt][nt], ah[mt], blp);
                }
        }
        __syncthreads();
        if (c + 2 < 16) {
            k3a_load(sb + (c & 1) * STAGE, tid, (c + 2) * KC, row0);
            CP_COMMIT();
        }
    }

    int gp = lane >> 2, tq = lane & 3;
    int ncol0 = wn * 32;
    #pragma unroll
    for (int mt = 0; mt < 2; mt++) {
        #pragma unroll
        for (int half = 0; half < 2; half++) {
            int p = row0 + wm*32 + mt*16 + gp + half*8;
            if (p >= NROWS) continue;
            float* lp = out_logits + (size_t)p * NCLS;
            #pragma unroll
            for (int nt = 0; nt < 4; nt++) {
                int col = ncol0 + nt*8 + tq*2;
                if (col < NCLS)     lp[col]     = acc[mt][nt][half*2+0] + b2[col];
                if (col + 1 < NCLS) lp[col + 1] = acc[mt][nt][half*2+1] + b2[col + 1];
            }
        }
    }
}

// =============================================================================
// K3b: softmax -> probs output; fp32 overall (ranking key)
// =============================================================================
__global__ void k3b_softmax(const float* __restrict__ out_logits,
                            const float* __restrict__ scores,
                            const int*   __restrict__ connect,
                            float* __restrict__ out_probs)
{
    int row = blockIdx.x * blockDim.x + threadIdx.x;
    if (row >= NROWS) return;
    const float* lp = out_logits + (size_t)row * NCLS;
    float l[NCLS];
    float m = -1e30f;
    #pragma unroll
    for (int c = 0; c < NCLS; c++) { l[c] = lp[c]; m = fmaxf(m, l[c]); }
    float s = 0.f;
    #pragma unroll
    for (int c = 0; c < NCLS; c++) { l[c] = expf(l[c] - m); s += l[c]; }
    float inv = 1.0f / s;
    float* pp = out_probs + (size_t)row * NCLS;
    float best = 0.f;
    #pragma unroll
    for (int c = 0; c < NCLS; c++) {
        float pr = l[c] * inv;
        pp[c] = pr;
        if (c >= 1 && pr > best) best = pr;
    }
    int b = row / NPAIR, p = row % NPAIR;
    int si = connect[(size_t)b*2*NPAIR + p];
    int oi = connect[(size_t)b*2*NPAIR + NPAIR + p];
    g_overall[row] = best * scores[b*NINST + si] * scores[b*NINST + oi];
}

// =============================================================================
// K4: warp-tournament top-NCAND selection
// =============================================================================
__global__ __launch_bounds__(1024) void k4_select()
{
    __shared__ float vals[NPAIR];
    __shared__ float wmax[32];
    __shared__ int   warg[32];
    __shared__ int   s_win;
    int b = blockIdx.x, tid = threadIdx.x, w = tid >> 5, lane = tid & 31;
    for (int i = tid; i < NPAIR; i += 1024) vals[i] = g_overall[b*NPAIR + i];
    __syncthreads();

    int lo = w * 310;
    int hiv = lo + 310; if (hiv > NPAIR) hiv = NPAIR;
    float bv = -1.f; int bi = 0x7fffffff;
    for (int i = lo + lane; i < hiv; i += 32) {
        float v = vals[i];
        if (v > bv || (v == bv && i < bi)) { bv = v; bi = i; }
    }
    #pragma unroll
    for (int o = 16; o; o >>= 1) {
        float ov = __shfl_down_sync(0xffffffffu, bv, o);
        int   oi = __shfl_down_sync(0xffffffffu, bi, o);
        if (ov > bv || (ov == bv && oi < bi)) { bv = ov; bi = oi; }
    }
    if (lane == 0) { wmax[w] = bv; warg[w] = bi; }
    __syncthreads();

    for (int t = 0; t < NCAND; t++) {
        if (tid < 32) {
            float v = wmax[lane]; int i2 = warg[lane];
            #pragma unroll
            for (int o = 16; o; o >>= 1) {
                float ov = __shfl_down_sync(0xffffffffu, v, o);
                int   oi = __shfl_down_sync(0xffffffffu, i2, o);
                if (ov > v || (ov == v && oi < i2)) { v = ov; i2 = oi; }
            }
            if (lane == 0) {
                g_cand_idx[b*NCAND + t] = i2;
                vals[i2] = -2.f;
                s_win = i2 / 310;
            }
        }
        __syncthreads();
        if (w == s_win) {
            float nv = -1.f; int ni = 0x7fffffff;
            for (int i = lo + lane; i < hiv; i += 32) {
                float v = vals[i];
                if (v > nv || (v == nv && i < ni)) { nv = v; ni = i; }
            }
            #pragma unroll
            for (int o = 16; o; o >>= 1) {
                float ov = __shfl_down_sync(0xffffffffu, nv, o);
                int   oi = __shfl_down_sync(0xffffffffu, ni, o);
                if (ov > nv || (ov == nv && oi < ni)) { nv = ov; ni = oi; }
            }
            if (lane == 0) { wmax[w] = nv; warg[w] = ni; }
        }
        __syncthreads();
    }
}

// =============================================================================
// K5: compensated-fp32 exact partial h for candidates (TwoSum + FMA err)
// =============================================================================
#define CPB 4
__global__ __launch_bounds__(256) void k5_repair_h(const float* __restrict__ inst,
                                                   const float* __restrict__ phrase,
                                                   const float* __restrict__ W1,
                                                   const int*   __restrict__ connect,
                                                   const int*   __restrict__ pidx)
{
    __shared__ float sf[CPB][1536];
    int ks = blockIdx.x;
    int g  = blockIdx.y;
    int b  = blockIdx.z;
    int tid = threadIdx.x;
    int k0 = ks * 1536;

    #pragma unroll 1
    for (int c = 0; c < CPB; c++) {
        int slot = b*NCAND + g*CPB + c;
        int p  = g_cand_idx[slot];
        int si = connect[(size_t)b*2*NPAIR + p];
        int oi = connect[(size_t)b*2*NPAIR + NPAIR + p];
        int ph = pidx[b*NPAIR + p];
        const float* s0 = inst   + ((size_t)b*NINST + si)*1024;
        const float* s1 = inst   + ((size_t)b*NINST + oi)*1024;
        const float* s2 = phrase + ((size_t)b*NPAIR + ph)*1024;
        for (int k = tid; k < 1536; k += 256) {
            int f = k0 + k;
            float v;
            if (f < 1024)       v = s0[f];
            else if (f < 2048)  v = s1[f - 1024];
            else                v = s2[f - 2048];
            sf[c][k] = v;
        }
    }
    __syncthreads();

    float s[CPB][4] = {};
    float comp[CPB][4] = {};
    const float* wcol = W1 + (size_t)k0 * 1024 + tid * 4;
    #pragma unroll 2
    for (int k = 0; k < 1536; k++) {
        float4 w = *(const float4*)(wcol + (size_t)k * 1024);
        float wv[4] = {w.x, w.y, w.z, w.w};
        #pragma unroll
        for (int c = 0; c < CPB; c++) {
            float f = sf[c][k];
            #pragma unroll
            for (int j = 0; j < 4; j++) {
                float p  = __fmul_rn(f, wv[j]);
                float e  = __fmaf_rn(f, wv[j], -p);
                float t  = __fadd_rn(s[c][j], p);
                float z  = __fsub_rn(t, s[c][j]);
                float e2 = __fadd_rn(__fsub_rn(s[c][j], __fsub_rn(t, z)),
                                     __fsub_rn(p, z));
                comp[c][j] = __fadd_rn(comp[c][j], __fadd_rn(e2, e));
                s[c][j] = t;
            }
        }
    }
    float* outs = g_hs[ks];
    float* outc = g_hc[ks];
    #pragma unroll
    for (int c = 0; c < CPB; c++) {
        int slot = b*NCAND + g*CPB + c;
        *(float4*)(outs + (size_t)slot*1024 + tid*4) =
            make_float4(s[c][0], s[c][1], s[c][2], s[c][3]);
        *(float4*)(outc + (size_t)slot*1024 + tid*4) =
            make_float4(comp[c][0], comp[c][1], comp[c][2], comp[c][3]);
    }
}

// =============================================================================
// K6: combine compensated halves + b1 + lrelu (fp64), logits+softmax+decisions
// =============================================================================
__global__ __launch_bounds__(64) void k6_decide(const float* __restrict__ W2,
                                                const float* __restrict__ b2,
                                                const float* __restrict__ b1,
                                                const float* __restrict__ scores,
                                                const int*   __restrict__ connect)
{
    __shared__ double sh[1024];
    __shared__ double slog[NCLS];
    int slot = blockIdx.x;
    int tid = threadIdx.x;
    size_t base = (size_t)slot * 1024;
    for (int k = tid; k < 1024; k += 64) {
        double v = ((double)g_hs[0][base + k] + (double)g_hc[0][base + k])
                 + ((double)g_hs[1][base + k] + (double)g_hc[1][base + k])
                 + (double)b1[k];
        v = v > 0.0 ? v : 0.01 * v;
        sh[k] = v;
    }
    __syncthreads();

    if (tid < NCLS) {
        double acc = 0.0;
        #pragma unroll 8
        for (int k = 0; k < 1024; k++)
            acc = fma(sh[k], (double)W2[(size_t)k*NCLS + tid], acc);
        slog[tid] = acc + (double)b2[tid];
    }
    __syncthreads();

    if (tid == 0) {
        double m = slog[0];
        for (int c = 1; c < NCLS; c++) m = slog[c] > m ? slog[c] : m;
        double e[NCLS]; double ssum = 0.0;
        for (int c = 0; c < NCLS; c++) { e[c] = exp(slog[c] - m); ssum += e[c]; }
        double best = 0.0; int bl = 0;
        for (int c = 1; c < NCLS; c++) {
            double pr = e[c] / ssum;
            if (pr > best) { best = pr; bl = c; }
        }
        int b = slot >> 7;
        int p = g_cand_idx[slot];
        int si = connect[(size_t)b*2*NPAIR + p];
        int oi = connect[(size_t)b*2*NPAIR + NPAIR + p];
        double ov = best * (double)scores[b*NINST + si] * (double)scores[b*NINST + oi];
        g_cand_ovr[slot]  = ov;
        g_cand_prob[slot] = best;
        g_cand_lab[slot]  = bl;
    }
}

// =============================================================================
// K7: final top-100 per batch over NCAND candidates
// =============================================================================
__global__ __launch_bounds__(128) void k7_final(float* __restrict__ outbase)
{
    __shared__ double v[NCAND];
    __shared__ int    pix[NCAND];
    int b = blockIdx.x, tid = threadIdx.x;
    v[tid]   = g_cand_ovr[b*NCAND + tid];
    pix[tid] = g_cand_idx[b*NCAND + tid];
    __syncthreads();

    if (tid == 0) {
        float* out_lab  = outbase;
        float* out_prob = outbase + 800;
        float* out_val  = outbase + 1600;
        float* out_idx  = outbase + 2400;
        for (int t = 0; t < 100; t++) {
            double bv = -1.0; int bj = 0; int bidx = 0x7fffffff;
            for (int j = 0; j < NCAND; j++) {
                double val = v[j]; int ix = pix[j];
                if (val > bv || (val == bv && ix < bidx)) { bv = val; bj = j; bidx = ix; }
            }
            int slot2 = b*NCAND + bj;
            out_val [b*100 + t] = (float)bv;
            out_idx [b*100 + t] = (float)bidx;
            out_lab [b*100 + t] = (float)g_cand_lab[slot2];
            out_prob[b*100 + t] = (float)g_cand_prob[slot2];
            v[bj] = -2.0;
        }
    }
}

// =============================================================================
extern "C" void kernel_launch(void* const* d_in, const int* in_sizes, int n_in,
                              void* d_out, int out_size)
{
    const float* inst    = (const float*)d_in[0];
    const float* phrase  = (const float*)d_in[1];
    const float* scores  = (const float*)d_in[2];
    const float* W1      = (const float*)d_in[3];
    const float* b1      = (const float*)d_in[4];
    const float* W2      = (const float*)d_in[5];
    const float* b2      = (const float*)d_in[6];
    const int*   connect = (const int*)d_in[7];
    const int*   pidx    = (const int*)d_in[8];

    float* out        = (float*)d_out;
    float* out_logits = out;
    float* out_probs  = out + (size_t)BATCH*NPAIR*NCLS;
    float* out_top    = out + (size_t)2*BATCH*NPAIR*NCLS;

    cudaFuncSetAttribute(k2_mma,     cudaFuncAttributeMaxDynamicSharedMemorySize, MM_SMEM);
    cudaFuncSetAttribute(k3a_logits, cudaFuncAttributeMaxDynamicSharedMemorySize, MM_SMEM);

    kprep_w<<<dim3(32, 32), 256>>>(W1);
    kprep_w2<<<64, 256>>>(W2);
    kprep_a<<<NROWS, 256>>>(phrase, pidx);
    k1_instproj<<<dim3(32, 13), 256>>>(inst, W1);
    k2_mma<<<dim3(16, 78, BATCH), 256, MM_SMEM>>>(b1, connect);
    k3a_logits<<<619, 256, MM_SMEM>>>(b2, out_logits);
    k3b_softmax<<<(NROWS + 255) / 256, 256>>>(out_logits, scores, connect, out_probs);
    k4_select<<<BATCH, 1024>>>();
    k5_repair_h<<<dim3(2, 32, BATCH), 256>>>(inst, phrase, W1, connect, pidx);
    k6_decide<<<BATCH*NCAND, 64>>>(W2, b2, b1, scores, connect);
    k7_final<<<BATCH, 128>>>(out_top);
}

// round 8
// speedup vs baseline: 3.1172x; 1.0056x over previous
#include <cuda_runtime.h>
#include <cuda_bf16.h>
#include <math.h>
#include <stdint.h>

#define BATCH 8
#define NINST 100
#define NPAIR 9900
#define NCLS  51
#define NROWS (BATCH*NPAIR)   // 79200
#define NCAND 128
#define KC    64
#define MARGIN 5e-4f
// k2/k3a stage: Ahi 16K | Alo 16K | Bhi 8K | Blo 8K = 48KB
#define SA_LO 16384
#define SB_HI 32768
#define SB_LO 40960
#define STAGE 49152
#define MM_SMEM (2*STAGE)

// ---------------- scratch (device globals; no allocs allowed) ----------------
__device__ float  g_A12[BATCH*NINST*2048];
__device__ float  g_overall[NROWS];
__device__ float  g_predprob[NROWS];
__device__ float  g_margin[NROWS];
__device__ int    g_predlab[NROWS];
__device__ int    g_cand_idx[BATCH*NCAND];
__device__ int    g_cand_lab[BATCH*NCAND];
__device__ double g_cand_prob[BATCH*NCAND];
__device__ double g_cand_ovr[BATCH*NCAND];
__device__ int    g_fix_list[BATCH*NCAND];
__device__ int    g_fix_cnt[BATCH];
__device__ float  g_hs[2][BATCH*NCAND*1024];   // compensated fp32 partial h (sum)
__device__ float  g_hc[2][BATCH*NCAND*1024];   // compensated fp32 partial h (comp)
__device__ __align__(16) unsigned short g_Ahi[81100800];  // gathered phrase bf16 hi
__device__ __align__(16) unsigned short g_Alo[81100800];  // bf16 lo
__device__ __align__(16) unsigned short g_Bhi[1024*1024]; // W1c^T [n][k] bf16 hi
__device__ __align__(16) unsigned short g_Blo[1024*1024];
__device__ __align__(16) unsigned short g_Hhi[81100800];  // hidden h bf16 hi
__device__ __align__(16) unsigned short g_Hlo[81100800];  // hidden h bf16 lo
__device__ __align__(16) unsigned short g_W2hi[64*1024];  // W2^T padded [64][1024]
__device__ __align__(16) unsigned short g_W2lo[64*1024];

// ---------------- helpers (baseline PTX only) ----------------
__device__ __forceinline__ uint32_t smem_u32(const void* p) {
    uint32_t a;
    asm("{ .reg .u64 t; cvta.to.shared.u64 t, %1; cvt.u32.u64 %0, t; }" : "=r"(a) : "l"(p));
    return a;
}
#define SWZ(x) ((x) ^ (((x) >> 3) & 0x70))
__device__ __forceinline__ void cpasync16(uint32_t dst, const void* src) {
    asm volatile("cp.async.cg.shared.global [%0], [%1], 16;" :: "r"(dst), "l"(src));
}
#define CP_COMMIT() asm volatile("cp.async.commit_group;" ::: "memory")
__device__ __forceinline__ void ldsm4(uint32_t* r, uint32_t addr) {
    asm volatile("ldmatrix.sync.aligned.m8n8.x4.shared.b16 {%0,%1,%2,%3}, [%4];"
        : "=r"(r[0]), "=r"(r[1]), "=r"(r[2]), "=r"(r[3]) : "r"(addr));
}
__device__ __forceinline__ void mma16816(float* c, const uint32_t* a, const uint32_t* b) {
    asm volatile("mma.sync.aligned.m16n8k16.row.col.f32.bf16.bf16.f32 "
        "{%0,%1,%2,%3}, {%4,%5,%6,%7}, {%8,%9}, {%0,%1,%2,%3};"
        : "+f"(c[0]), "+f"(c[1]), "+f"(c[2]), "+f"(c[3])
        : "r"(a[0]), "r"(a[1]), "r"(a[2]), "r"(a[3]), "r"(b[0]), "r"(b[1]));
}

// =============================================================================
// prep_w: W1c (rows 2048..3071 of W1, [k][n]) -> g_Bhi/g_Blo as [n][k] bf16
// =============================================================================
__global__ __launch_bounds__(256) void kprep_w(const float* __restrict__ W1)
{
    __shared__ float t[32][33];
    int kk0 = blockIdx.x * 32, nn0 = blockIdx.y * 32;
    int tx = threadIdx.x & 31, ty = threadIdx.x >> 5;
    #pragma unroll
    for (int i = 0; i < 32; i += 8)
        t[ty + i][tx] = W1[(size_t)(2048 + kk0 + ty + i) * 1024 + nn0 + tx];
    __syncthreads();
    #pragma unroll
    for (int i = 0; i < 32; i += 8) {
        float x = t[tx][ty + i];
        __nv_bfloat16 h = __float2bfloat16(x);
        float lo = x - __bfloat162float(h);
        __nv_bfloat16 l = __float2bfloat16(lo);
        size_t o = (size_t)(nn0 + ty + i) * 1024 + kk0 + tx;
        g_Bhi[o] = __bfloat16_as_ushort(h);
        g_Blo[o] = __bfloat16_as_ushort(l);
    }
}

// =============================================================================
// prep_w2: W2 [k][51] -> g_W2hi/lo [n=64 pad][k] bf16
// =============================================================================
__global__ __launch_bounds__(256) void kprep_w2(const float* __restrict__ W2)
{
    int n = blockIdx.x;            // 0..63
    for (int k = threadIdx.x; k < 1024; k += 256) {
        float x = (n < NCLS) ? W2[(size_t)k * NCLS + n] : 0.f;
        __nv_bfloat16 h = __float2bfloat16(x);
        float lo = x - __bfloat162float(h);
        g_W2hi[n * 1024 + k] = __bfloat16_as_ushort(h);
        g_W2lo[n * 1024 + k] = __bfloat16_as_ushort(__float2bfloat16(lo));
    }
}

// =============================================================================
// prep_a: gather phrase rows per pair, split into bf16 hi/lo
// =============================================================================
__global__ __launch_bounds__(256) void kprep_a(const float* __restrict__ phrase,
                                               const int* __restrict__ pidx)
{
    int r = blockIdx.x;
    int b = r / NPAIR;
    int ph = pidx[r];
    const float4* src = (const float4*)(phrase + ((size_t)b * NPAIR + ph) * 1024);
    float4 v = src[threadIdx.x];
    ushort4 hi, lo;
    #define SPL(c, hf, lf) { __nv_bfloat16 _h = __float2bfloat16(v.c); \
        float _l = v.c - __bfloat162float(_h); \
        hf = __bfloat16_as_ushort(_h); lf = __bfloat16_as_ushort(__float2bfloat16(_l)); }
    SPL(x, hi.x, lo.x) SPL(y, hi.y, lo.y) SPL(z, hi.z, lo.z) SPL(w, hi.w, lo.w)
    #undef SPL
    size_t o = (size_t)r * 1024 + threadIdx.x * 4;
    *(ushort4*)(g_Ahi + o) = hi;
    *(ushort4*)(g_Alo + o) = lo;
}

// =============================================================================
// K1: A12[r, j] = inst[r, :] @ W1[half*1024 + :, jc]   (fp32, small)
// =============================================================================
__global__ __launch_bounds__(256) void k1_instproj(const float* __restrict__ inst,
                                                   const float* __restrict__ W1)
{
    __shared__ float As[16][68];
    __shared__ float Bs[16][64];
    int tid = threadIdx.x;
    int n0 = blockIdx.x * 64;
    int m0 = blockIdx.y * 64;
    int half = n0 >> 10;
    int jc0  = n0 & 1023;
    const float* wbase = W1 + (size_t)half * 1024 * 1024 + jc0;

    int arow = tid >> 2;
    int akq  = (tid & 3) * 4;
    int ar   = m0 + arow; if (ar > 799) ar = 799;
    const float* aptr = inst + (size_t)ar * 1024 + akq;
    int brow = tid >> 4;
    int bn   = (tid & 15) * 4;
    int tx = tid & 15, ty = tid >> 4;
    float acc[4][4] = {};

    for (int k0 = 0; k0 < 1024; k0 += 16) {
        float4 av = *(const float4*)(aptr + k0);
        float4 bv = *(const float4*)(wbase + (size_t)(k0 + brow) * 1024 + bn);
        As[akq+0][arow] = av.x; As[akq+1][arow] = av.y;
        As[akq+2][arow] = av.z; As[akq+3][arow] = av.w;
        *(float4*)&Bs[brow][bn] = bv;
        __syncthreads();
        #pragma unroll
        for (int kk = 0; kk < 16; kk++) {
            float af[4], bf[4];
            *(float4*)af = *(const float4*)&As[kk][ty*4];
            *(float4*)bf = *(const float4*)&Bs[kk][tx*4];
            #pragma unroll
            for (int i = 0; i < 4; i++)
                #pragma unroll
                for (int j = 0; j < 4; j++)
                    acc[i][j] += af[i] * bf[j];
        }
        __syncthreads();
    }
    #pragma unroll
    for (int i = 0; i < 4; i++) {
        int r = m0 + ty*4 + i;
        if (r < 800)
            *(float4*)&g_A12[(size_t)r*2048 + n0 + tx*4] =
                make_float4(acc[i][0], acc[i][1], acc[i][2], acc[i][3]);
    }
}

// =============================================================================
// K2 (mma.sync bf16 split, 2 CTA/SM): h = lrelu(Aphr@W1c + A12[sub]+A12[obj]+b1)
// =============================================================================
__device__ __forceinline__ void k2_load(uint32_t st, int tid, int k0,
                                        size_t rowbase, int p0, int n0)
{
    #pragma unroll 1
    for (int i = tid; i < 3072; i += 256) {
        int q = i & 7;
        const unsigned short* src;
        uint32_t dst;
        if (i < 2048) {
            int t = i >> 10;
            int r = (i >> 3) & 127;
            int p = p0 + r; if (p > NPAIR - 1) p = NPAIR - 1;
            src = (t ? g_Alo : g_Ahi) + (rowbase + p) * 1024 + k0 + q * 8;
            dst = st + t * SA_LO + SWZ(r * 128 + q * 16);
        } else {
            int j = i - 2048;
            int t = j >> 9;
            int n = (j >> 3) & 63;
            src = (t ? g_Blo : g_Bhi) + (size_t)(n0 + n) * 1024 + k0 + q * 8;
            dst = st + SB_HI + t * 8192 + SWZ(n * 128 + q * 16);
        }
        cpasync16(dst, src);
    }
}

__global__ void __launch_bounds__(256, 2) k2_mma(const float* __restrict__ b1,
                                                 const int* __restrict__ connect)
{
    extern __shared__ __align__(1024) char smem[];
    uint32_t sb = smem_u32(smem);
    int tid = threadIdx.x;
    int lane = tid & 31, wid = tid >> 5;
    int wm = wid & 3, wn = wid >> 2;
    int n0 = blockIdx.x * 64;
    int p0 = blockIdx.y * 128;
    int b  = blockIdx.z;
    size_t rowbase = (size_t)b * NPAIR;

    float acc[2][4][4] = {};

    k2_load(sb,         tid, 0,  rowbase, p0, n0); CP_COMMIT();
    k2_load(sb + STAGE, tid, KC, rowbase, p0, n0); CP_COMMIT();

    #pragma unroll 1
    for (int c = 0; c < 16; c++) {
        if (c < 15) asm volatile("cp.async.wait_group 1;" ::: "memory");
        else        asm volatile("cp.async.wait_group 0;" ::: "memory");
        __syncthreads();

        uint32_t st  = sb + (c & 1) * STAGE;
        uint32_t sAh = st, sAl = st + SA_LO, sBh = st + SB_HI, sBl = st + SB_LO;

        #pragma unroll
        for (int ks = 0; ks < 4; ks++) {
            int kb = ks * 32;
            uint32_t ah[2][4], al[2][4], bh[2][4], bl[2][4];
            #pragma unroll
            for (int mt = 0; mt < 2; mt++) {
                uint32_t off = SWZ((wm*32 + mt*16 + (lane & 15)) * 128 + kb + (lane >> 4) * 16);
                ldsm4(ah[mt], sAh + off);
                ldsm4(al[mt], sAl + off);
            }
            int nrow  = (lane & 7) + ((lane >> 4) & 1) * 8;
            int khalf = ((lane >> 3) & 1) * 16;
            #pragma unroll
            for (int ntq = 0; ntq < 2; ntq++) {
                uint32_t off = SWZ((wn*32 + ntq*16 + nrow) * 128 + kb + khalf);
                ldsm4(bh[ntq], sBh + off);
                ldsm4(bl[ntq], sBl + off);
            }
            #pragma unroll
            for (int mt = 0; mt < 2; mt++)
                #pragma unroll
                for (int nt = 0; nt < 4; nt++) {
                    const uint32_t* bhp = &bh[nt >> 1][(nt & 1) * 2];
                    const uint32_t* blp = &bl[nt >> 1][(nt & 1) * 2];
                    mma16816(acc[mt][nt], ah[mt], bhp);
                    mma16816(acc[mt][nt], al[mt], bhp);
                    mma16816(acc[mt][nt], ah[mt], blp);
                }
        }
        __syncthreads();
        if (c + 2 < 16) {
            k2_load(sb + (c & 1) * STAGE, tid, (c + 2) * KC, rowbase, p0, n0);
            CP_COMMIT();
        }
    }

    int gp = lane >> 2, tq = lane & 3;
    int n0w = n0 + wn * 32;
    size_t bb2 = (size_t)b * 2 * NPAIR;
    const float* a12b = g_A12 + (size_t)b * NINST * 2048;
    #pragma unroll
    for (int mt = 0; mt < 2; mt++) {
        #pragma unroll
        for (int half = 0; half < 2; half++) {
            int p = p0 + wm*32 + mt*16 + gp + half*8;
            if (p >= NPAIR) continue;
            int sub = connect[bb2 + p];
            int obj = connect[bb2 + NPAIR + p];
            const float* r1 = a12b + (size_t)sub * 2048 + n0w;
            const float* r2 = a12b + (size_t)obj * 2048 + 1024 + n0w;
            size_t hoff = ((size_t)b * NPAIR + p) * 1024 + n0w;
            #pragma unroll
            for (int nt = 0; nt < 4; nt++) {
                int cc = nt*8 + tq*2;
                float2 v1 = *(const float2*)(r1 + cc);
                float2 v2 = *(const float2*)(r2 + cc);
                float2 vb = *(const float2*)(b1 + n0w + cc);
                float x = acc[mt][nt][half*2+0] + v1.x + v2.x + vb.x;
                float y = acc[mt][nt][half*2+1] + v1.y + v2.y + vb.y;
                x = x > 0.f ? x : 0.01f * x;
                y = y > 0.f ? y : 0.01f * y;
                __nv_bfloat16 xh = __float2bfloat16(x);
                __nv_bfloat16 yh = __float2bfloat16(y);
                ushort2 hi2, lo2;
                hi2.x = __bfloat16_as_ushort(xh);
                hi2.y = __bfloat16_as_ushort(yh);
                lo2.x = __bfloat16_as_ushort(__float2bfloat16(x - __bfloat162float(xh)));
                lo2.y = __bfloat16_as_ushort(__float2bfloat16(y - __bfloat162float(yh)));
                *(ushort2*)(g_Hhi + hoff + cc) = hi2;
                *(ushort2*)(g_Hlo + hoff + cc) = lo2;
            }
        }
    }
}

// =============================================================================
// K3a (tensor): logits = h @ W2 + b2
// =============================================================================
__device__ __forceinline__ void k3a_load(uint32_t st, int tid, int k0, int row0)
{
    #pragma unroll 1
    for (int i = tid; i < 3072; i += 256) {
        int q = i & 7;
        const unsigned short* src;
        uint32_t dst;
        if (i < 2048) {
            int t = i >> 10;
            int r = (i >> 3) & 127;
            int p = row0 + r; if (p > NROWS - 1) p = NROWS - 1;
            src = (t ? g_Hlo : g_Hhi) + (size_t)p * 1024 + k0 + q * 8;
            dst = st + t * SA_LO + SWZ(r * 128 + q * 16);
        } else {
            int j = i - 2048;
            int t = j >> 9;
            int n = (j >> 3) & 63;
            src = (t ? g_W2lo : g_W2hi) + (size_t)n * 1024 + k0 + q * 8;
            dst = st + SB_HI + t * 8192 + SWZ(n * 128 + q * 16);
        }
        cpasync16(dst, src);
    }
}

__global__ void __launch_bounds__(256, 2) k3a_logits(const float* __restrict__ b2,
                                                     float* __restrict__ out_logits)
{
    extern __shared__ __align__(1024) char smem[];
    uint32_t sb = smem_u32(smem);
    int tid = threadIdx.x;
    int lane = tid & 31, wid = tid >> 5;
    int wm = wid & 3, wn = wid >> 2;
    int row0 = blockIdx.x * 128;

    float acc[2][4][4] = {};

    k3a_load(sb,         tid, 0,  row0); CP_COMMIT();
    k3a_load(sb + STAGE, tid, KC, row0); CP_COMMIT();

    #pragma unroll 1
    for (int c = 0; c < 16; c++) {
        if (c < 15) asm volatile("cp.async.wait_group 1;" ::: "memory");
        else        asm volatile("cp.async.wait_group 0;" ::: "memory");
        __syncthreads();

        uint32_t st  = sb + (c & 1) * STAGE;
        uint32_t sAh = st, sAl = st + SA_LO, sBh = st + SB_HI, sBl = st + SB_LO;

        #pragma unroll
        for (int ks = 0; ks < 4; ks++) {
            int kb = ks * 32;
            uint32_t ah[2][4], al[2][4], bh[2][4], bl[2][4];
            #pragma unroll
            for (int mt = 0; mt < 2; mt++) {
                uint32_t off = SWZ((wm*32 + mt*16 + (lane & 15)) * 128 + kb + (lane >> 4) * 16);
                ldsm4(ah[mt], sAh + off);
                ldsm4(al[mt], sAl + off);
            }
            int nrow  = (lane & 7) + ((lane >> 4) & 1) * 8;
            int khalf = ((lane >> 3) & 1) * 16;
            #pragma unroll
            for (int ntq = 0; ntq < 2; ntq++) {
                uint32_t off = SWZ((wn*32 + ntq*16 + nrow) * 128 + kb + khalf);
                ldsm4(bh[ntq], sBh + off);
                ldsm4(bl[ntq], sBl + off);
            }
            #pragma unroll
            for (int mt = 0; mt < 2; mt++)
                #pragma unroll
                for (int nt = 0; nt < 4; nt++) {
                    const uint32_t* bhp = &bh[nt >> 1][(nt & 1) * 2];
                    const uint32_t* blp = &bl[nt >> 1][(nt & 1) * 2];
                    mma16816(acc[mt][nt], ah[mt], bhp);
                    mma16816(acc[mt][nt], al[mt], bhp);
                    mma16816(acc[mt][nt], ah[mt], blp);
                }
        }
        __syncthreads();
        if (c + 2 < 16) {
            k3a_load(sb + (c & 1) * STAGE, tid, (c + 2) * KC, row0);
            CP_COMMIT();
        }
    }

    int gp = lane >> 2, tq = lane & 3;
    int ncol0 = wn * 32;
    #pragma unroll
    for (int mt = 0; mt < 2; mt++) {
        #pragma unroll
        for (int half = 0; half < 2; half++) {
            int p = row0 + wm*32 + mt*16 + gp + half*8;
            if (p >= NROWS) continue;
            float* lp = out_logits + (size_t)p * NCLS;
            #pragma unroll
            for (int nt = 0; nt < 4; nt++) {
                int col = ncol0 + nt*8 + tq*2;
                if (col < NCLS)     lp[col]     = acc[mt][nt][half*2+0] + b2[col];
                if (col + 1 < NCLS) lp[col + 1] = acc[mt][nt][half*2+1] + b2[col + 1];
            }
        }
    }
}

// =============================================================================
// K3b: softmax -> probs; dense decisions + margins
// =============================================================================
__global__ void k3b_softmax(const float* __restrict__ out_logits,
                            const float* __restrict__ scores,
                            const int*   __restrict__ connect,
                            float* __restrict__ out_probs)
{
    int row = blockIdx.x * blockDim.x + threadIdx.x;
    if (row >= NROWS) return;
    const float* lp = out_logits + (size_t)row * NCLS;
    float l[NCLS];
    float m = -1e30f;
    #pragma unroll
    for (int c = 0; c < NCLS; c++) { l[c] = lp[c]; m = fmaxf(m, l[c]); }
    float s = 0.f;
    #pragma unroll
    for (int c = 0; c < NCLS; c++) { l[c] = expf(l[c] - m); s += l[c]; }
    float inv = 1.0f / s;
    float* pp = out_probs + (size_t)row * NCLS;
    float best = 0.f, second = 0.f; int bidx = 0;
    #pragma unroll
    for (int c = 0; c < NCLS; c++) {
        float pr = l[c] * inv;
        pp[c] = pr;
        if (c >= 1) {
            if (pr > best) { second = best; best = pr; bidx = c; }
            else if (pr > second) second = pr;
        }
    }
    int b = row / NPAIR, p = row % NPAIR;
    int si = connect[(size_t)b*2*NPAIR + p];
    int oi = connect[(size_t)b*2*NPAIR + NPAIR + p];
    g_overall[row]  = best * scores[b*NINST + si] * scores[b*NINST + oi];
    g_predprob[row] = best;
    g_predlab[row]  = bidx;
    g_margin[row]   = best - second;
}

// =============================================================================
// K4: warp-tournament top-NCAND selection
// =============================================================================
__global__ __launch_bounds__(1024) void k4_select()
{
    __shared__ float vals[NPAIR];
    __shared__ float wmax[32];
    __shared__ int   warg[32];
    __shared__ int   s_win;
    int b = blockIdx.x, tid = threadIdx.x, w = tid >> 5, lane = tid & 31;
    for (int i = tid; i < NPAIR; i += 1024) vals[i] = g_overall[b*NPAIR + i];
    __syncthreads();

    int lo = w * 310;
    int hiv = lo + 310; if (hiv > NPAIR) hiv = NPAIR;
    float bv = -1.f; int bi = 0x7fffffff;
    for (int i = lo + lane; i < hiv; i += 32) {
        float v = vals[i];
        if (v > bv || (v == bv && i < bi)) { bv = v; bi = i; }
    }
    #pragma unroll
    for (int o = 16; o; o >>= 1) {
        float ov = __shfl_down_sync(0xffffffffu, bv, o);
        int   oi = __shfl_down_sync(0xffffffffu, bi, o);
        if (ov > bv || (ov == bv && oi < bi)) { bv = ov; bi = oi; }
    }
    if (lane == 0) { wmax[w] = bv; warg[w] = bi; }
    __syncthreads();

    for (int t = 0; t < NCAND; t++) {
        if (tid < 32) {
            float v = wmax[lane]; int i2 = warg[lane];
            #pragma unroll
            for (int o = 16; o; o >>= 1) {
                float ov = __shfl_down_sync(0xffffffffu, v, o);
                int   oi = __shfl_down_sync(0xffffffffu, i2, o);
                if (ov > v || (ov == v && oi < i2)) { v = ov; i2 = oi; }
            }
            if (lane == 0) {
                g_cand_idx[b*NCAND + t] = i2;
                vals[i2] = -2.f;
                s_win = i2 / 310;
            }
        }
        __syncthreads();
        if (w == s_win) {
            float nv = -1.f; int ni = 0x7fffffff;
            for (int i = lo + lane; i < hiv; i += 32) {
                float v = vals[i];
                if (v > nv || (v == nv && i < ni)) { nv = v; ni = i; }
            }
            #pragma unroll
            for (int o = 16; o; o >>= 1) {
                float ov = __shfl_down_sync(0xffffffffu, nv, o);
                int   oi = __shfl_down_sync(0xffffffffu, ni, o);
                if (ov > nv || (ov == nv && oi < ni)) { nv = ov; ni = oi; }
            }
            if (lane == 0) { wmax[w] = nv; warg[w] = ni; }
        }
        __syncthreads();
    }
}

// =============================================================================
// K4b: init candidate outputs with dense values; flag decision-critical ones
// (argmax margin or pairwise overall gap < MARGIN); compact flagged list.
// =============================================================================
__global__ __launch_bounds__(NCAND) void k4b_flag()
{
    __shared__ float ov[NCAND];
    __shared__ int   fl[NCAND];
    int b = blockIdx.x, i = threadIdx.x;
    int cand = g_cand_idx[b*NCAND + i];
    int row  = b*NPAIR + cand;
    float o  = g_overall[row];
    ov[i] = o;
    __syncthreads();

    int f = (g_margin[row] < MARGIN) ? 1 : 0;
    for (int j = 0; j < NCAND; j++)
        if (j != i && fabsf(o - ov[j]) < MARGIN) f = 1;
    fl[i] = f;

    // dense init
    g_cand_ovr [b*NCAND + i] = (double)o;
    g_cand_prob[b*NCAND + i] = (double)g_predprob[row];
    g_cand_lab [b*NCAND + i] = g_predlab[row];
    __syncthreads();

    if (i == 0) {
        int n = 0;
        for (int j = 0; j < NCAND; j++)
            if (fl[j]) g_fix_list[b*NCAND + (n++)] = j;
        g_fix_cnt[b] = n;
    }
}

// =============================================================================
// K5: compensated-fp32 exact partial h — FLAGGED candidates only
// =============================================================================
#define CPB 4
__global__ __launch_bounds__(256) void k5_repair_h(const float* __restrict__ inst,
                                                   const float* __restrict__ phrase,
                                                   const float* __restrict__ W1,
                                                   const int*   __restrict__ connect,
                                                   const int*   __restrict__ pidx)
{
    __shared__ float sf[CPB][1536];
    int ks = blockIdx.x;
    int g  = blockIdx.y;
    int b  = blockIdx.z;
    int tid = threadIdx.x;
    int k0 = ks * 1536;

    int cnt = g_fix_cnt[b];
    if (g * CPB >= cnt) return;
    int slots[CPB];

    #pragma unroll 1
    for (int c = 0; c < CPB; c++) {
        int jj = g*CPB + c; if (jj > cnt - 1) jj = cnt - 1;
        int slot = b*NCAND + g_fix_list[b*NCAND + jj];
        slots[c] = slot;
        int p  = g_cand_idx[slot];
        int si = connect[(size_t)b*2*NPAIR + p];
        int oi = connect[(size_t)b*2*NPAIR + NPAIR + p];
        int ph = pidx[b*NPAIR + p];
        const float* s0 = inst   + ((size_t)b*NINST + si)*1024;
        const float* s1 = inst   + ((size_t)b*NINST + oi)*1024;
        const float* s2 = phrase + ((size_t)b*NPAIR + ph)*1024;
        for (int k = tid; k < 1536; k += 256) {
            int f = k0 + k;
            float v;
            if (f < 1024)       v = s0[f];
            else if (f < 2048)  v = s1[f - 1024];
            else                v = s2[f - 2048];
            sf[c][k] = v;
        }
    }
    __syncthreads();

    float s[CPB][4] = {};
    float comp[CPB][4] = {};
    const float* wcol = W1 + (size_t)k0 * 1024 + tid * 4;
    #pragma unroll 2
    for (int k = 0; k < 1536; k++) {
        float4 w = *(const float4*)(wcol + (size_t)k * 1024);
        float wv[4] = {w.x, w.y, w.z, w.w};
        #pragma unroll
        for (int c = 0; c < CPB; c++) {
            float f = sf[c][k];
            #pragma unroll
            for (int j = 0; j < 4; j++) {
                float p  = __fmul_rn(f, wv[j]);
                float e  = __fmaf_rn(f, wv[j], -p);
                float t  = __fadd_rn(s[c][j], p);
                float z  = __fsub_rn(t, s[c][j]);
                float e2 = __fadd_rn(__fsub_rn(s[c][j], __fsub_rn(t, z)),
                                     __fsub_rn(p, z));
                comp[c][j] = __fadd_rn(comp[c][j], __fadd_rn(e2, e));
                s[c][j] = t;
            }
        }
    }
    float* outs = g_hs[ks];
    float* outc = g_hc[ks];
    #pragma unroll
    for (int c = 0; c < CPB; c++) {
        int slot = slots[c];
        *(float4*)(outs + (size_t)slot*1024 + tid*4) =
            make_float4(s[c][0], s[c][1], s[c][2], s[c][3]);
        *(float4*)(outc + (size_t)slot*1024 + tid*4) =
            make_float4(comp[c][0], comp[c][1], comp[c][2], comp[c][3]);
    }
}

// =============================================================================
// K6: exact decisions — FLAGGED candidates only (overwrite dense init)
// =============================================================================
__global__ __launch_bounds__(64) void k6_decide(const float* __restrict__ W2,
                                                const float* __restrict__ b2,
                                                const float* __restrict__ b1,
                                                const float* __restrict__ scores,
                                                const int*   __restrict__ connect)
{
    __shared__ double sh[1024];
    __shared__ double slog[NCLS];
    int gid = blockIdx.x;
    int b = gid >> 7, j = gid & (NCAND - 1);
    if (j >= g_fix_cnt[b]) return;
    int slot = b*NCAND + g_fix_list[b*NCAND + j];
    int tid = threadIdx.x;
    size_t base = (size_t)slot * 1024;
    for (int k = tid; k < 1024; k += 64) {
        double v = ((double)g_hs[0][base + k] + (double)g_hc[0][base + k])
                 + ((double)g_hs[1][base + k] + (double)g_hc[1][base + k])
                 + (double)b1[k];
        v = v > 0.0 ? v : 0.01 * v;
        sh[k] = v;
    }
    __syncthreads();

    if (tid < NCLS) {
        double acc = 0.0;
        #pragma unroll 8
        for (int k = 0; k < 1024; k++)
            acc = fma(sh[k], (double)W2[(size_t)k*NCLS + tid], acc);
        slog[tid] = acc + (double)b2[tid];
    }
    __syncthreads();

    if (tid == 0) {
        double m = slog[0];
        for (int c = 1; c < NCLS; c++) m = slog[c] > m ? slog[c] : m;
        double e[NCLS]; double ssum = 0.0;
        for (int c = 0; c < NCLS; c++) { e[c] = exp(slog[c] - m); ssum += e[c]; }
        double best = 0.0; int bl = 0;
        for (int c = 1; c < NCLS; c++) {
            double pr = e[c] / ssum;
            if (pr > best) { best = pr; bl = c; }
        }
        int p = g_cand_idx[slot];
        int si = connect[(size_t)b*2*NPAIR + p];
        int oi = connect[(size_t)b*2*NPAIR + NPAIR + p];
        double ov = best * (double)scores[b*NINST + si] * (double)scores[b*NINST + oi];
        g_cand_ovr[slot]  = ov;
        g_cand_prob[slot] = best;
        g_cand_lab[slot]  = bl;
    }
}

// =============================================================================
// K7: final top-100 per batch over NCAND candidates
// =============================================================================
__global__ __launch_bounds__(128) void k7_final(float* __restrict__ outbase)
{
    __shared__ double v[NCAND];
    __shared__ int    pix[NCAND];
    int b = blockIdx.x, tid = threadIdx.x;
    v[tid]   = g_cand_ovr[b*NCAND + tid];
    pix[tid] = g_cand_idx[b*NCAND + tid];
    __syncthreads();

    if (tid == 0) {
        float* out_lab  = outbase;
        float* out_prob = outbase + 800;
        float* out_val  = outbase + 1600;
        float* out_idx  = outbase + 2400;
        for (int t = 0; t < 100; t++) {
            double bv = -1.0; int bj = 0; int bidx = 0x7fffffff;
            for (int j = 0; j < NCAND; j++) {
                double val = v[j]; int ix = pix[j];
                if (val > bv || (val == bv && ix < bidx)) { bv = val; bj = j; bidx = ix; }
            }
            int slot2 = b*NCAND + bj;
            out_val [b*100 + t] = (float)bv;
            out_idx [b*100 + t] = (float)bidx;
            out_lab [b*100 + t] = (float)g_cand_lab[slot2];
            out_prob[b*100 + t] = (float)g_cand_prob[slot2];
            v[bj] = -2.0;
        }
    }
}

// =============================================================================
extern "C" void kernel_launch(void* const* d_in, const int* in_sizes, int n_in,
                              void* d_out, int out_size)
{
    const float* inst    = (const float*)d_in[0];
    const float* phrase  = (const float*)d_in[1];
    const float* scores  = (const float*)d_in[2];
    const float* W1      = (const float*)d_in[3];
    const float* b1      = (const float*)d_in[4];
    const float* W2      = (const float*)d_in[5];
    const float* b2      = (const float*)d_in[6];
    const int*   connect = (const int*)d_in[7];
    const int*   pidx    = (const int*)d_in[8];

    float* out        = (float*)d_out;
    float* out_logits = out;
    float* out_probs  = out + (size_t)BATCH*NPAIR*NCLS;
    float* out_top    = out + (size_t)2*BATCH*NPAIR*NCLS;

    cudaFuncSetAttribute(k2_mma,     cudaFuncAttributeMaxDynamicSharedMemorySize, MM_SMEM);
    cudaFuncSetAttribute(k3a_logits, cudaFuncAttributeMaxDynamicSharedMemorySize, MM_SMEM);

    kprep_w<<<dim3(32, 32), 256>>>(W1);
    kprep_w2<<<64, 256>>>(W2);
    kprep_a<<<NROWS, 256>>>(phrase, pidx);
    k1_instproj<<<dim3(32, 13), 256>>>(inst, W1);
    k2_mma<<<dim3(16, 78, BATCH), 256, MM_SMEM>>>(b1, connect);
    k3a_logits<<<619, 256, MM_SMEM>>>(b2, out_logits);
    k3b_softmax<<<(NROWS + 255) / 256, 256>>>(out_logits, scores, connect, out_probs);
    k4_select<<<BATCH, 1024>>>();
    k4b_flag<<<BATCH, NCAND>>>();
    k5_repair_h<<<dim3(2, 32, BATCH), 256>>>(inst, phrase, W1, connect, pidx);
    k6_decide<<<BATCH*NCAND, 64>>>(W2, b2, b1, scores, connect);
    k7_final<<<BATCH, 128>>>(out_top);
}

// round 9
// speedup vs baseline: 3.3416x; 1.0720x over previous
#include <cuda_runtime.h>
#include <cuda_bf16.h>
#include <cuda_fp16.h>
#include <math.h>
#include <stdint.h>

#define BATCH 8
#define NINST 100
#define NPAIR 9900
#define NCLS  51
#define NROWS (BATCH*NPAIR)   // 79200
#define NCAND 128
#define KC    64
#define MARGIN 2.5e-3f
// k2 stage: Ahi 16K | Alo 16K | Bhi 8K = 40KB (fp16, 2-product)
#define K2A_LO 16384
#define K2B    32768
#define K2STG  40960
#define K2_SMEM (2*K2STG)
// k3a stage: Ahi 16K | Alo 16K | Bhi 8K | Blo 8K = 48KB (bf16, 3-product)
#define SA_LO 16384
#define SB_HI 32768
#define SB_LO 40960
#define STAGE 49152
#define MM_SMEM (2*STAGE)

// ---------------- scratch (device globals; no allocs allowed) ----------------
__device__ float  g_A12[BATCH*NINST*2048];
__device__ float  g_overall[NROWS];
__device__ float  g_predprob[NROWS];
__device__ float  g_margin[NROWS];
__device__ int    g_predlab[NROWS];
__device__ int    g_cand_idx[BATCH*NCAND];
__device__ int    g_cand_lab[BATCH*NCAND];
__device__ double g_cand_prob[BATCH*NCAND];
__device__ double g_cand_ovr[BATCH*NCAND];
__device__ int    g_fix_list[BATCH*NCAND];
__device__ int    g_fix_cnt[BATCH];
__device__ float  g_hs[2][BATCH*NCAND*1024];   // compensated fp32 partial h (sum)
__device__ float  g_hc[2][BATCH*NCAND*1024];   // compensated fp32 partial h (comp)
__device__ __align__(16) unsigned short g_Ahi[81100800];  // gathered phrase fp16 hi
__device__ __align__(16) unsigned short g_Alo[81100800];  // fp16 lo
__device__ __align__(16) unsigned short g_Bhi[1024*1024]; // W1c^T [n][k] fp16 hi
__device__ __align__(16) unsigned short g_Hhi[81100800];  // hidden h bf16 hi
__device__ __align__(16) unsigned short g_Hlo[81100800];  // hidden h bf16 lo
__device__ __align__(16) unsigned short g_W2hi[64*1024];  // W2^T padded bf16 hi
__device__ __align__(16) unsigned short g_W2lo[64*1024];  // bf16 lo

// ---------------- helpers (baseline PTX only) ----------------
__device__ __forceinline__ uint32_t smem_u32(const void* p) {
    uint32_t a;
    asm("{ .reg .u64 t; cvta.to.shared.u64 t, %1; cvt.u32.u64 %0, t; }" : "=r"(a) : "l"(p));
    return a;
}
#define SWZ(x) ((x) ^ (((x) >> 3) & 0x70))
__device__ __forceinline__ void cpasync16(uint32_t dst, const void* src) {
    asm volatile("cp.async.cg.shared.global [%0], [%1], 16;" :: "r"(dst), "l"(src));
}
#define CP_COMMIT() asm volatile("cp.async.commit_group;" ::: "memory")
__device__ __forceinline__ void ldsm4(uint32_t* r, uint32_t addr) {
    asm volatile("ldmatrix.sync.aligned.m8n8.x4.shared.b16 {%0,%1,%2,%3}, [%4];"
        : "=r"(r[0]), "=r"(r[1]), "=r"(r[2]), "=r"(r[3]) : "r"(addr));
}
// bf16 mma (k3a)
__device__ __forceinline__ void mma16816(float* c, const uint32_t* a, const uint32_t* b) {
    asm volatile("mma.sync.aligned.m16n8k16.row.col.f32.bf16.bf16.f32 "
        "{%0,%1,%2,%3}, {%4,%5,%6,%7}, {%8,%9}, {%0,%1,%2,%3};"
        : "+f"(c[0]), "+f"(c[1]), "+f"(c[2]), "+f"(c[3])
        : "r"(a[0]), "r"(a[1]), "r"(a[2]), "r"(a[3]), "r"(b[0]), "r"(b[1]));
}
// fp16 mma (k2)
__device__ __forceinline__ void mma16816f(float* c, const uint32_t* a, const uint32_t* b) {
    asm volatile("mma.sync.aligned.m16n8k16.row.col.f32.f16.f16.f32 "
        "{%0,%1,%2,%3}, {%4,%5,%6,%7}, {%8,%9}, {%0,%1,%2,%3};"
        : "+f"(c[0]), "+f"(c[1]), "+f"(c[2]), "+f"(c[3])
        : "r"(a[0]), "r"(a[1]), "r"(a[2]), "r"(a[3]), "r"(b[0]), "r"(b[1]));
}

// =============================================================================
// prep_w: W1c (rows 2048..3071 of W1, [k][n]) -> g_Bhi as [n][k] fp16
// =============================================================================
__global__ __launch_bounds__(256) void kprep_w(const float* __restrict__ W1)
{
    __shared__ float t[32][33];
    int kk0 = blockIdx.x * 32, nn0 = blockIdx.y * 32;
    int tx = threadIdx.x & 31, ty = threadIdx.x >> 5;
    #pragma unroll
    for (int i = 0; i < 32; i += 8)
        t[ty + i][tx] = W1[(size_t)(2048 + kk0 + ty + i) * 1024 + nn0 + tx];
    __syncthreads();
    #pragma unroll
    for (int i = 0; i < 32; i += 8) {
        float x = t[tx][ty + i];
        size_t o = (size_t)(nn0 + ty + i) * 1024 + kk0 + tx;
        g_Bhi[o] = __half_as_ushort(__float2half_rn(x));
    }
}

// =============================================================================
// prep_w2: W2 [k][51] -> g_W2hi/lo [n=64 pad][k] bf16
// =============================================================================
__global__ __launch_bounds__(256) void kprep_w2(const float* __restrict__ W2)
{
    int n = blockIdx.x;            // 0..63
    for (int k = threadIdx.x; k < 1024; k += 256) {
        float x = (n < NCLS) ? W2[(size_t)k * NCLS + n] : 0.f;
        __nv_bfloat16 h = __float2bfloat16(x);
        float lo = x - __bfloat162float(h);
        g_W2hi[n * 1024 + k] = __bfloat16_as_ushort(h);
        g_W2lo[n * 1024 + k] = __bfloat16_as_ushort(__float2bfloat16(lo));
    }
}

// =============================================================================
// prep_a: gather phrase rows per pair, split into fp16 hi/lo
// =============================================================================
__global__ __launch_bounds__(256) void kprep_a(const float* __restrict__ phrase,
                                               const int* __restrict__ pidx)
{
    int r = blockIdx.x;
    int b = r / NPAIR;
    int ph = pidx[r];
    const float4* src = (const float4*)(phrase + ((size_t)b * NPAIR + ph) * 1024);
    float4 v = src[threadIdx.x];
    ushort4 hi, lo;
    #define SPL(c, hf, lf) { __half _h = __float2half_rn(v.c); \
        float _l = v.c - __half2float(_h); \
        hf = __half_as_ushort(_h); lf = __half_as_ushort(__float2half_rn(_l)); }
    SPL(x, hi.x, lo.x) SPL(y, hi.y, lo.y) SPL(z, hi.z, lo.z) SPL(w, hi.w, lo.w)
    #undef SPL
    size_t o = (size_t)r * 1024 + threadIdx.x * 4;
    *(ushort4*)(g_Ahi + o) = hi;
    *(ushort4*)(g_Alo + o) = lo;
}

// =============================================================================
// K1: A12[r, j] = inst[r, :] @ W1[half*1024 + :, jc]   (fp32, small)
// =============================================================================
__global__ __launch_bounds__(256) void k1_instproj(const float* __restrict__ inst,
                                                   const float* __restrict__ W1)
{
    __shared__ float As[16][68];
    __shared__ float Bs[16][64];
    int tid = threadIdx.x;
    int n0 = blockIdx.x * 64;
    int m0 = blockIdx.y * 64;
    int half = n0 >> 10;
    int jc0  = n0 & 1023;
    const float* wbase = W1 + (size_t)half * 1024 * 1024 + jc0;

    int arow = tid >> 2;
    int akq  = (tid & 3) * 4;
    int ar   = m0 + arow; if (ar > 799) ar = 799;
    const float* aptr = inst + (size_t)ar * 1024 + akq;
    int brow = tid >> 4;
    int bn   = (tid & 15) * 4;
    int tx = tid & 15, ty = tid >> 4;
    float acc[4][4] = {};

    for (int k0 = 0; k0 < 1024; k0 += 16) {
        float4 av = *(const float4*)(aptr + k0);
        float4 bv = *(const float4*)(wbase + (size_t)(k0 + brow) * 1024 + bn);
        As[akq+0][arow] = av.x; As[akq+1][arow] = av.y;
        As[akq+2][arow] = av.z; As[akq+3][arow] = av.w;
        *(float4*)&Bs[brow][bn] = bv;
        __syncthreads();
        #pragma unroll
        for (int kk = 0; kk < 16; kk++) {
            float af[4], bf[4];
            *(float4*)af = *(const float4*)&As[kk][ty*4];
            *(float4*)bf = *(const float4*)&Bs[kk][tx*4];
            #pragma unroll
            for (int i = 0; i < 4; i++)
                #pragma unroll
                for (int j = 0; j < 4; j++)
                    acc[i][j] += af[i] * bf[j];
        }
        __syncthreads();
    }
    #pragma unroll
    for (int i = 0; i < 4; i++) {
        int r = m0 + ty*4 + i;
        if (r < 800)
            *(float4*)&g_A12[(size_t)r*2048 + n0 + tx*4] =
                make_float4(acc[i][0], acc[i][1], acc[i][2], acc[i][3]);
    }
}

// =============================================================================
// K2 (fp16 2-product mma): h = lrelu((Ahi+Alo)@Bhi + A12[sub]+A12[obj]+b1)
// CTA 128 rows x 64 cols; 8 warps = 4M x 2N; KC=64, 2 stages (40KB each).
// =============================================================================
__device__ __forceinline__ void k2_load(uint32_t st, int tid, int k0,
                                        size_t rowbase, int p0, int n0)
{
    #pragma unroll 1
    for (int i = tid; i < 2560; i += 256) {
        int q = i & 7;
        const unsigned short* src;
        uint32_t dst;
        if (i < 2048) {
            int t = i >> 10;
            int r = (i >> 3) & 127;
            int p = p0 + r; if (p > NPAIR - 1) p = NPAIR - 1;
            src = (t ? g_Alo : g_Ahi) + (rowbase + p) * 1024 + k0 + q * 8;
            dst = st + t * K2A_LO + SWZ(r * 128 + q * 16);
        } else {
            int j = i - 2048;
            int n = (j >> 3) & 63;
            src = g_Bhi + (size_t)(n0 + n) * 1024 + k0 + q * 8;
            dst = st + K2B + SWZ(n * 128 + q * 16);
        }
        cpasync16(dst, src);
    }
}

__global__ void __launch_bounds__(256, 2) k2_mma(const float* __restrict__ b1,
                                                 const int* __restrict__ connect)
{
    extern __shared__ __align__(1024) char smem[];
    uint32_t sb = smem_u32(smem);
    int tid = threadIdx.x;
    int lane = tid & 31, wid = tid >> 5;
    int wm = wid & 3, wn = wid >> 2;
    int n0 = blockIdx.x * 64;
    int p0 = blockIdx.y * 128;
    int b  = blockIdx.z;
    size_t rowbase = (size_t)b * NPAIR;

    float acc[2][4][4] = {};

    k2_load(sb,         tid, 0,  rowbase, p0, n0); CP_COMMIT();
    k2_load(sb + K2STG, tid, KC, rowbase, p0, n0); CP_COMMIT();

    #pragma unroll 1
    for (int c = 0; c < 16; c++) {
        if (c < 15) asm volatile("cp.async.wait_group 1;" ::: "memory");
        else        asm volatile("cp.async.wait_group 0;" ::: "memory");
        __syncthreads();

        uint32_t st  = sb + (c & 1) * K2STG;
        uint32_t sAh = st, sAl = st + K2A_LO, sBh = st + K2B;

        #pragma unroll
        for (int ks = 0; ks < 4; ks++) {
            int kb = ks * 32;
            uint32_t ah[2][4], al[2][4], bh[2][4];
            #pragma unroll
            for (int mt = 0; mt < 2; mt++) {
                uint32_t off = SWZ((wm*32 + mt*16 + (lane & 15)) * 128 + kb + (lane >> 4) * 16);
                ldsm4(ah[mt], sAh + off);
                ldsm4(al[mt], sAl + off);
            }
            int nrow  = (lane & 7) + ((lane >> 4) & 1) * 8;
            int khalf = ((lane >> 3) & 1) * 16;
            #pragma unroll
            for (int ntq = 0; ntq < 2; ntq++) {
                uint32_t off = SWZ((wn*32 + ntq*16 + nrow) * 128 + kb + khalf);
                ldsm4(bh[ntq], sBh + off);
            }
            #pragma unroll
            for (int mt = 0; mt < 2; mt++)
                #pragma unroll
                for (int nt = 0; nt < 4; nt++) {
                    const uint32_t* bhp = &bh[nt >> 1][(nt & 1) * 2];
                    mma16816f(acc[mt][nt], ah[mt], bhp);
                    mma16816f(acc[mt][nt], al[mt], bhp);
                }
        }
        __syncthreads();
        if (c + 2 < 16) {
            k2_load(sb + (c & 1) * K2STG, tid, (c + 2) * KC, rowbase, p0, n0);
            CP_COMMIT();
        }
    }

    int gp = lane >> 2, tq = lane & 3;
    int n0w = n0 + wn * 32;
    size_t bb2 = (size_t)b * 2 * NPAIR;
    const float* a12b = g_A12 + (size_t)b * NINST * 2048;
    #pragma unroll
    for (int mt = 0; mt < 2; mt++) {
        #pragma unroll
        for (int half = 0; half < 2; half++) {
            int p = p0 + wm*32 + mt*16 + gp + half*8;
            if (p >= NPAIR) continue;
            int sub = connect[bb2 + p];
            int obj = connect[bb2 + NPAIR + p];
            const float* r1 = a12b + (size_t)sub * 2048 + n0w;
            const float* r2 = a12b + (size_t)obj * 2048 + 1024 + n0w;
            size_t hoff = ((size_t)b * NPAIR + p) * 1024 + n0w;
            #pragma unroll
            for (int nt = 0; nt < 4; nt++) {
                int cc = nt*8 + tq*2;
                float2 v1 = *(const float2*)(r1 + cc);
                float2 v2 = *(const float2*)(r2 + cc);
                float2 vb = *(const float2*)(b1 + n0w + cc);
                float x = acc[mt][nt][half*2+0] + v1.x + v2.x + vb.x;
                float y = acc[mt][nt][half*2+1] + v1.y + v2.y + vb.y;
                x = x > 0.f ? x : 0.01f * x;
                y = y > 0.f ? y : 0.01f * y;
                __nv_bfloat16 xh = __float2bfloat16(x);
                __nv_bfloat16 yh = __float2bfloat16(y);
                ushort2 hi2, lo2;
                hi2.x = __bfloat16_as_ushort(xh);
                hi2.y = __bfloat16_as_ushort(yh);
                lo2.x = __bfloat16_as_ushort(__float2bfloat16(x - __bfloat162float(xh)));
                lo2.y = __bfloat16_as_ushort(__float2bfloat16(y - __bfloat162float(yh)));
                *(ushort2*)(g_Hhi + hoff + cc) = hi2;
                *(ushort2*)(g_Hlo + hoff + cc) = lo2;
            }
        }
    }
}

// =============================================================================
// K3a (tensor, bf16 3-product): logits = h @ W2 + b2
// =============================================================================
__device__ __forceinline__ void k3a_load(uint32_t st, int tid, int k0, int row0)
{
    #pragma unroll 1
    for (int i = tid; i < 3072; i += 256) {
        int q = i & 7;
        const unsigned short* src;
        uint32_t dst;
        if (i < 2048) {
            int t = i >> 10;
            int r = (i >> 3) & 127;
            int p = row0 + r; if (p > NROWS - 1) p = NROWS - 1;
            src = (t ? g_Hlo : g_Hhi) + (size_t)p * 1024 + k0 + q * 8;
            dst = st + t * SA_LO + SWZ(r * 128 + q * 16);
        } else {
            int j = i - 2048;
            int t = j >> 9;
            int n = (j >> 3) & 63;
            src = (t ? g_W2lo : g_W2hi) + (size_t)n * 1024 + k0 + q * 8;
            dst = st + SB_HI + t * 8192 + SWZ(n * 128 + q * 16);
        }
        cpasync16(dst, src);
    }
}

__global__ void __launch_bounds__(256, 2) k3a_logits(const float* __restrict__ b2,
                                                     float* __restrict__ out_logits)
{
    extern __shared__ __align__(1024) char smem[];
    uint32_t sb = smem_u32(smem);
    int tid = threadIdx.x;
    int lane = tid & 31, wid = tid >> 5;
    int wm = wid & 3, wn = wid >> 2;
    int row0 = blockIdx.x * 128;

    float acc[2][4][4] = {};

    k3a_load(sb,         tid, 0,  row0); CP_COMMIT();
    k3a_load(sb + STAGE, tid, KC, row0); CP_COMMIT();

    #pragma unroll 1
    for (int c = 0; c < 16; c++) {
        if (c < 15) asm volatile("cp.async.wait_group 1;" ::: "memory");
        else        asm volatile("cp.async.wait_group 0;" ::: "memory");
        __syncthreads();

        uint32_t st  = sb + (c & 1) * STAGE;
        uint32_t sAh = st, sAl = st + SA_LO, sBh = st + SB_HI, sBl = st + SB_LO;

        #pragma unroll
        for (int ks = 0; ks < 4; ks++) {
            int kb = ks * 32;
            uint32_t ah[2][4], al[2][4], bh[2][4], bl[2][4];
            #pragma unroll
            for (int mt = 0; mt < 2; mt++) {
                uint32_t off = SWZ((wm*32 + mt*16 + (lane & 15)) * 128 + kb + (lane >> 4) * 16);
                ldsm4(ah[mt], sAh + off);
                ldsm4(al[mt], sAl + off);
            }
            int nrow  = (lane & 7) + ((lane >> 4) & 1) * 8;
            int khalf = ((lane >> 3) & 1) * 16;
            #pragma unroll
            for (int ntq = 0; ntq < 2; ntq++) {
                uint32_t off = SWZ((wn*32 + ntq*16 + nrow) * 128 + kb + khalf);
                ldsm4(bh[ntq], sBh + off);
                ldsm4(bl[ntq], sBl + off);
            }
            #pragma unroll
            for (int mt = 0; mt < 2; mt++)
                #pragma unroll
                for (int nt = 0; nt < 4; nt++) {
                    const uint32_t* bhp = &bh[nt >> 1][(nt & 1) * 2];
                    const uint32_t* blp = &bl[nt >> 1][(nt & 1) * 2];
                    mma16816(acc[mt][nt], ah[mt], bhp);
                    mma16816(acc[mt][nt], al[mt], bhp);
                    mma16816(acc[mt][nt], ah[mt], blp);
                }
        }
        __syncthreads();
        if (c + 2 < 16) {
            k3a_load(sb + (c & 1) * STAGE, tid, (c + 2) * KC, row0);
            CP_COMMIT();
        }
    }

    int gp = lane >> 2, tq = lane & 3;
    int ncol0 = wn * 32;
    #pragma unroll
    for (int mt = 0; mt < 2; mt++) {
        #pragma unroll
        for (int half = 0; half < 2; half++) {
            int p = row0 + wm*32 + mt*16 + gp + half*8;
            if (p >= NROWS) continue;
            float* lp = out_logits + (size_t)p * NCLS;
            #pragma unroll
            for (int nt = 0; nt < 4; nt++) {
                int col = ncol0 + nt*8 + tq*2;
                if (col < NCLS)     lp[col]     = acc[mt][nt][half*2+0] + b2[col];
                if (col + 1 < NCLS) lp[col + 1] = acc[mt][nt][half*2+1] + b2[col + 1];
            }
        }
    }
}

// =============================================================================
// K3b: softmax -> probs; dense decisions + margins
// =============================================================================
__global__ void k3b_softmax(const float* __restrict__ out_logits,
                            const float* __restrict__ scores,
                            const int*   __restrict__ connect,
                            float* __restrict__ out_probs)
{
    int row = blockIdx.x * blockDim.x + threadIdx.x;
    if (row >= NROWS) return;
    const float* lp = out_logits + (size_t)row * NCLS;
    float l[NCLS];
    float m = -1e30f;
    #pragma unroll
    for (int c = 0; c < NCLS; c++) { l[c] = lp[c]; m = fmaxf(m, l[c]); }
    float s = 0.f;
    #pragma unroll
    for (int c = 0; c < NCLS; c++) { l[c] = expf(l[c] - m); s += l[c]; }
    float inv = 1.0f / s;
    float* pp = out_probs + (size_t)row * NCLS;
    float best = 0.f, second = 0.f; int bidx = 0;
    #pragma unroll
    for (int c = 0; c < NCLS; c++) {
        float pr = l[c] * inv;
        pp[c] = pr;
        if (c >= 1) {
            if (pr > best) { second = best; best = pr; bidx = c; }
            else if (pr > second) second = pr;
        }
    }
    int b = row / NPAIR, p = row % NPAIR;
    int si = connect[(size_t)b*2*NPAIR + p];
    int oi = connect[(size_t)b*2*NPAIR + NPAIR + p];
    g_overall[row]  = best * scores[b*NINST + si] * scores[b*NINST + oi];
    g_predprob[row] = best;
    g_predlab[row]  = bidx;
    g_margin[row]   = best - second;
}

// =============================================================================
// K4: warp-tournament top-NCAND selection
// =============================================================================
__global__ __launch_bounds__(1024) void k4_select()
{
    __shared__ float vals[NPAIR];
    __shared__ float wmax[32];
    __shared__ int   warg[32];
    __shared__ int   s_win;
    int b = blockIdx.x, tid = threadIdx.x, w = tid >> 5, lane = tid & 31;
    for (int i = tid; i < NPAIR; i += 1024) vals[i] = g_overall[b*NPAIR + i];
    __syncthreads();

    int lo = w * 310;
    int hiv = lo + 310; if (hiv > NPAIR) hiv = NPAIR;
    float bv = -1.f; int bi = 0x7fffffff;
    for (int i = lo + lane; i < hiv; i += 32) {
        float v = vals[i];
        if (v > bv || (v == bv && i < bi)) { bv = v; bi = i; }
    }
    #pragma unroll
    for (int o = 16; o; o >>= 1) {
        float ov = __shfl_down_sync(0xffffffffu, bv, o);
        int   oi = __shfl_down_sync(0xffffffffu, bi, o);
        if (ov > bv || (ov == bv && oi < bi)) { bv = ov; bi = oi; }
    }
    if (lane == 0) { wmax[w] = bv; warg[w] = bi; }
    __syncthreads();

    for (int t = 0; t < NCAND; t++) {
        if (tid < 32) {
            float v = wmax[lane]; int i2 = warg[lane];
            #pragma unroll
            for (int o = 16; o; o >>= 1) {
                float ov = __shfl_down_sync(0xffffffffu, v, o);
                int   oi = __shfl_down_sync(0xffffffffu, i2, o);
                if (ov > v || (ov == v && oi < i2)) { v = ov; i2 = oi; }
            }
            if (lane == 0) {
                g_cand_idx[b*NCAND + t] = i2;
                vals[i2] = -2.f;
                s_win = i2 / 310;
            }
        }
        __syncthreads();
        if (w == s_win) {
            float nv = -1.f; int ni = 0x7fffffff;
            for (int i = lo + lane; i < hiv; i += 32) {
                float v = vals[i];
                if (v > nv || (v == nv && i < ni)) { nv = v; ni = i; }
            }
            #pragma unroll
            for (int o = 16; o; o >>= 1) {
                float ov = __shfl_down_sync(0xffffffffu, nv, o);
                int   oi = __shfl_down_sync(0xffffffffu, ni, o);
                if (ov > nv || (ov == nv && oi < ni)) { nv = ov; ni = oi; }
            }
            if (lane == 0) { wmax[w] = nv; warg[w] = ni; }
        }
        __syncthreads();
    }
}

// =============================================================================
// K4b: init candidate outputs with dense values; flag decision-critical ones
// =============================================================================
__global__ __launch_bounds__(NCAND) void k4b_flag()
{
    __shared__ float ov[NCAND];
    __shared__ int   fl[NCAND];
    int b = blockIdx.x, i = threadIdx.x;
    int cand = g_cand_idx[b*NCAND + i];
    int row  = b*NPAIR + cand;
    float o  = g_overall[row];
    ov[i] = o;
    __syncthreads();

    int f = (g_margin[row] < MARGIN) ? 1 : 0;
    for (int j = 0; j < NCAND; j++)
        if (j != i && fabsf(o - ov[j]) < MARGIN) f = 1;
    fl[i] = f;

    g_cand_ovr [b*NCAND + i] = (double)o;
    g_cand_prob[b*NCAND + i] = (double)g_predprob[row];
    g_cand_lab [b*NCAND + i] = g_predlab[row];
    __syncthreads();

    if (i == 0) {
        int n = 0;
        for (int j = 0; j < NCAND; j++)
            if (fl[j]) g_fix_list[b*NCAND + (n++)] = j;
        g_fix_cnt[b] = n;
    }
}

// =============================================================================
// K5: compensated-fp32 exact partial h — FLAGGED candidates only
// =============================================================================
#define CPB 4
__global__ __launch_bounds__(256) void k5_repair_h(const float* __restrict__ inst,
                                                   const float* __restrict__ phrase,
                                                   const float* __restrict__ W1,
                                                   const int*   __restrict__ connect,
                                                   const int*   __restrict__ pidx)
{
    __shared__ float sf[CPB][1536];
    int ks = blockIdx.x;
    int g  = blockIdx.y;
    int b  = blockIdx.z;
    int tid = threadIdx.x;
    int k0 = ks * 1536;

    int cnt = g_fix_cnt[b];
    if (g * CPB >= cnt) return;
    int slots[CPB];

    #pragma unroll 1
    for (int c = 0; c < CPB; c++) {
        int jj = g*CPB + c; if (jj > cnt - 1) jj = cnt - 1;
        int slot = b*NCAND + g_fix_list[b*NCAND + jj];
        slots[c] = slot;
        int p  = g_cand_idx[slot];
        int si = connect[(size_t)b*2*NPAIR + p];
        int oi = connect[(size_t)b*2*NPAIR + NPAIR + p];
        int ph = pidx[b*NPAIR + p];
        const float* s0 = inst   + ((size_t)b*NINST + si)*1024;
        const float* s1 = inst   + ((size_t)b*NINST + oi)*1024;
        const float* s2 = phrase + ((size_t)b*NPAIR + ph)*1024;
        for (int k = tid; k < 1536; k += 256) {
            int f = k0 + k;
            float v;
            if (f < 1024)       v = s0[f];
            else if (f < 2048)  v = s1[f - 1024];
            else                v = s2[f - 2048];
            sf[c][k] = v;
        }
    }
    __syncthreads();

    float s[CPB][4] = {};
    float comp[CPB][4] = {};
    const float* wcol = W1 + (size_t)k0 * 1024 + tid * 4;
    #pragma unroll 2
    for (int k = 0; k < 1536; k++) {
        float4 w = *(const float4*)(wcol + (size_t)k * 1024);
        float wv[4] = {w.x, w.y, w.z, w.w};
        #pragma unroll
        for (int c = 0; c < CPB; c++) {
            float f = sf[c][k];
            #pragma unroll
            for (int j = 0; j < 4; j++) {
                float p  = __fmul_rn(f, wv[j]);
                float e  = __fmaf_rn(f, wv[j], -p);
                float t  = __fadd_rn(s[c][j], p);
                float z  = __fsub_rn(t, s[c][j]);
                float e2 = __fadd_rn(__fsub_rn(s[c][j], __fsub_rn(t, z)),
                                     __fsub_rn(p, z));
                comp[c][j] = __fadd_rn(comp[c][j], __fadd_rn(e2, e));
                s[c][j] = t;
            }
        }
    }
    float* outs = g_hs[ks];
    float* outc = g_hc[ks];
    #pragma unroll
    for (int c = 0; c < CPB; c++) {
        int slot = slots[c];
        *(float4*)(outs + (size_t)slot*1024 + tid*4) =
            make_float4(s[c][0], s[c][1], s[c][2], s[c][3]);
        *(float4*)(outc + (size_t)slot*1024 + tid*4) =
            make_float4(comp[c][0], comp[c][1], comp[c][2], comp[c][3]);
    }
}

// =============================================================================
// K6: exact decisions — FLAGGED candidates only
// =============================================================================
__global__ __launch_bounds__(64) void k6_decide(const float* __restrict__ W2,
                                                const float* __restrict__ b2,
                                                const float* __restrict__ b1,
                                                const float* __restrict__ scores,
                                                const int*   __restrict__ connect)
{
    __shared__ double sh[1024];
    __shared__ double slog[NCLS];
    int gid = blockIdx.x;
    int b = gid >> 7, j = gid & (NCAND - 1);
    if (j >= g_fix_cnt[b]) return;
    int slot = b*NCAND + g_fix_list[b*NCAND + j];
    int tid = threadIdx.x;
    size_t base = (size_t)slot * 1024;
    for (int k = tid; k < 1024; k += 64) {
        double v = ((double)g_hs[0][base + k] + (double)g_hc[0][base + k])
                 + ((double)g_hs[1][base + k] + (double)g_hc[1][base + k])
                 + (double)b1[k];
        v = v > 0.0 ? v : 0.01 * v;
        sh[k] = v;
    }
    __syncthreads();

    if (tid < NCLS) {
        double acc = 0.0;
        #pragma unroll 8
        for (int k = 0; k < 1024; k++)
            acc = fma(sh[k], (double)W2[(size_t)k*NCLS + tid], acc);
        slog[tid] = acc + (double)b2[tid];
    }
    __syncthreads();

    if (tid == 0) {
        double m = slog[0];
        for (int c = 1; c < NCLS; c++) m = slog[c] > m ? slog[c] : m;
        double e[NCLS]; double ssum = 0.0;
        for (int c = 0; c < NCLS; c++) { e[c] = exp(slog[c] - m); ssum += e[c]; }
        double best = 0.0; int bl = 0;
        for (int c = 1; c < NCLS; c++) {
            double pr = e[c] / ssum;
            if (pr > best) { best = pr; bl = c; }
        }
        int p = g_cand_idx[slot];
        int si = connect[(size_t)b*2*NPAIR + p];
        int oi = connect[(size_t)b*2*NPAIR + NPAIR + p];
        double ov = best * (double)scores[b*NINST + si] * (double)scores[b*NINST + oi];
        g_cand_ovr[slot]  = ov;
        g_cand_prob[slot] = best;
        g_cand_lab[slot]  = bl;
    }
}

// =============================================================================
// K7: final top-100 per batch over NCAND candidates
// =============================================================================
__global__ __launch_bounds__(128) void k7_final(float* __restrict__ outbase)
{
    __shared__ double v[NCAND];
    __shared__ int    pix[NCAND];
    int b = blockIdx.x, tid = threadIdx.x;
    v[tid]   = g_cand_ovr[b*NCAND + tid];
    pix[tid] = g_cand_idx[b*NCAND + tid];
    __syncthreads();

    if (tid == 0) {
        float* out_lab  = outbase;
        float* out_prob = outbase + 800;
        float* out_val  = outbase + 1600;
        float* out_idx  = outbase + 2400;
        for (int t = 0; t < 100; t++) {
            double bv = -1.0; int bj = 0; int bidx = 0x7fffffff;
            for (int j = 0; j < NCAND; j++) {
                double val = v[j]; int ix = pix[j];
                if (val > bv || (val == bv && ix < bidx)) { bv = val; bj = j; bidx = ix; }
            }
            int slot2 = b*NCAND + bj;
            out_val [b*100 + t] = (float)bv;
            out_idx [b*100 + t] = (float)bidx;
            out_lab [b*100 + t] = (float)g_cand_lab[slot2];
            out_prob[b*100 + t] = (float)g_cand_prob[slot2];
            v[bj] = -2.0;
        }
    }
}

// =============================================================================
extern "C" void kernel_launch(void* const* d_in, const int* in_sizes, int n_in,
                              void* d_out, int out_size)
{
    const float* inst    = (const float*)d_in[0];
    const float* phrase  = (const float*)d_in[1];
    const float* scores  = (const float*)d_in[2];
    const float* W1      = (const float*)d_in[3];
    const float* b1      = (const float*)d_in[4];
    const float* W2      = (const float*)d_in[5];
    const float* b2      = (const float*)d_in[6];
    const int*   connect = (const int*)d_in[7];
    const int*   pidx    = (const int*)d_in[8];

    float* out        = (float*)d_out;
    float* out_logits = out;
    float* out_probs  = out + (size_t)BATCH*NPAIR*NCLS;
    float* out_top    = out + (size_t)2*BATCH*NPAIR*NCLS;

    cudaFuncSetAttribute(k2_mma,     cudaFuncAttributeMaxDynamicSharedMemorySize, K2_SMEM);
    cudaFuncSetAttribute(k3a_logits, cudaFuncAttributeMaxDynamicSharedMemorySize, MM_SMEM);

    kprep_w<<<dim3(32, 32), 256>>>(W1);
    kprep_w2<<<64, 256>>>(W2);
    kprep_a<<<NROWS, 256>>>(phrase, pidx);
    k1_instproj<<<dim3(32, 13), 256>>>(inst, W1);
    k2_mma<<<dim3(16, 78, BATCH), 256, K2_SMEM>>>(b1, connect);
    k3a_logits<<<619, 256, MM_SMEM>>>(b2, out_logits);
    k3b_softmax<<<(NROWS + 255) / 256, 256>>>(out_logits, scores, connect, out_probs);
    k4_select<<<BATCH, 1024>>>();
    k4b_flag<<<BATCH, NCAND>>>();
    k5_repair_h<<<dim3(2, 32, BATCH), 256>>>(inst, phrase, W1, connect, pidx);
    k6_decide<<<BATCH*NCAND, 64>>>(W2, b2, b1, scores, connect);
    k7_final<<<BATCH, 128>>>(out_top);
}

// round 10
// speedup vs baseline: 3.4654x; 1.0371x over previous
#include <cuda_runtime.h>
#include <cuda_bf16.h>
#include <cuda_fp16.h>
#include <math.h>
#include <stdint.h>

#define BATCH 8
#define NINST 100
#define NPAIR 9900
#define NCLS  51
#define NROWS (BATCH*NPAIR)   // 79200
#define NCAND 128
#define KC    64
#define MARGIN 2.5e-3f
// k2 stage: Ahi 16K | Alo 16K | Bhi 32K = 64KB (fp16 2-product, N-tile 256)
#define K2A_LO 16384
#define K2B    32768
#define K2STG  65536
#define K2_SMEM (2*K2STG)
// k3a stage: Ahi 16K | Alo 16K | Bhi 8K | Blo 8K = 48KB (bf16, 3-product)
#define SA_LO 16384
#define SB_HI 32768
#define SB_LO 40960
#define STAGE 49152
#define MM_SMEM (2*STAGE)

// ---------------- scratch (device globals; no allocs allowed) ----------------
__device__ float  g_A12[BATCH*NINST*2048];
__device__ float  g_overall[NROWS];
__device__ float  g_predprob[NROWS];
__device__ float  g_margin[NROWS];
__device__ int    g_predlab[NROWS];
__device__ int    g_cand_idx[BATCH*NCAND];
__device__ int    g_cand_lab[BATCH*NCAND];
__device__ double g_cand_prob[BATCH*NCAND];
__device__ double g_cand_ovr[BATCH*NCAND];
__device__ int    g_fix_list[BATCH*NCAND];
__device__ int    g_fix_cnt[BATCH];
__device__ float  g_hs[2][BATCH*NCAND*1024];   // compensated fp32 partial h (sum)
__device__ float  g_hc[2][BATCH*NCAND*1024];   // compensated fp32 partial h (comp)
__device__ __align__(16) unsigned short g_Ahi[81100800];  // gathered phrase fp16 hi
__device__ __align__(16) unsigned short g_Alo[81100800];  // fp16 lo
__device__ __align__(16) unsigned short g_Bhi[1024*1024]; // W1c^T [n][k] fp16 hi
__device__ __align__(16) unsigned short g_Hhi[81100800];  // hidden h bf16 hi
__device__ __align__(16) unsigned short g_Hlo[81100800];  // hidden h bf16 lo
__device__ __align__(16) unsigned short g_W2hi[64*1024];  // W2^T padded bf16 hi
__device__ __align__(16) unsigned short g_W2lo[64*1024];  // bf16 lo

// ---------------- helpers (baseline PTX only) ----------------
__device__ __forceinline__ uint32_t smem_u32(const void* p) {
    uint32_t a;
    asm("{ .reg .u64 t; cvta.to.shared.u64 t, %1; cvt.u32.u64 %0, t; }" : "=r"(a) : "l"(p));
    return a;
}
#define SWZ(x) ((x) ^ (((x) >> 3) & 0x70))
__device__ __forceinline__ void cpasync16(uint32_t dst, const void* src) {
    asm volatile("cp.async.cg.shared.global [%0], [%1], 16;" :: "r"(dst), "l"(src));
}
#define CP_COMMIT() asm volatile("cp.async.commit_group;" ::: "memory")
__device__ __forceinline__ void ldsm4(uint32_t* r, uint32_t addr) {
    asm volatile("ldmatrix.sync.aligned.m8n8.x4.shared.b16 {%0,%1,%2,%3}, [%4];"
        : "=r"(r[0]), "=r"(r[1]), "=r"(r[2]), "=r"(r[3]) : "r"(addr));
}
// bf16 mma (k3a)
__device__ __forceinline__ void mma16816(float* c, const uint32_t* a, const uint32_t* b) {
    asm volatile("mma.sync.aligned.m16n8k16.row.col.f32.bf16.bf16.f32 "
        "{%0,%1,%2,%3}, {%4,%5,%6,%7}, {%8,%9}, {%0,%1,%2,%3};"
        : "+f"(c[0]), "+f"(c[1]), "+f"(c[2]), "+f"(c[3])
        : "r"(a[0]), "r"(a[1]), "r"(a[2]), "r"(a[3]), "r"(b[0]), "r"(b[1]));
}
// fp16 mma (k2)
__device__ __forceinline__ void mma16816f(float* c, const uint32_t* a, const uint32_t* b) {
    asm volatile("mma.sync.aligned.m16n8k16.row.col.f32.f16.f16.f32 "
        "{%0,%1,%2,%3}, {%4,%5,%6,%7}, {%8,%9}, {%0,%1,%2,%3};"
        : "+f"(c[0]), "+f"(c[1]), "+f"(c[2]), "+f"(c[3])
        : "r"(a[0]), "r"(a[1]), "r"(a[2]), "r"(a[3]), "r"(b[0]), "r"(b[1]));
}

// =============================================================================
// prep_w: W1c (rows 2048..3071 of W1, [k][n]) -> g_Bhi as [n][k] fp16
// =============================================================================
__global__ __launch_bounds__(256) void kprep_w(const float* __restrict__ W1)
{
    __shared__ float t[32][33];
    int kk0 = blockIdx.x * 32, nn0 = blockIdx.y * 32;
    int tx = threadIdx.x & 31, ty = threadIdx.x >> 5;
    #pragma unroll
    for (int i = 0; i < 32; i += 8)
        t[ty + i][tx] = W1[(size_t)(2048 + kk0 + ty + i) * 1024 + nn0 + tx];
    __syncthreads();
    #pragma unroll
    for (int i = 0; i < 32; i += 8) {
        float x = t[tx][ty + i];
        size_t o = (size_t)(nn0 + ty + i) * 1024 + kk0 + tx;
        g_Bhi[o] = __half_as_ushort(__float2half_rn(x));
    }
}

// =============================================================================
// prep_w2: W2 [k][51] -> g_W2hi/lo [n=64 pad][k] bf16
// =============================================================================
__global__ __launch_bounds__(256) void kprep_w2(const float* __restrict__ W2)
{
    int n = blockIdx.x;            // 0..63
    for (int k = threadIdx.x; k < 1024; k += 256) {
        float x = (n < NCLS) ? W2[(size_t)k * NCLS + n] : 0.f;
        __nv_bfloat16 h = __float2bfloat16(x);
        float lo = x - __bfloat162float(h);
        g_W2hi[n * 1024 + k] = __bfloat16_as_ushort(h);
        g_W2lo[n * 1024 + k] = __bfloat16_as_ushort(__float2bfloat16(lo));
    }
}

// =============================================================================
// prep_a: gather phrase rows per pair, split into fp16 hi/lo
// =============================================================================
__global__ __launch_bounds__(256) void kprep_a(const float* __restrict__ phrase,
                                               const int* __restrict__ pidx)
{
    int r = blockIdx.x;
    int b = r / NPAIR;
    int ph = pidx[r];
    const float4* src = (const float4*)(phrase + ((size_t)b * NPAIR + ph) * 1024);
    float4 v = src[threadIdx.x];
    ushort4 hi, lo;
    #define SPL(c, hf, lf) { __half _h = __float2half_rn(v.c); \
        float _l = v.c - __half2float(_h); \
        hf = __half_as_ushort(_h); lf = __half_as_ushort(__float2half_rn(_l)); }
    SPL(x, hi.x, lo.x) SPL(y, hi.y, lo.y) SPL(z, hi.z, lo.z) SPL(w, hi.w, lo.w)
    #undef SPL
    size_t o = (size_t)r * 1024 + threadIdx.x * 4;
    *(ushort4*)(g_Ahi + o) = hi;
    *(ushort4*)(g_Alo + o) = lo;
}

// =============================================================================
// K1: A12[r, j] = inst[r, :] @ W1[half*1024 + :, jc]   (fp32, small)
// =============================================================================
__global__ __launch_bounds__(256) void k1_instproj(const float* __restrict__ inst,
                                                   const float* __restrict__ W1)
{
    __shared__ float As[16][68];
    __shared__ float Bs[16][64];
    int tid = threadIdx.x;
    int n0 = blockIdx.x * 64;
    int m0 = blockIdx.y * 64;
    int half = n0 >> 10;
    int jc0  = n0 & 1023;
    const float* wbase = W1 + (size_t)half * 1024 * 1024 + jc0;

    int arow = tid >> 2;
    int akq  = (tid & 3) * 4;
    int ar   = m0 + arow; if (ar > 799) ar = 799;
    const float* aptr = inst + (size_t)ar * 1024 + akq;
    int brow = tid >> 4;
    int bn   = (tid & 15) * 4;
    int tx = tid & 15, ty = tid >> 4;
    float acc[4][4] = {};

    for (int k0 = 0; k0 < 1024; k0 += 16) {
        float4 av = *(const float4*)(aptr + k0);
        float4 bv = *(const float4*)(wbase + (size_t)(k0 + brow) * 1024 + bn);
        As[akq+0][arow] = av.x; As[akq+1][arow] = av.y;
        As[akq+2][arow] = av.z; As[akq+3][arow] = av.w;
        *(float4*)&Bs[brow][bn] = bv;
        __syncthreads();
        #pragma unroll
        for (int kk = 0; kk < 16; kk++) {
            float af[4], bf[4];
            *(float4*)af = *(const float4*)&As[kk][ty*4];
            *(float4*)bf = *(const float4*)&Bs[kk][tx*4];
            #pragma unroll
            for (int i = 0; i < 4; i++)
                #pragma unroll
                for (int j = 0; j < 4; j++)
                    acc[i][j] += af[i] * bf[j];
        }
        __syncthreads();
    }
    #pragma unroll
    for (int i = 0; i < 4; i++) {
        int r = m0 + ty*4 + i;
        if (r < 800)
            *(float4*)&g_A12[(size_t)r*2048 + n0 + tx*4] =
                make_float4(acc[i][0], acc[i][1], acc[i][2], acc[i][3]);
    }
}

// =============================================================================
// K2 v3 (fp16 2-product, big-N): CTA 128 rows x 256 cols, 512 threads,
// 16 warps = 4M x 4N, warp tile 32x64. KC=64, 2 stages of 64KB (1 CTA/SM).
// h = lrelu((Ahi+Alo)@Bhi + A12[sub]+A12[obj]+b1), stored bf16 hi/lo.
// =============================================================================
__device__ __forceinline__ void k2_load(uint32_t st, int tid, int k0,
                                        size_t rowbase, int p0, int n0)
{
    #pragma unroll 1
    for (int i = tid; i < 4096; i += 512) {
        int q = i & 7;
        const unsigned short* src;
        uint32_t dst;
        if (i < 2048) {
            int t = i >> 10;
            int r = (i >> 3) & 127;
            int p = p0 + r; if (p > NPAIR - 1) p = NPAIR - 1;
            src = (t ? g_Alo : g_Ahi) + (rowbase + p) * 1024 + k0 + q * 8;
            dst = st + t * K2A_LO + SWZ(r * 128 + q * 16);
        } else {
            int j = i - 2048;
            int n = (j >> 3) & 255;
            src = g_Bhi + (size_t)(n0 + n) * 1024 + k0 + q * 8;
            dst = st + K2B + SWZ(n * 128 + q * 16);
        }
        cpasync16(dst, src);
    }
}

__global__ void __launch_bounds__(512, 1) k2_mma(const float* __restrict__ b1,
                                                 const int* __restrict__ connect)
{
    extern __shared__ __align__(1024) char smem[];
    uint32_t sb = smem_u32(smem);
    int tid = threadIdx.x;
    int lane = tid & 31, wid = tid >> 5;
    int wm = wid & 3, wn = wid >> 2;       // 4 M-warps x 4 N-warps
    int n0 = blockIdx.x * 256;
    int p0 = blockIdx.y * 128;
    int b  = blockIdx.z;
    size_t rowbase = (size_t)b * NPAIR;

    float acc[2][8][4] = {};

    k2_load(sb,         tid, 0,  rowbase, p0, n0); CP_COMMIT();
    k2_load(sb + K2STG, tid, KC, rowbase, p0, n0); CP_COMMIT();

    #pragma unroll 1
    for (int c = 0; c < 16; c++) {
        if (c < 15) asm volatile("cp.async.wait_group 1;" ::: "memory");
        else        asm volatile("cp.async.wait_group 0;" ::: "memory");
        __syncthreads();

        uint32_t st  = sb + (c & 1) * K2STG;
        uint32_t sAh = st, sAl = st + K2A_LO, sBh = st + K2B;

        #pragma unroll
        for (int ks = 0; ks < 4; ks++) {
            int kb = ks * 32;
            uint32_t ah[2][4], al[2][4], bh[4][4];
            #pragma unroll
            for (int mt = 0; mt < 2; mt++) {
                uint32_t off = SWZ((wm*32 + mt*16 + (lane & 15)) * 128 + kb + (lane >> 4) * 16);
                ldsm4(ah[mt], sAh + off);
                ldsm4(al[mt], sAl + off);
            }
            int nrow  = (lane & 7) + ((lane >> 4) & 1) * 8;
            int khalf = ((lane >> 3) & 1) * 16;
            #pragma unroll
            for (int ntq = 0; ntq < 4; ntq++) {
                uint32_t off = SWZ((wn*64 + ntq*16 + nrow) * 128 + kb + khalf);
                ldsm4(bh[ntq], sBh + off);
            }
            #pragma unroll
            for (int mt = 0; mt < 2; mt++)
                #pragma unroll
                for (int nt = 0; nt < 8; nt++) {
                    const uint32_t* bhp = &bh[nt >> 1][(nt & 1) * 2];
                    mma16816f(acc[mt][nt], ah[mt], bhp);
                    mma16816f(acc[mt][nt], al[mt], bhp);
                }
        }
        __syncthreads();
        if (c + 2 < 16) {
            k2_load(sb + (c & 1) * K2STG, tid, (c + 2) * KC, rowbase, p0, n0);
            CP_COMMIT();
        }
    }

    int gp = lane >> 2, tq = lane & 3;
    int n0w = n0 + wn * 64;
    size_t bb2 = (size_t)b * 2 * NPAIR;
    const float* a12b = g_A12 + (size_t)b * NINST * 2048;
    #pragma unroll
    for (int mt = 0; mt < 2; mt++) {
        #pragma unroll
        for (int half = 0; half < 2; half++) {
            int p = p0 + wm*32 + mt*16 + gp + half*8;
            if (p >= NPAIR) continue;
            int sub = connect[bb2 + p];
            int obj = connect[bb2 + NPAIR + p];
            const float* r1 = a12b + (size_t)sub * 2048 + n0w;
            const float* r2 = a12b + (size_t)obj * 2048 + 1024 + n0w;
            size_t hoff = ((size_t)b * NPAIR + p) * 1024 + n0w;
            #pragma unroll
            for (int nt = 0; nt < 8; nt++) {
                int cc = nt*8 + tq*2;
                float2 v1 = *(const float2*)(r1 + cc);
                float2 v2 = *(const float2*)(r2 + cc);
                float2 vb = *(const float2*)(b1 + n0w + cc);
                float x = acc[mt][nt][half*2+0] + v1.x + v2.x + vb.x;
                float y = acc[mt][nt][half*2+1] + v1.y + v2.y + vb.y;
                x = x > 0.f ? x : 0.01f * x;
                y = y > 0.f ? y : 0.01f * y;
                __nv_bfloat16 xh = __float2bfloat16(x);
                __nv_bfloat16 yh = __float2bfloat16(y);
                ushort2 hi2, lo2;
                hi2.x = __bfloat16_as_ushort(xh);
                hi2.y = __bfloat16_as_ushort(yh);
                lo2.x = __bfloat16_as_ushort(__float2bfloat16(x - __bfloat162float(xh)));
                lo2.y = __bfloat16_as_ushort(__float2bfloat16(y - __bfloat162float(yh)));
                *(ushort2*)(g_Hhi + hoff + cc) = hi2;
                *(ushort2*)(g_Hlo + hoff + cc) = lo2;
            }
        }
    }
}

// =============================================================================
// K3a (tensor, bf16 3-product): logits = h @ W2 + b2
// =============================================================================
__device__ __forceinline__ void k3a_load(uint32_t st, int tid, int k0, int row0)
{
    #pragma unroll 1
    for (int i = tid; i < 3072; i += 256) {
        int q = i & 7;
        const unsigned short* src;
        uint32_t dst;
        if (i < 2048) {
            int t = i >> 10;
            int r = (i >> 3) & 127;
            int p = row0 + r; if (p > NROWS - 1) p = NROWS - 1;
            src = (t ? g_Hlo : g_Hhi) + (size_t)p * 1024 + k0 + q * 8;
            dst = st + t * SA_LO + SWZ(r * 128 + q * 16);
        } else {
            int j = i - 2048;
            int t = j >> 9;
            int n = (j >> 3) & 63;
            src = (t ? g_W2lo : g_W2hi) + (size_t)n * 1024 + k0 + q * 8;
            dst = st + SB_HI + t * 8192 + SWZ(n * 128 + q * 16);
        }
        cpasync16(dst, src);
    }
}

__global__ void __launch_bounds__(256, 2) k3a_logits(const float* __restrict__ b2,
                                                     float* __restrict__ out_logits)
{
    extern __shared__ __align__(1024) char smem[];
    uint32_t sb = smem_u32(smem);
    int tid = threadIdx.x;
    int lane = tid & 31, wid = tid >> 5;
    int wm = wid & 3, wn = wid >> 2;
    int row0 = blockIdx.x * 128;

    float acc[2][4][4] = {};

    k3a_load(sb,         tid, 0,  row0); CP_COMMIT();
    k3a_load(sb + STAGE, tid, KC, row0); CP_COMMIT();

    #pragma unroll 1
    for (int c = 0; c < 16; c++) {
        if (c < 15) asm volatile("cp.async.wait_group 1;" ::: "memory");
        else        asm volatile("cp.async.wait_group 0;" ::: "memory");
        __syncthreads();

        uint32_t st  = sb + (c & 1) * STAGE;
        uint32_t sAh = st, sAl = st + SA_LO, sBh = st + SB_HI, sBl = st + SB_LO;

        #pragma unroll
        for (int ks = 0; ks < 4; ks++) {
            int kb = ks * 32;
            uint32_t ah[2][4], al[2][4], bh[2][4], bl[2][4];
            #pragma unroll
            for (int mt = 0; mt < 2; mt++) {
                uint32_t off = SWZ((wm*32 + mt*16 + (lane & 15)) * 128 + kb + (lane >> 4) * 16);
                ldsm4(ah[mt], sAh + off);
                ldsm4(al[mt], sAl + off);
            }
            int nrow  = (lane & 7) + ((lane >> 4) & 1) * 8;
            int khalf = ((lane >> 3) & 1) * 16;
            #pragma unroll
            for (int ntq = 0; ntq < 2; ntq++) {
                uint32_t off = SWZ((wn*32 + ntq*16 + nrow) * 128 + kb + khalf);
                ldsm4(bh[ntq], sBh + off);
                ldsm4(bl[ntq], sBl + off);
            }
            #pragma unroll
            for (int mt = 0; mt < 2; mt++)
                #pragma unroll
                for (int nt = 0; nt < 4; nt++) {
                    const uint32_t* bhp = &bh[nt >> 1][(nt & 1) * 2];
                    const uint32_t* blp = &bl[nt >> 1][(nt & 1) * 2];
                    mma16816(acc[mt][nt], ah[mt], bhp);
                    mma16816(acc[mt][nt], al[mt], bhp);
                    mma16816(acc[mt][nt], ah[mt], blp);
                }
        }
        __syncthreads();
        if (c + 2 < 16) {
            k3a_load(sb + (c & 1) * STAGE, tid, (c + 2) * KC, row0);
            CP_COMMIT();
        }
    }

    int gp = lane >> 2, tq = lane & 3;
    int ncol0 = wn * 32;
    #pragma unroll
    for (int mt = 0; mt < 2; mt++) {
        #pragma unroll
        for (int half = 0; half < 2; half++) {
            int p = row0 + wm*32 + mt*16 + gp + half*8;
            if (p >= NROWS) continue;
            float* lp = out_logits + (size_t)p * NCLS;
            #pragma unroll
            for (int nt = 0; nt < 4; nt++) {
                int col = ncol0 + nt*8 + tq*2;
                if (col < NCLS)     lp[col]     = acc[mt][nt][half*2+0] + b2[col];
                if (col + 1 < NCLS) lp[col + 1] = acc[mt][nt][half*2+1] + b2[col + 1];
            }
        }
    }
}

// =============================================================================
// K3b: softmax -> probs; dense decisions + margins
// =============================================================================
__global__ void k3b_softmax(const float* __restrict__ out_logits,
                            const float* __restrict__ scores,
                            const int*   __restrict__ connect,
                            float* __restrict__ out_probs)
{
    int row = blockIdx.x * blockDim.x + threadIdx.x;
    if (row >= NROWS) return;
    const float* lp = out_logits + (size_t)row * NCLS;
    float l[NCLS];
    float m = -1e30f;
    #pragma unroll
    for (int c = 0; c < NCLS; c++) { l[c] = lp[c]; m = fmaxf(m, l[c]); }
    float s = 0.f;
    #pragma unroll
    for (int c = 0; c < NCLS; c++) { l[c] = expf(l[c] - m); s += l[c]; }
    float inv = 1.0f / s;
    float* pp = out_probs + (size_t)row * NCLS;
    float best = 0.f, second = 0.f; int bidx = 0;
    #pragma unroll
    for (int c = 0; c < NCLS; c++) {
        float pr = l[c] * inv;
        pp[c] = pr;
        if (c >= 1) {
            if (pr > best) { second = best; best = pr; bidx = c; }
            else if (pr > second) second = pr;
        }
    }
    int b = row / NPAIR, p = row % NPAIR;
    int si = connect[(size_t)b*2*NPAIR + p];
    int oi = connect[(size_t)b*2*NPAIR + NPAIR + p];
    g_overall[row]  = best * scores[b*NINST + si] * scores[b*NINST + oi];
    g_predprob[row] = best;
    g_predlab[row]  = bidx;
    g_margin[row]   = best - second;
}

// =============================================================================
// K4: warp-tournament top-NCAND selection
// =============================================================================
__global__ __launch_bounds__(1024) void k4_select()
{
    __shared__ float vals[NPAIR];
    __shared__ float wmax[32];
    __shared__ int   warg[32];
    __shared__ int   s_win;
    int b = blockIdx.x, tid = threadIdx.x, w = tid >> 5, lane = tid & 31;
    for (int i = tid; i < NPAIR; i += 1024) vals[i] = g_overall[b*NPAIR + i];
    __syncthreads();

    int lo = w * 310;
    int hiv = lo + 310; if (hiv > NPAIR) hiv = NPAIR;
    float bv = -1.f; int bi = 0x7fffffff;
    for (int i = lo + lane; i < hiv; i += 32) {
        float v = vals[i];
        if (v > bv || (v == bv && i < bi)) { bv = v; bi = i; }
    }
    #pragma unroll
    for (int o = 16; o; o >>= 1) {
        float ov = __shfl_down_sync(0xffffffffu, bv, o);
        int   oi = __shfl_down_sync(0xffffffffu, bi, o);
        if (ov > bv || (ov == bv && oi < bi)) { bv = ov; bi = oi; }
    }
    if (lane == 0) { wmax[w] = bv; warg[w] = bi; }
    __syncthreads();

    for (int t = 0; t < NCAND; t++) {
        if (tid < 32) {
            float v = wmax[lane]; int i2 = warg[lane];
            #pragma unroll
            for (int o = 16; o; o >>= 1) {
                float ov = __shfl_down_sync(0xffffffffu, v, o);
                int   oi = __shfl_down_sync(0xffffffffu, i2, o);
                if (ov > v || (ov == v && oi < i2)) { v = ov; i2 = oi; }
            }
            if (lane == 0) {
                g_cand_idx[b*NCAND + t] = i2;
                vals[i2] = -2.f;
                s_win = i2 / 310;
            }
        }
        __syncthreads();
        if (w == s_win) {
            float nv = -1.f; int ni = 0x7fffffff;
            for (int i = lo + lane; i < hiv; i += 32) {
                float v = vals[i];
                if (v > nv || (v == nv && i < ni)) { nv = v; ni = i; }
            }
            #pragma unroll
            for (int o = 16; o; o >>= 1) {
                float ov = __shfl_down_sync(0xffffffffu, nv, o);
                int   oi = __shfl_down_sync(0xffffffffu, ni, o);
                if (ov > nv || (ov == nv && oi < ni)) { nv = ov; ni = oi; }
            }
            if (lane == 0) { wmax[w] = nv; warg[w] = ni; }
        }
        __syncthreads();
    }
}

// =============================================================================
// K4b: init candidate outputs with dense values; flag decision-critical ones
// =============================================================================
__global__ __launch_bounds__(NCAND) void k4b_flag()
{
    __shared__ float ov[NCAND];
    __shared__ int   fl[NCAND];
    int b = blockIdx.x, i = threadIdx.x;
    int cand = g_cand_idx[b*NCAND + i];
    int row  = b*NPAIR + cand;
    float o  = g_overall[row];
    ov[i] = o;
    __syncthreads();

    int f = (g_margin[row] < MARGIN) ? 1 : 0;
    for (int j = 0; j < NCAND; j++)
        if (j != i && fabsf(o - ov[j]) < MARGIN) f = 1;
    fl[i] = f;

    g_cand_ovr [b*NCAND + i] = (double)o;
    g_cand_prob[b*NCAND + i] = (double)g_predprob[row];
    g_cand_lab [b*NCAND + i] = g_predlab[row];
    __syncthreads();

    if (i == 0) {
        int n = 0;
        for (int j = 0; j < NCAND; j++)
            if (fl[j]) g_fix_list[b*NCAND + (n++)] = j;
        g_fix_cnt[b] = n;
    }
}

// =============================================================================
// K5: compensated-fp32 exact partial h — FLAGGED candidates only
// =============================================================================
#define CPB 4
__global__ __launch_bounds__(256) void k5_repair_h(const float* __restrict__ inst,
                                                   const float* __restrict__ phrase,
                                                   const float* __restrict__ W1,
                                                   const int*   __restrict__ connect,
                                                   const int*   __restrict__ pidx)
{
    __shared__ float sf[CPB][1536];
    int ks = blockIdx.x;
    int g  = blockIdx.y;
    int b  = blockIdx.z;
    int tid = threadIdx.x;
    int k0 = ks * 1536;

    int cnt = g_fix_cnt[b];
    if (g * CPB >= cnt) return;
    int slots[CPB];

    #pragma unroll 1
    for (int c = 0; c < CPB; c++) {
        int jj = g*CPB + c; if (jj > cnt - 1) jj = cnt - 1;
        int slot = b*NCAND + g_fix_list[b*NCAND + jj];
        slots[c] = slot;
        int p  = g_cand_idx[slot];
        int si = connect[(size_t)b*2*NPAIR + p];
        int oi = connect[(size_t)b*2*NPAIR + NPAIR + p];
        int ph = pidx[b*NPAIR + p];
        const float* s0 = inst   + ((size_t)b*NINST + si)*1024;
        const float* s1 = inst   + ((size_t)b*NINST + oi)*1024;
        const float* s2 = phrase + ((size_t)b*NPAIR + ph)*1024;
        for (int k = tid; k < 1536; k += 256) {
            int f = k0 + k;
            float v;
            if (f < 1024)       v = s0[f];
            else if (f < 2048)  v = s1[f - 1024];
            else                v = s2[f - 2048];
            sf[c][k] = v;
        }
    }
    __syncthreads();

    float s[CPB][4] = {};
    float comp[CPB][4] = {};
    const float* wcol = W1 + (size_t)k0 * 1024 + tid * 4;
    #pragma unroll 2
    for (int k = 0; k < 1536; k++) {
        float4 w = *(const float4*)(wcol + (size_t)k * 1024);
        float wv[4] = {w.x, w.y, w.z, w.w};
        #pragma unroll
        for (int c = 0; c < CPB; c++) {
            float f = sf[c][k];
            #pragma unroll
            for (int j = 0; j < 4; j++) {
                float p  = __fmul_rn(f, wv[j]);
                float e  = __fmaf_rn(f, wv[j], -p);
                float t  = __fadd_rn(s[c][j], p);
                float z  = __fsub_rn(t, s[c][j]);
                float e2 = __fadd_rn(__fsub_rn(s[c][j], __fsub_rn(t, z)),
                                     __fsub_rn(p, z));
                comp[c][j] = __fadd_rn(comp[c][j], __fadd_rn(e2, e));
                s[c][j] = t;
            }
        }
    }
    float* outs = g_hs[ks];
    float* outc = g_hc[ks];
    #pragma unroll
    for (int c = 0; c < CPB; c++) {
        int slot = slots[c];
        *(float4*)(outs + (size_t)slot*1024 + tid*4) =
            make_float4(s[c][0], s[c][1], s[c][2], s[c][3]);
        *(float4*)(outc + (size_t)slot*1024 + tid*4) =
            make_float4(comp[c][0], comp[c][1], comp[c][2], comp[c][3]);
    }
}

// =============================================================================
// K6: exact decisions — FLAGGED candidates only
// =============================================================================
__global__ __launch_bounds__(64) void k6_decide(const float* __restrict__ W2,
                                                const float* __restrict__ b2,
                                                const float* __restrict__ b1,
                                                const float* __restrict__ scores,
                                                const int*   __restrict__ connect)
{
    __shared__ double sh[1024];
    __shared__ double slog[NCLS];
    int gid = blockIdx.x;
    int b = gid >> 7, j = gid & (NCAND - 1);
    if (j >= g_fix_cnt[b]) return;
    int slot = b*NCAND + g_fix_list[b*NCAND + j];
    int tid = threadIdx.x;
    size_t base = (size_t)slot * 1024;
    for (int k = tid; k < 1024; k += 64) {
        double v = ((double)g_hs[0][base + k] + (double)g_hc[0][base + k])
                 + ((double)g_hs[1][base + k] + (double)g_hc[1][base + k])
                 + (double)b1[k];
        v = v > 0.0 ? v : 0.01 * v;
        sh[k] = v;
    }
    __syncthreads();

    if (tid < NCLS) {
        double acc = 0.0;
        #pragma unroll 8
        for (int k = 0; k < 1024; k++)
            acc = fma(sh[k], (double)W2[(size_t)k*NCLS + tid], acc);
        slog[tid] = acc + (double)b2[tid];
    }
    __syncthreads();

    if (tid == 0) {
        double m = slog[0];
        for (int c = 1; c < NCLS; c++) m = slog[c] > m ? slog[c] : m;
        double e[NCLS]; double ssum = 0.0;
        for (int c = 0; c < NCLS; c++) { e[c] = exp(slog[c] - m); ssum += e[c]; }
        double best = 0.0; int bl = 0;
        for (int c = 1; c < NCLS; c++) {
            double pr = e[c] / ssum;
            if (pr > best) { best = pr; bl = c; }
        }
        int p = g_cand_idx[slot];
        int si = connect[(size_t)b*2*NPAIR + p];
        int oi = connect[(size_t)b*2*NPAIR + NPAIR + p];
        double ov = best * (double)scores[b*NINST + si] * (double)scores[b*NINST + oi];
        g_cand_ovr[slot]  = ov;
        g_cand_prob[slot] = best;
        g_cand_lab[slot]  = bl;
    }
}

// =============================================================================
// K7: final top-100 per batch over NCAND candidates
// =============================================================================
__global__ __launch_bounds__(128) void k7_final(float* __restrict__ outbase)
{
    __shared__ double v[NCAND];
    __shared__ int    pix[NCAND];
    int b = blockIdx.x, tid = threadIdx.x;
    v[tid]   = g_cand_ovr[b*NCAND + tid];
    pix[tid] = g_cand_idx[b*NCAND + tid];
    __syncthreads();

    if (tid == 0) {
        float* out_lab  = outbase;
        float* out_prob = outbase + 800;
        float* out_val  = outbase + 1600;
        float* out_idx  = outbase + 2400;
        for (int t = 0; t < 100; t++) {
            double bv = -1.0; int bj = 0; int bidx = 0x7fffffff;
            for (int j = 0; j < NCAND; j++) {
                double val = v[j]; int ix = pix[j];
                if (val > bv || (val == bv && ix < bidx)) { bv = val; bj = j; bidx = ix; }
            }
            int slot2 = b*NCAND + bj;
            out_val [b*100 + t] = (float)bv;
            out_idx [b*100 + t] = (float)bidx;
            out_lab [b*100 + t] = (float)g_cand_lab[slot2];
            out_prob[b*100 + t] = (float)g_cand_prob[slot2];
            v[bj] = -2.0;
        }
    }
}

// =============================================================================
extern "C" void kernel_launch(void* const* d_in, const int* in_sizes, int n_in,
                              void* d_out, int out_size)
{
    const float* inst    = (const float*)d_in[0];
    const float* phrase  = (const float*)d_in[1];
    const float* scores  = (const float*)d_in[2];
    const float* W1      = (const float*)d_in[3];
    const float* b1      = (const float*)d_in[4];
    const float* W2      = (const float*)d_in[5];
    const float* b2      = (const float*)d_in[6];
    const int*   connect = (const int*)d_in[7];
    const int*   pidx    = (const int*)d_in[8];

    float* out        = (float*)d_out;
    float* out_logits = out;
    float* out_probs  = out + (size_t)BATCH*NPAIR*NCLS;
    float* out_top    = out + (size_t)2*BATCH*NPAIR*NCLS;

    cudaFuncSetAttribute(k2_mma,     cudaFuncAttributeMaxDynamicSharedMemorySize, K2_SMEM);
    cudaFuncSetAttribute(k3a_logits, cudaFuncAttributeMaxDynamicSharedMemorySize, MM_SMEM);

    // launch order puts k2_mma at slot #4 so the ncu capture profiles it
    kprep_w<<<dim3(32, 32), 256>>>(W1);
    kprep_a<<<NROWS, 256>>>(phrase, pidx);
    k1_instproj<<<dim3(32, 13), 256>>>(inst, W1);
    k2_mma<<<dim3(4, 78, BATCH), 512, K2_SMEM>>>(b1, connect);
    kprep_w2<<<64, 256>>>(W2);
    k3a_logits<<<619, 256, MM_SMEM>>>(b2, out_logits);
    k3b_softmax<<<(NROWS + 255) / 256, 256>>>(out_logits, scores, connect, out_probs);
    k4_select<<<BATCH, 1024>>>();
    k4b_flag<<<BATCH, NCAND>>>();
    k5_repair_h<<<dim3(2, 32, BATCH), 256>>>(inst, phrase, W1, connect, pidx);
    k6_decide<<<BATCH*NCAND, 64>>>(W2, b2, b1, scores, connect);
    k7_final<<<BATCH, 128>>>(out_top);
}